// round 7
// baseline (speedup 1.0000x reference)
#include <cuda_runtime.h>
#include <cuda_bf16.h>
#include <math.h>
#include <stdint.h>

#define NUM_O   5000
#define NUM_T   20000
#define DD      128
#define HH      512
#define GG      64
#define LL      5
#define K1      (3*DD)        // 384
#define N2      (2*HH+DD)     // 1152

typedef __nv_bfloat16 bf16;

// ================= scratch =================
__device__ float g_ov    [NUM_O * DD];
__device__ float g_pooled[NUM_O * HH];
__device__ float g_counts[NUM_O];
__device__ float g_invcnt[NUM_O];
__device__ float g_scores[NUM_O];
__device__ float g_gvec  [GG * DD];

__device__ bf16 g_ovh[NUM_O * DD], g_ovl[NUM_O * DD];
__device__ bf16 g_pvh[NUM_T * DD], g_pvl[NUM_T * DD];
__device__ bf16 g_hh [NUM_T * HH], g_hl [NUM_T * HH];
__device__ bf16 g_h2h[NUM_O * HH], g_h2l[NUM_O * HH];

__device__ bf16 g_w1h[LL * HH * K1], g_w1l[LL * HH * K1];
__device__ bf16 g_w3h[LL * HH * HH], g_w3l[LL * HH * HH];
__device__ bf16 g_w4h[LL * DD * HH], g_w4l[LL * DD * HH];

// int8 path (GEMM2)
__device__ int8_t g_qah[NUM_T * HH], g_qal[NUM_T * HH];
__device__ float  g_saq[20096];                       // padded to 157*128
__device__ int8_t g_qbh[LL * N2 * HH], g_qbl[LL * N2 * HH];
__device__ float  g_sbq[LL * N2];

__device__ __forceinline__ void f32split(float v, bf16& h, bf16& l) {
    h = __float2bfloat16(v);
    l = __float2bfloat16(v - __bfloat162float(h));
}
__device__ __forceinline__ uint32_t bfpack(bf16 a, bf16 b) {
    __nv_bfloat162 t; t.x = a; t.y = b;
    return *reinterpret_cast<uint32_t*>(&t);
}
__device__ __forceinline__ uint32_t smem_u32(const void* p) {
    uint32_t a;
    asm("{ .reg .u64 t; cvta.to.shared.u64 t, %1; cvt.u32.u64 %0, t; }" : "=r"(a) : "l"(p));
    return a;
}

// ================= glue =================
__global__ void zero_kernel(float* p, int n) {
    int i = blockIdx.x * blockDim.x + threadIdx.x;
    if (i < n) p[i] = 0.f;
}
__global__ void gather_ov_init(const float* __restrict__ obj_emb,
                               const int* __restrict__ objs,
                               bf16* __restrict__ ovh, bf16* __restrict__ ovl) {
    int i = blockIdx.x, d = threadIdx.x;
    float v = obj_emb[objs[i] * DD + d];
    bf16 h, l; f32split(v, h, l);
    ovh[i * DD + d] = h; ovl[i * DD + d] = l;
}
__global__ void gather_pv0(const float* __restrict__ pred_emb,
                           const int* __restrict__ trip,
                           bf16* __restrict__ pvh, bf16* __restrict__ pvl) {
    int i = blockIdx.x, d = threadIdx.x;
    int p = trip[3 * i + 1];
    float v = pred_emb[p * DD + d];
    bf16 h, l; f32split(v, h, l);
    pvh[i * DD + d] = h; pvl[i * DD + d] = l;
}
__global__ void count_kernel(const int* __restrict__ trip, float* __restrict__ counts) {
    int i = blockIdx.x * blockDim.x + threadIdx.x;
    if (i < NUM_T) {
        atomicAdd(&counts[trip[3 * i + 0]], 1.f);
        atomicAdd(&counts[trip[3 * i + 2]], 1.f);
    }
}
__global__ void inv_kernel(const float* __restrict__ counts, float* __restrict__ inv) {
    int i = blockIdx.x * blockDim.x + threadIdx.x;
    if (i < NUM_O) inv[i] = 1.f / fmaxf(counts[i], 1.f);
}
__global__ void wtrans_split(const float* __restrict__ w,
                             bf16* __restrict__ oh,
                             bf16* __restrict__ ol, int K, int N) {
    __shared__ float tile[32][33];
    int l = blockIdx.z;
    int k0 = blockIdx.y * 32, n0 = blockIdx.x * 32;
    const float* wl = w + (size_t)l * K * N;
    tile[threadIdx.y][threadIdx.x] = wl[(size_t)(k0 + threadIdx.y) * N + n0 + threadIdx.x];
    __syncthreads();
    int on = n0 + threadIdx.y, ok = k0 + threadIdx.x;
    float v = tile[threadIdx.x][threadIdx.y];
    bf16 h, lo; f32split(v, h, lo);
    size_t idx = ((size_t)l * N + on) * K + ok;
    oh[idx] = h; ol[idx] = lo;
}

// weights [L,K,N] fp32 -> int8 q14 planes [L,N,K] + per-row scale
__global__ void wquant(const float* __restrict__ w,
                       int8_t* __restrict__ qbh, int8_t* __restrict__ qbl,
                       float* __restrict__ sbq, int K, int N) {
    extern __shared__ float ws[];   // 32 x (K+2)
    int l = blockIdx.y;
    int n0 = blockIdx.x * 32;
    int tx = threadIdx.x & 31, ty = threadIdx.x >> 5;   // 32 x 8
    const float* wl = w + (size_t)l * K * N;
    for (int k = ty; k < K; k += 8)
        ws[tx * (K + 2) + k] = wl[(size_t)k * N + n0 + tx];
    __syncthreads();
    int lane = threadIdx.x & 31, w8 = threadIdx.x >> 5;
    for (int p = 0; p < 4; p++) {
        int nl = p * 8 + w8;
        float mx = 0.f;
        for (int k = lane; k < K; k += 32) mx = fmaxf(mx, fabsf(ws[nl * (K + 2) + k]));
#pragma unroll
        for (int off = 16; off; off >>= 1) mx = fmaxf(mx, __shfl_xor_sync(0xffffffff, mx, off));
        float inv = mx > 1e-30f ? 8191.f / mx : 0.f;
        for (int k = lane; k < K; k += 32) {
            int q = __float2int_rn(ws[nl * (K + 2) + k] * inv);
            int qh = q >> 7;
            int ql = q - (qh << 7);
            size_t idx = ((size_t)l * N + n0 + nl) * K + k;
            qbh[idx] = (int8_t)qh; qbl[idx] = (int8_t)ql;
        }
        if (lane == 0) sbq[(size_t)l * N + n0 + nl] = mx / 8191.f;
    }
}

// h (bf16 pair) -> q14 int8 planes + per-row scale. h >= 0 (relu).
__global__ void quant_rows(const bf16* __restrict__ xh, const bf16* __restrict__ xl,
                           int8_t* __restrict__ qh, int8_t* __restrict__ ql,
                           float* __restrict__ saq) {
    int row = blockIdx.x, t = threadIdx.x;   // 128 threads, 512 cols
    __shared__ float red[128];
    const size_t base = (size_t)row * HH;
    float v[4]; float mx = 0.f;
#pragma unroll
    for (int j = 0; j < 4; j++) {
        int c = t + j * 128;
        v[j] = __bfloat162float(xh[base + c]) + __bfloat162float(xl[base + c]);
        mx = fmaxf(mx, v[j]);
    }
    red[t] = mx; __syncthreads();
    for (int s = 64; s > 0; s >>= 1) { if (t < s) red[t] = fmaxf(red[t], red[t + s]); __syncthreads(); }
    float s = red[0];
    float inv = s > 1e-30f ? 8191.f / s : 0.f;
#pragma unroll
    for (int j = 0; j < 4; j++) {
        int c = t + j * 128;
        int q = __float2int_rn(v[j] * inv);
        int qhi = q >> 7;
        qh[base + c] = (int8_t)qhi;
        ql[base + c] = (int8_t)(q - (qhi << 7));
    }
    if (t == 0) saq[row] = s / 8191.f;
}

// ================= bf16 HMMA GEMM (2-stage, R4 config) =================
#define BN   128
#define BK   32

#define CP_ASYNC16(dst, src, sz) \
    asm volatile("cp.async.cg.shared.global [%0], [%1], 16, %2;" :: "r"(dst), "l"(src), "r"(sz))
#define CP_COMMIT() asm volatile("cp.async.commit_group;")
#define LDSM_X4(R0,R1,R2,R3,ADDR) \
    asm volatile("ldmatrix.sync.aligned.m8n8.x4.shared.b16 {%0,%1,%2,%3}, [%4];" \
                 : "=r"(R0),"=r"(R1),"=r"(R2),"=r"(R3) : "r"(ADDR))
#define MMA16816(C,A0,A1,A2,A3,B0,B1) \
    asm volatile("mma.sync.aligned.m16n8k16.row.col.f32.bf16.bf16.f32 " \
                 "{%0,%1,%2,%3},{%4,%5,%6,%7},{%8,%9},{%0,%1,%2,%3};" \
                 : "+f"((C)[0]),"+f"((C)[1]),"+f"((C)[2]),"+f"((C)[3]) \
                 : "r"(A0),"r"(A1),"r"(A2),"r"(A3),"r"(B0),"r"(B1))
#define IMMA16832(D,A0,A1,A2,A3,B0,B1) \
    asm volatile("mma.sync.aligned.m16n8k32.row.col.s32.s8.s8.s32 " \
                 "{%0,%1,%2,%3},{%4,%5,%6,%7},{%8,%9},{%0,%1,%2,%3};" \
                 : "+r"((D)[0]),"+r"((D)[1]),"+r"((D)[2]),"+r"((D)[3]) \
                 : "r"(A0),"r"(A1),"r"(A2),"r"(A3),"r"(B0),"r"(B1))
#define STS128(ADDR,A,B,C,D) \
    asm volatile("st.shared.v4.b32 [%0], {%1,%2,%3,%4};" :: "r"(ADDR),"r"(A),"r"(B),"r"(C),"r"(D))
#define REDV4(PTR,X,Y,Z,W) \
    asm volatile("red.global.add.v4.f32 [%0], {%1,%2,%3,%4};" :: "l"(PTR),"f"(X),"f"(Y),"f"(Z),"f"(W) : "memory")

__device__ __forceinline__ uint32_t sw_off(int row, int c) {
    return (uint32_t)(row * 64 + (((c ^ (row & 3))) << 4));
}

template <int A_MODE, int TBM>
__device__ __forceinline__ void ld_stage(
    uint32_t st,
    const bf16* __restrict__ Ah, const bf16* __restrict__ Al,
    const float* __restrict__ Af, const float* __restrict__ inv,
    const bf16* __restrict__ OVh, const bf16* __restrict__ OVl,
    const bf16* __restrict__ PVh, const bf16* __restrict__ PVl,
    const int* __restrict__ trip,
    const bf16* __restrict__ Bh, const bf16* __restrict__ Bl,
    int bm, int bn, int k0, int M, int K, int tid)
{
    constexpr uint32_t OFF_AL = TBM * 64;
    constexpr uint32_t OFF_BH = TBM * 128;
    constexpr uint32_t OFF_BL = TBM * 128 + 8192;
    int seg = k0 >> 7;
    int koff_base = k0 & 127;
#pragma unroll
    for (int lin = tid; lin < TBM * 4; lin += 256) {
        int row = lin >> 2;
        int c   = lin & 3;
        uint32_t so = sw_off(row, c);
        int gr = bm + row;
        bool ok = gr < M;
        if (A_MODE == 2) {
            if (ok) {
                const float4* src = reinterpret_cast<const float4*>(Af + (size_t)gr * K + k0 + c * 8);
                float4 v0 = src[0], v1 = src[1];
                float s = __ldg(&inv[gr]);
                bf16 hb[8], lb[8];
                float vals[8] = {v0.x*s, v0.y*s, v0.z*s, v0.w*s, v1.x*s, v1.y*s, v1.z*s, v1.w*s};
#pragma unroll
                for (int j = 0; j < 8; j++) f32split(vals[j], hb[j], lb[j]);
                STS128(st + so, bfpack(hb[0],hb[1]), bfpack(hb[2],hb[3]), bfpack(hb[4],hb[5]), bfpack(hb[6],hb[7]));
                STS128(st + OFF_AL + so, bfpack(lb[0],lb[1]), bfpack(lb[2],lb[3]), bfpack(lb[4],lb[5]), bfpack(lb[6],lb[7]));
            } else {
                STS128(st + so, 0u, 0u, 0u, 0u);
                STS128(st + OFF_AL + so, 0u, 0u, 0u, 0u);
            }
        } else {
            uint32_t sz = ok ? 16u : 0u;
            const char *sh, *sl;
            if (A_MODE == 0) {
                size_t srow = ok ? (size_t)gr : 0;
                sh = (const char*)(Ah + srow * K + k0 + c * 8);
                sl = (const char*)(Al + srow * K + k0 + c * 8);
            } else {
                int gi = ok ? gr : 0;
                int koff = koff_base + c * 8;
                size_t off;
                if (seg == 0) {
                    int s = __ldg(&trip[3 * gi + 0]);
                    off = (size_t)s * DD + koff;
                    sh = (const char*)(OVh + off); sl = (const char*)(OVl + off);
                } else if (seg == 1) {
                    off = (size_t)gi * DD + koff;
                    sh = (const char*)(PVh + off); sl = (const char*)(PVl + off);
                } else {
                    int o = __ldg(&trip[3 * gi + 2]);
                    off = (size_t)o * DD + koff;
                    sh = (const char*)(OVh + off); sl = (const char*)(OVl + off);
                }
            }
            CP_ASYNC16(st + so, sh, sz);
            CP_ASYNC16(st + OFF_AL + so, sl, sz);
        }
    }
#pragma unroll
    for (int lin = tid; lin < 512; lin += 256) {
        int row = lin >> 2;
        int c   = lin & 3;
        uint32_t so = sw_off(row, c);
        int gr = bn + row;
        const char* sh = (const char*)(Bh + (size_t)gr * K + k0 + c * 8);
        const char* sl = (const char*)(Bl + (size_t)gr * K + k0 + c * 8);
        CP_ASYNC16(st + OFF_BH + so, sh, 16u);
        CP_ASYNC16(st + OFF_BL + so, sl, 16u);
    }
}

template <int A_MODE, int OUT_MODE, int TBM>
__global__ void __launch_bounds__(256)
gemm_hmma(const bf16* __restrict__ Ah, const bf16* __restrict__ Al,
          const float* __restrict__ Af, const float* __restrict__ inv,
          const bf16* __restrict__ OVh, const bf16* __restrict__ OVl,
          const bf16* __restrict__ PVh, const bf16* __restrict__ PVl,
          const int* __restrict__ trip,
          const bf16* __restrict__ Bh, const bf16* __restrict__ Bl,
          const float* __restrict__ bias,
          float* __restrict__ Cf,
          bf16* __restrict__ Ch, bf16* __restrict__ Cl,
          int M, int N, int K)
{
    constexpr uint32_t OFF_AL = TBM * 64;
    constexpr uint32_t OFF_BH = TBM * 128;
    constexpr uint32_t OFF_BL = TBM * 128 + 8192;
    constexpr uint32_t STAGE  = TBM * 128 + 16384;
    constexpr int NWM = (TBM == 128) ? 2 : 1;
    constexpr int NT  = (TBM == 128) ? 4 : 2;

    extern __shared__ char smem[];
    uint32_t sb = smem_u32(smem);

    int tid = threadIdx.x;
    int wid = tid >> 5, lane = tid & 31;
    int wm = (wid % NWM) * 64;
    int wn = (wid / NWM) * (NT * 8);
    int bm = blockIdx.y * TBM;
    int bn = blockIdx.x * BN;
    const int NC = K / BK;

    float acc[4][NT][4];
#pragma unroll
    for (int i = 0; i < 4; i++)
#pragma unroll
        for (int j = 0; j < NT; j++)
#pragma unroll
            for (int r = 0; r < 4; r++) acc[i][j][r] = 0.f;

    int lrow8 = (lane & 7) + ((lane >> 3) & 1) * 8;
    int lchunk = (lane >> 4);

    ld_stage<A_MODE, TBM>(sb, Ah, Al, Af, inv, OVh, OVl, PVh, PVl, trip, Bh, Bl, bm, bn, 0, M, K, tid);
    CP_COMMIT();

    for (int kc = 0; kc < NC; kc++) {
        if (kc + 1 < NC) {
            ld_stage<A_MODE, TBM>(sb + ((kc + 1) & 1) * STAGE, Ah, Al, Af, inv, OVh, OVl, PVh, PVl,
                                  trip, Bh, Bl, bm, bn, (kc + 1) * BK, M, K, tid);
            CP_COMMIT();
            asm volatile("cp.async.wait_group 1;");
        } else {
            asm volatile("cp.async.wait_group 0;");
        }
        __syncthreads();

        uint32_t sa = sb + (kc & 1) * STAGE;
#pragma unroll
        for (int ks = 0; ks < 2; ks++) {
            int c0 = ks * 2;
            uint32_t ah[4][4], al[4][4], bh[NT][2], bl[NT][2];
#pragma unroll
            for (int mt = 0; mt < 4; mt++) {
                int row = wm + mt * 16 + lrow8;
                uint32_t addr = sa + sw_off(row, c0 + lchunk);
                LDSM_X4(ah[mt][0], ah[mt][1], ah[mt][2], ah[mt][3], addr);
            }
#pragma unroll
            for (int np = 0; np < NT / 2; np++) {
                int row = wn + np * 16 + lrow8;
                uint32_t addr = sa + OFF_BH + sw_off(row, c0 + lchunk);
                uint32_t r0, r1, r2, r3;
                LDSM_X4(r0, r1, r2, r3, addr);
                bh[2*np][0] = r0; bh[2*np+1][0] = r1;
                bh[2*np][1] = r2; bh[2*np+1][1] = r3;
            }
#pragma unroll
            for (int mt = 0; mt < 4; mt++)
#pragma unroll
                for (int nt = 0; nt < NT; nt++)
                    MMA16816(acc[mt][nt], ah[mt][0], ah[mt][1], ah[mt][2], ah[mt][3],
                             bh[nt][0], bh[nt][1]);
#pragma unroll
            for (int np = 0; np < NT / 2; np++) {
                int row = wn + np * 16 + lrow8;
                uint32_t addr = sa + OFF_BL + sw_off(row, c0 + lchunk);
                uint32_t r0, r1, r2, r3;
                LDSM_X4(r0, r1, r2, r3, addr);
                bl[2*np][0] = r0; bl[2*np+1][0] = r1;
                bl[2*np][1] = r2; bl[2*np+1][1] = r3;
            }
#pragma unroll
            for (int mt = 0; mt < 4; mt++)
#pragma unroll
                for (int nt = 0; nt < NT; nt++)
                    MMA16816(acc[mt][nt], ah[mt][0], ah[mt][1], ah[mt][2], ah[mt][3],
                             bl[nt][0], bl[nt][1]);
#pragma unroll
            for (int mt = 0; mt < 4; mt++) {
                int row = wm + mt * 16 + lrow8;
                uint32_t addr = sa + OFF_AL + sw_off(row, c0 + lchunk);
                LDSM_X4(al[mt][0], al[mt][1], al[mt][2], al[mt][3], addr);
            }
#pragma unroll
            for (int mt = 0; mt < 4; mt++)
#pragma unroll
                for (int nt = 0; nt < NT; nt++)
                    MMA16816(acc[mt][nt], al[mt][0], al[mt][1], al[mt][2], al[mt][3],
                             bh[nt][0], bh[nt][1]);
        }
        __syncthreads();
    }

    int r = lane >> 2, q = lane & 3;
#pragma unroll
    for (int mt = 0; mt < 4; mt++) {
        int row0 = bm + wm + mt * 16 + r;
        int row1 = row0 + 8;
#pragma unroll
        for (int nt = 0; nt < NT; nt++) {
            int col = bn + wn + nt * 8 + q * 2;
            float b0 = bias[col], b1 = bias[col + 1];
            float v00 = fmaxf(acc[mt][nt][0] + b0, 0.f);
            float v01 = fmaxf(acc[mt][nt][1] + b1, 0.f);
            float v10 = fmaxf(acc[mt][nt][2] + b0, 0.f);
            float v11 = fmaxf(acc[mt][nt][3] + b1, 0.f);
            bf16 h0, l0, h1, l1;
            if (row0 < M) {
                if (OUT_MODE == 2)
                    *reinterpret_cast<float2*>(Cf + (size_t)row0 * N + col) = make_float2(v00, v01);
                f32split(v00, h0, l0); f32split(v01, h1, l1);
                *reinterpret_cast<uint32_t*>(Ch + (size_t)row0 * N + col) = bfpack(h0, h1);
                *reinterpret_cast<uint32_t*>(Cl + (size_t)row0 * N + col) = bfpack(l0, l1);
            }
            if (row1 < M) {
                if (OUT_MODE == 2)
                    *reinterpret_cast<float2*>(Cf + (size_t)row1 * N + col) = make_float2(v10, v11);
                f32split(v10, h0, l0); f32split(v11, h1, l1);
                *reinterpret_cast<uint32_t*>(Ch + (size_t)row1 * N + col) = bfpack(h0, h1);
                *reinterpret_cast<uint32_t*>(Cl + (size_t)row1 * N + col) = bfpack(l0, l1);
            }
        }
    }
}

// ================= int8 IMMA GEMM2 (q14 split, scatter epilogue) =================
// C tile 128x64. A: q8 planes [M,512], B: q8 planes [N2,512]. K=512 fixed.
// smem: stage = AH(4096)+AL(4096)+BH(2048)+BL(2048) = 12288; 2 stages; epi staging 32KB.
#define QSTAGE 12288

__device__ __forceinline__ uint32_t qsw(int row, int h) {
    return (uint32_t)(row * 32 + ((h ^ ((row >> 2) & 1)) << 4));
}

__device__ __forceinline__ void qld_stage(
    uint32_t st,
    const int8_t* __restrict__ Aqh, const int8_t* __restrict__ Aql,
    const int8_t* __restrict__ Bqh, const int8_t* __restrict__ Bql,
    int bm, int bn, int k0, int M, int tid)
{
    // A: 128 rows x 2 halves = 256 chunks; one per thread
    {
        int row = tid >> 1, h = tid & 1;
        uint32_t so = qsw(row, h);
        int gr = bm + row;
        uint32_t sz = gr < M ? 16u : 0u;
        size_t ga = (size_t)(gr < M ? gr : 0) * HH + k0 + h * 16;
        CP_ASYNC16(st + so, Aqh + ga, sz);
        CP_ASYNC16(st + 4096 + so, Aql + ga, sz);
    }
    // B: 64 rows x 2 halves x 2 planes = 256 chunks
    {
        int p = tid >> 7, rem = tid & 127;
        int row = rem >> 1, h = rem & 1;
        uint32_t so = qsw(row, h);
        size_t gb = (size_t)(bn + row) * HH + k0 + h * 16;
        const int8_t* Bp = p ? Bql : Bqh;
        CP_ASYNC16(st + 8192 + p * 2048 + so, Bp + gb, 16u);
    }
}

__global__ void __launch_bounds__(256)
gemm_imma_scatter(const int8_t* __restrict__ Aqh, const int8_t* __restrict__ Aql,
                  const float* __restrict__ saq,
                  const int8_t* __restrict__ Bqh, const int8_t* __restrict__ Bql,
                  const float* __restrict__ sbq,
                  const int* __restrict__ trip,
                  const float* __restrict__ bias,
                  float* __restrict__ pooled,
                  bf16* __restrict__ Pvh, bf16* __restrict__ Pvl,
                  int M)
{
    extern __shared__ char smem[];
    uint32_t sb = smem_u32(smem);

    int tid = threadIdx.x;
    int wid = tid >> 5, lane = tid & 31;
    int wm = (wid & 1) * 64;          // 2 warps along m
    int wn = (wid >> 1) * 16;         // 4 warps along n (4x16 = 64)
    int bm = blockIdx.y * 128;
    int bn = blockIdx.x * 64;

    int hh[4][2][4], mid[4][2][4], llv[4][2][4];
#pragma unroll
    for (int i = 0; i < 4; i++)
#pragma unroll
        for (int j = 0; j < 2; j++)
#pragma unroll
            for (int r = 0; r < 4; r++) { hh[i][j][r] = 0; mid[i][j][r] = 0; llv[i][j][r] = 0; }

    // ldmatrix lane addressing
    int mat = lane >> 3;
    int arow8 = (mat & 1) * 8 + (lane & 7);
    int ahalf = mat >> 1;
    uint32_t aoff[4];
#pragma unroll
    for (int mt = 0; mt < 4; mt++) {
        int row = wm + mt * 16 + arow8;
        aoff[mt] = qsw(row, ahalf);
    }
    int bn8 = wn + ((mat >> 1) & 1) * 8 + (lane & 7);
    int bhalf = mat & 1;
    uint32_t boff = qsw(bn8, bhalf);

    qld_stage(sb, Aqh, Aql, Bqh, Bql, bm, bn, 0, M, tid);
    CP_COMMIT();

    const int NC = HH / 32;   // 16
    for (int kc = 0; kc < NC; kc++) {
        if (kc + 1 < NC) {
            qld_stage(sb + ((kc + 1) & 1) * QSTAGE, Aqh, Aql, Bqh, Bql, bm, bn, (kc + 1) * 32, M, tid);
            CP_COMMIT();
            asm volatile("cp.async.wait_group 1;");
        } else {
            asm volatile("cp.async.wait_group 0;");
        }
        __syncthreads();

        uint32_t sa = sb + (kc & 1) * QSTAGE;
        uint32_t ah[4][4], al[4][4], bq[2][4];
#pragma unroll
        for (int mt = 0; mt < 4; mt++) {
            LDSM_X4(ah[mt][0], ah[mt][1], ah[mt][2], ah[mt][3], sa + aoff[mt]);
            LDSM_X4(al[mt][0], al[mt][1], al[mt][2], al[mt][3], sa + 4096 + aoff[mt]);
        }
        LDSM_X4(bq[0][0], bq[0][1], bq[0][2], bq[0][3], sa + 8192 + boff);
        LDSM_X4(bq[1][0], bq[1][1], bq[1][2], bq[1][3], sa + 10240 + boff);

#pragma unroll
        for (int mt = 0; mt < 4; mt++) {
#pragma unroll
            for (int nt = 0; nt < 2; nt++) {
                // b regs: [plane][nt*2] = b0(khalf0), [nt*2+1] = b1(khalf1)
                IMMA16832(hh[mt][nt],  ah[mt][0], ah[mt][1], ah[mt][2], ah[mt][3], bq[0][nt*2], bq[0][nt*2+1]);
                IMMA16832(mid[mt][nt], ah[mt][0], ah[mt][1], ah[mt][2], ah[mt][3], bq[1][nt*2], bq[1][nt*2+1]);
                IMMA16832(mid[mt][nt], al[mt][0], al[mt][1], al[mt][2], al[mt][3], bq[0][nt*2], bq[0][nt*2+1]);
                IMMA16832(llv[mt][nt], al[mt][0], al[mt][1], al[mt][2], al[mt][3], bq[1][nt*2], bq[1][nt*2+1]);
            }
        }
        __syncthreads();
    }

    // epilogue: dequant + bias + relu -> smem staging [128][64] fp32
    float* stg = reinterpret_cast<float*>(smem);
    int r = lane >> 2, q = lane & 3;
#pragma unroll
    for (int mt = 0; mt < 4; mt++) {
        int lr0 = wm + mt * 16 + r;
        float sa0 = __ldg(&saq[bm + lr0]);
        float sa1 = __ldg(&saq[bm + lr0 + 8]);
#pragma unroll
        for (int nt = 0; nt < 2; nt++) {
            int lc = wn + nt * 8 + q * 2;
            int col = bn + lc;
            float sb0 = __ldg(&sbq[col]), sb1 = __ldg(&sbq[col + 1]);
            float b0 = bias[col], b1 = bias[col + 1];
            float f0 = 16384.f * (float)hh[mt][nt][0] + 128.f * (float)mid[mt][nt][0] + (float)llv[mt][nt][0];
            float f1 = 16384.f * (float)hh[mt][nt][1] + 128.f * (float)mid[mt][nt][1] + (float)llv[mt][nt][1];
            float f2 = 16384.f * (float)hh[mt][nt][2] + 128.f * (float)mid[mt][nt][2] + (float)llv[mt][nt][2];
            float f3 = 16384.f * (float)hh[mt][nt][3] + 128.f * (float)mid[mt][nt][3] + (float)llv[mt][nt][3];
            float v00 = fmaxf(f0 * sa0 * sb0 + b0, 0.f);
            float v01 = fmaxf(f1 * sa0 * sb1 + b1, 0.f);
            float v10 = fmaxf(f2 * sa1 * sb0 + b0, 0.f);
            float v11 = fmaxf(f3 * sa1 * sb1 + b1, 0.f);
            *reinterpret_cast<float2*>(stg + lr0 * 64 + lc) = make_float2(v00, v01);
            *reinterpret_cast<float2*>(stg + (lr0 + 8) * 64 + lc) = make_float2(v10, v11);
        }
    }
    __syncthreads();

    // scatter: 256 threads, thread covers (row = tid>>1, 32 cols)
    int row = tid >> 1;
    int half = (tid & 1) * 32;
    int gr = bm + row;
    if (gr < M) {
        const float* srow = stg + row * 64 + half;
        if (bn >= 512 && bn < 640) {
            int pc = bn - 512 + half;
#pragma unroll
            for (int i = 0; i < 8; i++) {
                float4 v = *reinterpret_cast<const float4*>(srow + i * 4);
                bf16 h0,l0,h1,l1,h2,l2,h3,l3;
                f32split(v.x,h0,l0); f32split(v.y,h1,l1); f32split(v.z,h2,l2); f32split(v.w,h3,l3);
                uint2 hp = make_uint2(bfpack(h0,h1), bfpack(h2,h3));
                uint2 lp = make_uint2(bfpack(l0,l1), bfpack(l2,l3));
                *reinterpret_cast<uint2*>(Pvh + (size_t)gr * DD + pc + i * 4) = hp;
                *reinterpret_cast<uint2*>(Pvl + (size_t)gr * DD + pc + i * 4) = lp;
            }
        } else {
            int obj = __ldg(&trip[3 * gr + ((bn < 512) ? 0 : 2)]);
            float* dst = pooled + (size_t)obj * HH + ((bn < 512) ? bn : bn - 640) + half;
#pragma unroll
            for (int i = 0; i < 8; i++) {
                float4 v = *reinterpret_cast<const float4*>(srow + i * 4);
                REDV4(dst + i * 4, v.x, v.y, v.z, v.w);
            }
        }
    }
}

// ================= attention epilogue =================
__global__ void scores_kernel(const float* __restrict__ ov,
                              const float* __restrict__ att_w,
                              const float* __restrict__ att_b,
                              float* __restrict__ scores) {
    int gid = blockIdx.x * blockDim.x + threadIdx.x;
    int w = gid >> 5, lane = gid & 31;
    if (w >= NUM_O) return;
    float sum = 0.f;
#pragma unroll
    for (int d = lane; d < DD; d += 32) sum += ov[(size_t)w * DD + d] * att_w[d];
#pragma unroll
    for (int off = 16; off; off >>= 1) sum += __shfl_down_sync(0xffffffff, sum, off);
    if (lane == 0) scores[w] = sum + att_b[0];
}

__global__ void segment_kernel(const float* __restrict__ scores,
                               const int* __restrict__ img,
                               const float* __restrict__ ov,
                               float* __restrict__ gvec) {
    int g = blockIdx.x, t = threadIdx.x;
    __shared__ float sred[128];
    __shared__ int ired[128];

    float m = -3.4e38f;
    int lo = NUM_O, hi = -1;
    for (int i = t; i < NUM_O; i += 128) {
        if (img[i] == g) {
            m = fmaxf(m, scores[i]);
            lo = min(lo, i);
            hi = max(hi, i);
        }
    }
    sred[t] = m; __syncthreads();
    for (int s = 64; s > 0; s >>= 1) { if (t < s) sred[t] = fmaxf(sred[t], sred[t + s]); __syncthreads(); }
    m = sred[0]; __syncthreads();
    ired[t] = lo; __syncthreads();
    for (int s = 64; s > 0; s >>= 1) { if (t < s) ired[t] = min(ired[t], ired[t + s]); __syncthreads(); }
    lo = ired[0]; __syncthreads();
    ired[t] = hi; __syncthreads();
    for (int s = 64; s > 0; s >>= 1) { if (t < s) ired[t] = max(ired[t], ired[t + s]); __syncthreads(); }
    hi = ired[0]; __syncthreads();

    float z = 0.f;
    for (int i = lo + t; i <= hi; i += 128)
        if (img[i] == g) z += expf(scores[i] - m);
    sred[t] = z; __syncthreads();
    for (int s = 64; s > 0; s >>= 1) { if (t < s) sred[t] += sred[t + s]; __syncthreads(); }
    z = sred[0];
    float invz = 1.f / z;

    float acc = 0.f;
    for (int i = lo; i <= hi; i++) {
        if (img[i] == g)
            acc += expf(scores[i] - m) * invz * ov[(size_t)i * DD + t];
    }
    gvec[g * DD + t] = acc;
}

__global__ void concat_kernel(const float* __restrict__ ov,
                              const float* __restrict__ gvec,
                              const int* __restrict__ img,
                              float* __restrict__ out) {
    int i = blockIdx.x, t = threadIdx.x;
    if (t < DD) out[(size_t)i * 256 + t] = ov[(size_t)i * DD + t];
    else        out[(size_t)i * 256 + t] = gvec[img[i] * DD + (t - DD)];
}

// ================= launch =================
extern "C" void kernel_launch(void* const* d_in, const int* in_sizes, int n_in,
                              void* d_out, int out_size) {
    const int*   objs     = (const int*)d_in[0];
    const int*   trip     = (const int*)d_in[1];
    const int*   img      = (const int*)d_in[2];
    const float* obj_emb  = (const float*)d_in[3];
    const float* pred_emb = (const float*)d_in[4];
    const float* n1w1     = (const float*)d_in[5];
    const float* n1b1     = (const float*)d_in[6];
    const float* n1w2     = (const float*)d_in[7];
    const float* n1b2     = (const float*)d_in[8];
    const float* n2w1     = (const float*)d_in[9];
    const float* n2b1     = (const float*)d_in[10];
    const float* n2w2     = (const float*)d_in[11];
    const float* n2b2     = (const float*)d_in[12];
    const float* att_w    = (const float*)d_in[13];
    const float* att_b    = (const float*)d_in[14];
    float* out = (float*)d_out;

    float *ov, *pooled, *counts, *inv, *scores, *gvec, *saq, *sbq;
    bf16 *ovh, *ovl, *pvh, *pvl, *hh, *hl, *h2h, *h2l;
    bf16 *w1h, *w1l, *w3h, *w3l, *w4h, *w4l;
    int8_t *qah, *qal, *qbh, *qbl;
    cudaGetSymbolAddress((void**)&ov,     g_ov);
    cudaGetSymbolAddress((void**)&pooled, g_pooled);
    cudaGetSymbolAddress((void**)&counts, g_counts);
    cudaGetSymbolAddress((void**)&inv,    g_invcnt);
    cudaGetSymbolAddress((void**)&scores, g_scores);
    cudaGetSymbolAddress((void**)&gvec,   g_gvec);
    cudaGetSymbolAddress((void**)&ovh, g_ovh); cudaGetSymbolAddress((void**)&ovl, g_ovl);
    cudaGetSymbolAddress((void**)&pvh, g_pvh); cudaGetSymbolAddress((void**)&pvl, g_pvl);
    cudaGetSymbolAddress((void**)&hh,  g_hh);  cudaGetSymbolAddress((void**)&hl,  g_hl);
    cudaGetSymbolAddress((void**)&h2h, g_h2h); cudaGetSymbolAddress((void**)&h2l, g_h2l);
    cudaGetSymbolAddress((void**)&w1h, g_w1h); cudaGetSymbolAddress((void**)&w1l, g_w1l);
    cudaGetSymbolAddress((void**)&w3h, g_w3h); cudaGetSymbolAddress((void**)&w3l, g_w3l);
    cudaGetSymbolAddress((void**)&w4h, g_w4h); cudaGetSymbolAddress((void**)&w4l, g_w4l);
    cudaGetSymbolAddress((void**)&qah, g_qah); cudaGetSymbolAddress((void**)&qal, g_qal);
    cudaGetSymbolAddress((void**)&qbh, g_qbh); cudaGetSymbolAddress((void**)&qbl, g_qbl);
    cudaGetSymbolAddress((void**)&saq, g_saq); cudaGetSymbolAddress((void**)&sbq, g_sbq);

    const int SMEM128 = 65536;                 // 2 stages bf16 TBM=128
    const int SMEM64  = 49152;                 // 2 stages bf16 TBM=64
    const int SMEMQ   = 32768;                 // max(2*12288, 128*64*4)
    const int SMEMWQ  = 32 * (HH + 2) * 4;     // 65792
    cudaFuncSetAttribute(gemm_hmma<1,1,128>, cudaFuncAttributeMaxDynamicSharedMemorySize, SMEM128);
    cudaFuncSetAttribute(gemm_hmma<2,1,64>,  cudaFuncAttributeMaxDynamicSharedMemorySize, SMEM64);
    cudaFuncSetAttribute(gemm_hmma<0,2,64>,  cudaFuncAttributeMaxDynamicSharedMemorySize, SMEM64);
    cudaFuncSetAttribute(gemm_imma_scatter,  cudaFuncAttributeMaxDynamicSharedMemorySize, SMEMQ);
    cudaFuncSetAttribute(wquant,             cudaFuncAttributeMaxDynamicSharedMemorySize, SMEMWQ);

    const int mT   = (NUM_T + 127) / 128;   // 157
    const int mO64 = (NUM_O + 63) / 64;     // 79

    // launch order: GEMM1(l0) at index 3 for ncu capture
    wtrans_split<<<dim3(HH/32, K1/32, LL), dim3(32,32)>>>(n1w1, w1h, w1l, K1, HH);   // 0
    gather_ov_init<<<NUM_O, DD>>>(obj_emb, objs, ovh, ovl);                          // 1
    gather_pv0<<<NUM_T, DD>>>(pred_emb, trip, pvh, pvl);                             // 2

    gemm_hmma<1,1,128><<<dim3(HH/BN, mT), 256, SMEM128>>>(                            // 3 (profiled)
        nullptr, nullptr, nullptr, nullptr, ovh, ovl, pvh, pvl, trip,
        w1h, w1l, n1b1, nullptr, hh, hl, NUM_T, HH, K1);

    wquant<<<dim3(N2/32, LL), 256, SMEMWQ>>>(n1w2, qbh, qbl, sbq, HH, N2);           // 4
    quant_rows<<<NUM_T, 128>>>(hh, hl, qah, qal, saq);                               // 5
    zero_kernel<<<(NUM_O + 255) / 256, 256>>>(counts, NUM_O);                        // 6
    count_kernel<<<(NUM_T + 255) / 256, 256>>>(trip, counts);                        // 7
    inv_kernel<<<(NUM_O + 255) / 256, 256>>>(counts, inv);                           // 8
    wtrans_split<<<dim3(HH/32, HH/32, LL), dim3(32,32)>>>(n2w1, w3h, w3l, HH, HH);   // 9
    wtrans_split<<<dim3(DD/32, HH/32, LL), dim3(32,32)>>>(n2w2, w4h, w4l, HH, DD);   // 10

    for (int l = 0; l < LL; l++) {
        if (l > 0) {
            gemm_hmma<1,1,128><<<dim3(HH/BN, mT), 256, SMEM128>>>(
                nullptr, nullptr, nullptr, nullptr, ovh, ovl, pvh, pvl, trip,
                w1h + (size_t)l*HH*K1, w1l + (size_t)l*HH*K1, n1b1 + (size_t)l*HH,
                nullptr, hh, hl, NUM_T, HH, K1);
            quant_rows<<<NUM_T, 128>>>(hh, hl, qah, qal, saq);
        }

        zero_kernel<<<(NUM_O * HH + 255) / 256, 256>>>(pooled, NUM_O * HH);

        gemm_imma_scatter<<<dim3(N2/64, mT), 256, SMEMQ>>>(
            qah, qal, saq,
            qbh + (size_t)l*N2*HH, qbl + (size_t)l*N2*HH, sbq + (size_t)l*N2,
            trip, n1b2 + (size_t)l*N2,
            pooled, pvh, pvl, NUM_T);

        gemm_hmma<2,1,64><<<dim3(HH/BN, mO64), 256, SMEM64>>>(
            nullptr, nullptr, pooled, inv, nullptr, nullptr, nullptr, nullptr, trip,
            w3h + (size_t)l*HH*HH, w3l + (size_t)l*HH*HH, n2b1 + (size_t)l*HH,
            nullptr, h2h, h2l, NUM_O, HH, HH);

        gemm_hmma<0,2,64><<<dim3(DD/BN, mO64), 256, SMEM64>>>(
            h2h, h2l, nullptr, nullptr, nullptr, nullptr, nullptr, nullptr, trip,
            w4h + (size_t)l*DD*HH, w4l + (size_t)l*DD*HH, n2b2 + (size_t)l*DD,
            ov, ovh, ovl, NUM_O, DD, HH);
    }

    scores_kernel<<<(NUM_O * 32 + 255) / 256, 256>>>(ov, att_w, att_b, scores);
    segment_kernel<<<GG, 128>>>(scores, img, ov, gvec);
    concat_kernel<<<NUM_O, 256>>>(ov, gvec, img, out);
}

// round 8
// speedup vs baseline: 3.5046x; 3.5046x over previous
#include <cuda_runtime.h>
#include <cuda_bf16.h>
#include <math.h>
#include <stdint.h>

#define NUM_O   5000
#define NUM_T   20000
#define DD      128
#define HH      512
#define GG      64
#define LL      5
#define K1      (3*DD)        // 384
#define N2      (2*HH+DD)     // 1152

typedef __nv_bfloat16 bf16;

// ================= scratch =================
__device__ float g_ov    [NUM_O * DD];
__device__ float g_pooled[NUM_O * HH];
__device__ float g_counts[NUM_O];
__device__ float g_invcnt[NUM_O];
__device__ float g_scores[NUM_O];
__device__ float g_gvec  [GG * DD];
__device__ float g_Us    [NUM_O * HH];
__device__ float g_Uo    [NUM_O * HH];

__device__ bf16 g_ovh[NUM_O * DD], g_ovl[NUM_O * DD];
__device__ bf16 g_pvh[NUM_T * DD], g_pvl[NUM_T * DD];
__device__ bf16 g_hh [NUM_T * HH], g_hl [NUM_T * HH];
__device__ bf16 g_h2h[NUM_O * HH], g_h2l[NUM_O * HH];

__device__ bf16 g_w1h[LL * HH * K1], g_w1l[LL * HH * K1];
__device__ bf16 g_w2h[LL * N2 * HH], g_w2l[LL * N2 * HH];
__device__ bf16 g_w3h[LL * HH * HH], g_w3l[LL * HH * HH];
__device__ bf16 g_w4h[LL * DD * HH], g_w4l[LL * DD * HH];

__device__ __forceinline__ void f32split(float v, bf16& h, bf16& l) {
    h = __float2bfloat16(v);
    l = __float2bfloat16(v - __bfloat162float(h));
}
__device__ __forceinline__ uint32_t bfpack(bf16 a, bf16 b) {
    __nv_bfloat162 t; t.x = a; t.y = b;
    return *reinterpret_cast<uint32_t*>(&t);
}
__device__ __forceinline__ uint32_t smem_u32(const void* p) {
    uint32_t a;
    asm("{ .reg .u64 t; cvta.to.shared.u64 t, %1; cvt.u32.u64 %0, t; }" : "=r"(a) : "l"(p));
    return a;
}

// ================= glue =================
__global__ void zero_kernel(float* p, int n) {
    int i = blockIdx.x * blockDim.x + threadIdx.x;
    if (i < n) p[i] = 0.f;
}
__global__ void gather_ov_init(const float* __restrict__ obj_emb,
                               const int* __restrict__ objs,
                               bf16* __restrict__ ovh, bf16* __restrict__ ovl) {
    int i = blockIdx.x, d = threadIdx.x;
    float v = obj_emb[objs[i] * DD + d];
    bf16 h, l; f32split(v, h, l);
    ovh[i * DD + d] = h; ovl[i * DD + d] = l;
}
__global__ void gather_pv0(const float* __restrict__ pred_emb,
                           const int* __restrict__ trip,
                           bf16* __restrict__ pvh, bf16* __restrict__ pvl) {
    int i = blockIdx.x, d = threadIdx.x;
    int p = trip[3 * i + 1];
    float v = pred_emb[p * DD + d];
    bf16 h, l; f32split(v, h, l);
    pvh[i * DD + d] = h; pvl[i * DD + d] = l;
}
__global__ void count_kernel(const int* __restrict__ trip, float* __restrict__ counts) {
    int i = blockIdx.x * blockDim.x + threadIdx.x;
    if (i < NUM_T) {
        atomicAdd(&counts[trip[3 * i + 0]], 1.f);
        atomicAdd(&counts[trip[3 * i + 2]], 1.f);
    }
}
__global__ void inv_kernel(const float* __restrict__ counts, float* __restrict__ inv) {
    int i = blockIdx.x * blockDim.x + threadIdx.x;
    if (i < NUM_O) inv[i] = 1.f / fmaxf(counts[i], 1.f);
}
__global__ void wtrans_split(const float* __restrict__ w,
                             bf16* __restrict__ oh,
                             bf16* __restrict__ ol, int K, int N) {
    __shared__ float tile[32][33];
    int l = blockIdx.z;
    int k0 = blockIdx.y * 32, n0 = blockIdx.x * 32;
    const float* wl = w + (size_t)l * K * N;
    tile[threadIdx.y][threadIdx.x] = wl[(size_t)(k0 + threadIdx.y) * N + n0 + threadIdx.x];
    __syncthreads();
    int on = n0 + threadIdx.y, ok = k0 + threadIdx.x;
    float v = tile[threadIdx.x][threadIdx.y];
    bf16 h, lo; f32split(v, h, lo);
    size_t idx = ((size_t)l * N + on) * K + ok;
    oh[idx] = h; ol[idx] = lo;
}

// ================= HMMA GEMM =================
// C = A @ B^T (+bias, relu per OUT_MODE), 3-term bf16 split, fp32 accum.
// A_MODE 0: Ah/Al [M,K]. 2: fp32 Af * inv[row], split on the fly.
// OUT_MODE 0: raw fp32. 1: bias+relu bf16 pair. 2: bias+relu fp32 + bf16 pair.
//          3: smem-staged scatter (red.v4 + pv block). 5: relu(acc+bias+Us[s]+Uo[o]) bf16 pair.
#define BN   128
#define BK   32

#define CP_ASYNC16(dst, src, sz) \
    asm volatile("cp.async.cg.shared.global [%0], [%1], 16, %2;" :: "r"(dst), "l"(src), "r"(sz))
#define CP_COMMIT() asm volatile("cp.async.commit_group;")
#define LDSM_X4(R0,R1,R2,R3,ADDR) \
    asm volatile("ldmatrix.sync.aligned.m8n8.x4.shared.b16 {%0,%1,%2,%3}, [%4];" \
                 : "=r"(R0),"=r"(R1),"=r"(R2),"=r"(R3) : "r"(ADDR))
#define MMA16816(C,A0,A1,A2,A3,B0,B1) \
    asm volatile("mma.sync.aligned.m16n8k16.row.col.f32.bf16.bf16.f32 " \
                 "{%0,%1,%2,%3},{%4,%5,%6,%7},{%8,%9},{%0,%1,%2,%3};" \
                 : "+f"((C)[0]),"+f"((C)[1]),"+f"((C)[2]),"+f"((C)[3]) \
                 : "r"(A0),"r"(A1),"r"(A2),"r"(A3),"r"(B0),"r"(B1))
#define STS128(ADDR,A,B,C,D) \
    asm volatile("st.shared.v4.b32 [%0], {%1,%2,%3,%4};" :: "r"(ADDR),"r"(A),"r"(B),"r"(C),"r"(D))
#define REDV4(PTR,X,Y,Z,W) \
    asm volatile("red.global.add.v4.f32 [%0], {%1,%2,%3,%4};" :: "l"(PTR),"f"(X),"f"(Y),"f"(Z),"f"(W) : "memory")

__device__ __forceinline__ uint32_t sw_off(int row, int c) {
    return (uint32_t)(row * 64 + (((c ^ (row & 3))) << 4));
}

template <int A_MODE, int TBM>
__device__ __forceinline__ void ld_stage(
    uint32_t st,
    const bf16* __restrict__ Ah, const bf16* __restrict__ Al,
    const float* __restrict__ Af, const float* __restrict__ inv,
    const bf16* __restrict__ Bh, const bf16* __restrict__ Bl, int Bstride,
    int bm, int bn, int k0, int M, int K, int tid)
{
    constexpr uint32_t OFF_AL = TBM * 64;
    constexpr uint32_t OFF_BH = TBM * 128;
    constexpr uint32_t OFF_BL = TBM * 128 + 8192;
#pragma unroll
    for (int lin = tid; lin < TBM * 4; lin += 256) {
        int row = lin >> 2;
        int c   = lin & 3;
        uint32_t so = sw_off(row, c);
        int gr = bm + row;
        bool ok = gr < M;
        if (A_MODE == 2) {
            if (ok) {
                const float4* src = reinterpret_cast<const float4*>(Af + (size_t)gr * K + k0 + c * 8);
                float4 v0 = src[0], v1 = src[1];
                float s = __ldg(&inv[gr]);
                bf16 hb[8], lb[8];
                float vals[8] = {v0.x*s, v0.y*s, v0.z*s, v0.w*s, v1.x*s, v1.y*s, v1.z*s, v1.w*s};
#pragma unroll
                for (int j = 0; j < 8; j++) f32split(vals[j], hb[j], lb[j]);
                STS128(st + so, bfpack(hb[0],hb[1]), bfpack(hb[2],hb[3]), bfpack(hb[4],hb[5]), bfpack(hb[6],hb[7]));
                STS128(st + OFF_AL + so, bfpack(lb[0],lb[1]), bfpack(lb[2],lb[3]), bfpack(lb[4],lb[5]), bfpack(lb[6],lb[7]));
            } else {
                STS128(st + so, 0u, 0u, 0u, 0u);
                STS128(st + OFF_AL + so, 0u, 0u, 0u, 0u);
            }
        } else {
            uint32_t sz = ok ? 16u : 0u;
            size_t srow = ok ? (size_t)gr : 0;
            const char* sh = (const char*)(Ah + srow * K + k0 + c * 8);
            const char* sl = (const char*)(Al + srow * K + k0 + c * 8);
            CP_ASYNC16(st + so, sh, sz);
            CP_ASYNC16(st + OFF_AL + so, sl, sz);
        }
    }
#pragma unroll
    for (int lin = tid; lin < 512; lin += 256) {
        int row = lin >> 2;
        int c   = lin & 3;
        uint32_t so = sw_off(row, c);
        int gr = bn + row;
        const char* sh = (const char*)(Bh + (size_t)gr * Bstride + k0 + c * 8);
        const char* sl = (const char*)(Bl + (size_t)gr * Bstride + k0 + c * 8);
        CP_ASYNC16(st + OFF_BH + so, sh, 16u);
        CP_ASYNC16(st + OFF_BL + so, sl, 16u);
    }
}

template <int A_MODE, int OUT_MODE, int TBM>
__global__ void __launch_bounds__(256)
gemm_hmma(const bf16* __restrict__ Ah, const bf16* __restrict__ Al,
          const float* __restrict__ Af, const float* __restrict__ inv,
          const int* __restrict__ trip,
          const bf16* __restrict__ Bh, const bf16* __restrict__ Bl, int Bstride,
          const float* __restrict__ bias,
          const float* __restrict__ Us, const float* __restrict__ Uo,
          float* __restrict__ Cf,
          bf16* __restrict__ Ch, bf16* __restrict__ Cl,
          float* __restrict__ pooled,
          bf16* __restrict__ Pvh, bf16* __restrict__ Pvl,
          int M, int N, int K)
{
    constexpr uint32_t OFF_AL = TBM * 64;
    constexpr uint32_t OFF_BH = TBM * 128;
    constexpr uint32_t OFF_BL = TBM * 128 + 8192;
    constexpr uint32_t STAGE  = TBM * 128 + 16384;
    constexpr int NWM = (TBM == 128) ? 2 : 1;
    constexpr int NT  = (TBM == 128) ? 4 : 2;

    extern __shared__ char smem[];
    uint32_t sb = smem_u32(smem);

    int tid = threadIdx.x;
    int wid = tid >> 5, lane = tid & 31;
    int wm = (wid % NWM) * 64;
    int wn = (wid / NWM) * (NT * 8);
    int bm = blockIdx.y * TBM;
    int bn = blockIdx.x * BN;
    const int NC = K / BK;

    float acc[4][NT][4];
#pragma unroll
    for (int i = 0; i < 4; i++)
#pragma unroll
        for (int j = 0; j < NT; j++)
#pragma unroll
            for (int r = 0; r < 4; r++) acc[i][j][r] = 0.f;

    int lrow8 = (lane & 7) + ((lane >> 3) & 1) * 8;
    int lchunk = (lane >> 4);

    ld_stage<A_MODE, TBM>(sb, Ah, Al, Af, inv, Bh, Bl, Bstride, bm, bn, 0, M, K, tid);
    CP_COMMIT();

    for (int kc = 0; kc < NC; kc++) {
        if (kc + 1 < NC) {
            ld_stage<A_MODE, TBM>(sb + ((kc + 1) & 1) * STAGE, Ah, Al, Af, inv, Bh, Bl, Bstride,
                                  bm, bn, (kc + 1) * BK, M, K, tid);
            CP_COMMIT();
            asm volatile("cp.async.wait_group 1;");
        } else {
            asm volatile("cp.async.wait_group 0;");
        }
        __syncthreads();

        uint32_t sa = sb + (kc & 1) * STAGE;
#pragma unroll
        for (int ks = 0; ks < 2; ks++) {
            int c0 = ks * 2;
            uint32_t ah[4][4], al[4][4], bh[NT][2], bl[NT][2];
#pragma unroll
            for (int mt = 0; mt < 4; mt++) {
                int row = wm + mt * 16 + lrow8;
                uint32_t addr = sa + sw_off(row, c0 + lchunk);
                LDSM_X4(ah[mt][0], ah[mt][1], ah[mt][2], ah[mt][3], addr);
            }
#pragma unroll
            for (int np = 0; np < NT / 2; np++) {
                int row = wn + np * 16 + lrow8;
                uint32_t addr = sa + OFF_BH + sw_off(row, c0 + lchunk);
                uint32_t r0, r1, r2, r3;
                LDSM_X4(r0, r1, r2, r3, addr);
                bh[2*np][0] = r0; bh[2*np+1][0] = r1;
                bh[2*np][1] = r2; bh[2*np+1][1] = r3;
            }
#pragma unroll
            for (int mt = 0; mt < 4; mt++)
#pragma unroll
                for (int nt = 0; nt < NT; nt++)
                    MMA16816(acc[mt][nt], ah[mt][0], ah[mt][1], ah[mt][2], ah[mt][3],
                             bh[nt][0], bh[nt][1]);
#pragma unroll
            for (int np = 0; np < NT / 2; np++) {
                int row = wn + np * 16 + lrow8;
                uint32_t addr = sa + OFF_BL + sw_off(row, c0 + lchunk);
                uint32_t r0, r1, r2, r3;
                LDSM_X4(r0, r1, r2, r3, addr);
                bl[2*np][0] = r0; bl[2*np+1][0] = r1;
                bl[2*np][1] = r2; bl[2*np+1][1] = r3;
            }
#pragma unroll
            for (int mt = 0; mt < 4; mt++)
#pragma unroll
                for (int nt = 0; nt < NT; nt++)
                    MMA16816(acc[mt][nt], ah[mt][0], ah[mt][1], ah[mt][2], ah[mt][3],
                             bl[nt][0], bl[nt][1]);
#pragma unroll
            for (int mt = 0; mt < 4; mt++) {
                int row = wm + mt * 16 + lrow8;
                uint32_t addr = sa + OFF_AL + sw_off(row, c0 + lchunk);
                LDSM_X4(al[mt][0], al[mt][1], al[mt][2], al[mt][3], addr);
            }
#pragma unroll
            for (int mt = 0; mt < 4; mt++)
#pragma unroll
                for (int nt = 0; nt < NT; nt++)
                    MMA16816(acc[mt][nt], al[mt][0], al[mt][1], al[mt][2], al[mt][3],
                             bh[nt][0], bh[nt][1]);
        }
        __syncthreads();
    }

    int r = lane >> 2, q = lane & 3;

    if (OUT_MODE == 3) {
        // stage bias+relu'd tile to smem (128x128 fp32 = 64KB), then scatter
#pragma unroll
        for (int mt = 0; mt < 4; mt++) {
            int lr0 = wm + mt * 16 + r;
#pragma unroll
            for (int nt = 0; nt < NT; nt++) {
                int lc = wn + nt * 8 + q * 2;
                int col = bn + lc;
                float b0 = bias[col], b1 = bias[col + 1];
                float2 v0 = make_float2(fmaxf(acc[mt][nt][0] + b0, 0.f), fmaxf(acc[mt][nt][1] + b1, 0.f));
                float2 v1 = make_float2(fmaxf(acc[mt][nt][2] + b0, 0.f), fmaxf(acc[mt][nt][3] + b1, 0.f));
                *reinterpret_cast<float2*>(smem + ((size_t)lr0 * 128 + lc) * 4) = v0;
                *reinterpret_cast<float2*>(smem + ((size_t)(lr0 + 8) * 128 + lc) * 4) = v1;
            }
        }
        __syncthreads();
        int row = tid >> 1;
        int half = (tid & 1) * 64;
        int gr = bm + row;
        if (gr < M) {
            const float* srow = reinterpret_cast<const float*>(smem) + (size_t)row * 128 + half;
            if (bn == 512) {
#pragma unroll
                for (int i = 0; i < 16; i++) {
                    float4 v = *reinterpret_cast<const float4*>(srow + i * 4);
                    bf16 h0,l0,h1,l1,h2,l2,h3,l3;
                    f32split(v.x,h0,l0); f32split(v.y,h1,l1); f32split(v.z,h2,l2); f32split(v.w,h3,l3);
                    uint2 hp = make_uint2(bfpack(h0,h1), bfpack(h2,h3));
                    uint2 lp = make_uint2(bfpack(l0,l1), bfpack(l2,l3));
                    int pc = half + i * 4;
                    *reinterpret_cast<uint2*>(Pvh + (size_t)gr * DD + pc) = hp;
                    *reinterpret_cast<uint2*>(Pvl + (size_t)gr * DD + pc) = lp;
                }
            } else {
                int obj = __ldg(&trip[3 * gr + ((bn < 512) ? 0 : 2)]);
                float* dst = pooled + (size_t)obj * HH + ((bn < 512) ? bn : bn - 640) + half;
#pragma unroll
                for (int i = 0; i < 16; i++) {
                    float4 v = *reinterpret_cast<const float4*>(srow + i * 4);
                    REDV4(dst + i * 4, v.x, v.y, v.z, v.w);
                }
            }
        }
        return;
    }

#pragma unroll
    for (int mt = 0; mt < 4; mt++) {
        int row0 = bm + wm + mt * 16 + r;
        int row1 = row0 + 8;
        int s0 = 0, o0 = 0, s1 = 0, o1 = 0;
        if (OUT_MODE == 5) {
            if (row0 < M) { s0 = __ldg(&trip[3 * row0]); o0 = __ldg(&trip[3 * row0 + 2]); }
            if (row1 < M) { s1 = __ldg(&trip[3 * row1]); o1 = __ldg(&trip[3 * row1 + 2]); }
        }
#pragma unroll
        for (int nt = 0; nt < NT; nt++) {
            int col = bn + wn + nt * 8 + q * 2;
            if (OUT_MODE == 0) {
                if (row0 < M)
                    *reinterpret_cast<float2*>(Cf + (size_t)row0 * N + col) = make_float2(acc[mt][nt][0], acc[mt][nt][1]);
                if (row1 < M)
                    *reinterpret_cast<float2*>(Cf + (size_t)row1 * N + col) = make_float2(acc[mt][nt][2], acc[mt][nt][3]);
                continue;
            }
            float b0 = bias[col], b1 = bias[col + 1];
            float a00 = acc[mt][nt][0] + b0, a01 = acc[mt][nt][1] + b1;
            float a10 = acc[mt][nt][2] + b0, a11 = acc[mt][nt][3] + b1;
            if (OUT_MODE == 5) {
                if (row0 < M) {
                    float2 us = *reinterpret_cast<const float2*>(Us + (size_t)s0 * HH + col);
                    float2 uo = *reinterpret_cast<const float2*>(Uo + (size_t)o0 * HH + col);
                    a00 += us.x + uo.x; a01 += us.y + uo.y;
                }
                if (row1 < M) {
                    float2 us = *reinterpret_cast<const float2*>(Us + (size_t)s1 * HH + col);
                    float2 uo = *reinterpret_cast<const float2*>(Uo + (size_t)o1 * HH + col);
                    a10 += us.x + uo.x; a11 += us.y + uo.y;
                }
            }
            float v00 = fmaxf(a00, 0.f), v01 = fmaxf(a01, 0.f);
            float v10 = fmaxf(a10, 0.f), v11 = fmaxf(a11, 0.f);
            bf16 h0, l0, h1, l1;
            if (row0 < M) {
                if (OUT_MODE == 2)
                    *reinterpret_cast<float2*>(Cf + (size_t)row0 * N + col) = make_float2(v00, v01);
                f32split(v00, h0, l0); f32split(v01, h1, l1);
                *reinterpret_cast<uint32_t*>(Ch + (size_t)row0 * N + col) = bfpack(h0, h1);
                *reinterpret_cast<uint32_t*>(Cl + (size_t)row0 * N + col) = bfpack(l0, l1);
            }
            if (row1 < M) {
                if (OUT_MODE == 2)
                    *reinterpret_cast<float2*>(Cf + (size_t)row1 * N + col) = make_float2(v10, v11);
                f32split(v10, h0, l0); f32split(v11, h1, l1);
                *reinterpret_cast<uint32_t*>(Ch + (size_t)row1 * N + col) = bfpack(h0, h1);
                *reinterpret_cast<uint32_t*>(Cl + (size_t)row1 * N + col) = bfpack(l0, l1);
            }
        }
    }
}

// ================= attention epilogue =================
__global__ void scores_kernel(const float* __restrict__ ov,
                              const float* __restrict__ att_w,
                              const float* __restrict__ att_b,
                              float* __restrict__ scores) {
    int gid = blockIdx.x * blockDim.x + threadIdx.x;
    int w = gid >> 5, lane = gid & 31;
    if (w >= NUM_O) return;
    float sum = 0.f;
#pragma unroll
    for (int d = lane; d < DD; d += 32) sum += ov[(size_t)w * DD + d] * att_w[d];
#pragma unroll
    for (int off = 16; off; off >>= 1) sum += __shfl_down_sync(0xffffffff, sum, off);
    if (lane == 0) scores[w] = sum + att_b[0];
}

__global__ void segment_kernel(const float* __restrict__ scores,
                               const int* __restrict__ img,
                               const float* __restrict__ ov,
                               float* __restrict__ gvec) {
    int g = blockIdx.x, t = threadIdx.x;
    __shared__ float sred[128];
    __shared__ int ired[128];

    float m = -3.4e38f;
    int lo = NUM_O, hi = -1;
    for (int i = t; i < NUM_O; i += 128) {
        if (img[i] == g) {
            m = fmaxf(m, scores[i]);
            lo = min(lo, i);
            hi = max(hi, i);
        }
    }
    sred[t] = m; __syncthreads();
    for (int s = 64; s > 0; s >>= 1) { if (t < s) sred[t] = fmaxf(sred[t], sred[t + s]); __syncthreads(); }
    m = sred[0]; __syncthreads();
    ired[t] = lo; __syncthreads();
    for (int s = 64; s > 0; s >>= 1) { if (t < s) ired[t] = min(ired[t], ired[t + s]); __syncthreads(); }
    lo = ired[0]; __syncthreads();
    ired[t] = hi; __syncthreads();
    for (int s = 64; s > 0; s >>= 1) { if (t < s) ired[t] = max(ired[t], ired[t + s]); __syncthreads(); }
    hi = ired[0]; __syncthreads();

    float z = 0.f;
    for (int i = lo + t; i <= hi; i += 128)
        if (img[i] == g) z += expf(scores[i] - m);
    sred[t] = z; __syncthreads();
    for (int s = 64; s > 0; s >>= 1) { if (t < s) sred[t] += sred[t + s]; __syncthreads(); }
    z = sred[0];
    float invz = 1.f / z;

    float acc = 0.f;
    for (int i = lo; i <= hi; i++) {
        if (img[i] == g)
            acc += expf(scores[i] - m) * invz * ov[(size_t)i * DD + t];
    }
    gvec[g * DD + t] = acc;
}

__global__ void concat_kernel(const float* __restrict__ ov,
                              const float* __restrict__ gvec,
                              const int* __restrict__ img,
                              float* __restrict__ out) {
    int i = blockIdx.x, t = threadIdx.x;
    if (t < DD) out[(size_t)i * 256 + t] = ov[(size_t)i * DD + t];
    else        out[(size_t)i * 256 + t] = gvec[img[i] * DD + (t - DD)];
}

// ================= launch =================
extern "C" void kernel_launch(void* const* d_in, const int* in_sizes, int n_in,
                              void* d_out, int out_size) {
    const int*   objs     = (const int*)d_in[0];
    const int*   trip     = (const int*)d_in[1];
    const int*   img      = (const int*)d_in[2];
    const float* obj_emb  = (const float*)d_in[3];
    const float* pred_emb = (const float*)d_in[4];
    const float* n1w1     = (const float*)d_in[5];
    const float* n1b1     = (const float*)d_in[6];
    const float* n1w2     = (const float*)d_in[7];
    const float* n1b2     = (const float*)d_in[8];
    const float* n2w1     = (const float*)d_in[9];
    const float* n2b1     = (const float*)d_in[10];
    const float* n2w2     = (const float*)d_in[11];
    const float* n2b2     = (const float*)d_in[12];
    const float* att_w    = (const float*)d_in[13];
    const float* att_b    = (const float*)d_in[14];
    float* out = (float*)d_out;

    float *ov, *pooled, *counts, *inv, *scores, *gvec, *Us, *Uo;
    bf16 *ovh, *ovl, *pvh, *pvl, *hh, *hl, *h2h, *h2l;
    bf16 *w1h, *w1l, *w2h, *w2l, *w3h, *w3l, *w4h, *w4l;
    cudaGetSymbolAddress((void**)&ov,     g_ov);
    cudaGetSymbolAddress((void**)&pooled, g_pooled);
    cudaGetSymbolAddress((void**)&counts, g_counts);
    cudaGetSymbolAddress((void**)&inv,    g_invcnt);
    cudaGetSymbolAddress((void**)&scores, g_scores);
    cudaGetSymbolAddress((void**)&gvec,   g_gvec);
    cudaGetSymbolAddress((void**)&Us,     g_Us);
    cudaGetSymbolAddress((void**)&Uo,     g_Uo);
    cudaGetSymbolAddress((void**)&ovh, g_ovh); cudaGetSymbolAddress((void**)&ovl, g_ovl);
    cudaGetSymbolAddress((void**)&pvh, g_pvh); cudaGetSymbolAddress((void**)&pvl, g_pvl);
    cudaGetSymbolAddress((void**)&hh,  g_hh);  cudaGetSymbolAddress((void**)&hl,  g_hl);
    cudaGetSymbolAddress((void**)&h2h, g_h2h); cudaGetSymbolAddress((void**)&h2l, g_h2l);
    cudaGetSymbolAddress((void**)&w1h, g_w1h); cudaGetSymbolAddress((void**)&w1l, g_w1l);
    cudaGetSymbolAddress((void**)&w2h, g_w2h); cudaGetSymbolAddress((void**)&w2l, g_w2l);
    cudaGetSymbolAddress((void**)&w3h, g_w3h); cudaGetSymbolAddress((void**)&w3l, g_w3l);
    cudaGetSymbolAddress((void**)&w4h, g_w4h); cudaGetSymbolAddress((void**)&w4l, g_w4l);

    const int SMEM128 = 65536;   // 2 stages x 32KB (== 64KB epi staging for OUT3)
    const int SMEM64  = 49152;   // 2 stages x 24KB
    cudaFuncSetAttribute(gemm_hmma<0,0,64>,  cudaFuncAttributeMaxDynamicSharedMemorySize, SMEM64);
    cudaFuncSetAttribute(gemm_hmma<0,5,128>, cudaFuncAttributeMaxDynamicSharedMemorySize, SMEM128);
    cudaFuncSetAttribute(gemm_hmma<0,3,128>, cudaFuncAttributeMaxDynamicSharedMemorySize, SMEM128);
    cudaFuncSetAttribute(gemm_hmma<2,1,64>,  cudaFuncAttributeMaxDynamicSharedMemorySize, SMEM64);
    cudaFuncSetAttribute(gemm_hmma<0,2,64>,  cudaFuncAttributeMaxDynamicSharedMemorySize, SMEM64);

    const int mT   = (NUM_T + 127) / 128;   // 157
    const int mO64 = (NUM_O + 63) / 64;     // 79

    // ---- prologue (index 3 = U_s GEMM, profiled by ncu) ----
    wtrans_split<<<dim3(HH/32, K1/32, LL), dim3(32,32)>>>(n1w1, w1h, w1l, K1, HH);   // 0
    gather_ov_init<<<NUM_O, DD>>>(obj_emb, objs, ovh, ovl);                          // 1
    gather_pv0<<<NUM_T, DD>>>(pred_emb, trip, pvh, pvl);                             // 2

    gemm_hmma<0,0,64><<<dim3(HH/BN, mO64), 256, SMEM64>>>(                            // 3 (profiled)
        ovh, ovl, nullptr, nullptr, nullptr,
        w1h, w1l, K1, nullptr, nullptr, nullptr,
        Us, nullptr, nullptr, nullptr, nullptr, nullptr, NUM_O, HH, DD);

    gemm_hmma<0,0,64><<<dim3(HH/BN, mO64), 256, SMEM64>>>(                            // 4
        ovh, ovl, nullptr, nullptr, nullptr,
        w1h + 2*DD, w1l + 2*DD, K1, nullptr, nullptr, nullptr,
        Uo, nullptr, nullptr, nullptr, nullptr, nullptr, NUM_O, HH, DD);

    wtrans_split<<<dim3(N2/32, HH/32, LL), dim3(32,32)>>>(n1w2, w2h, w2l, HH, N2);   // 5
    zero_kernel<<<(NUM_O + 255) / 256, 256>>>(counts, NUM_O);                        // 6
    count_kernel<<<(NUM_T + 255) / 256, 256>>>(trip, counts);                        // 7
    inv_kernel<<<(NUM_O + 255) / 256, 256>>>(counts, inv);                           // 8
    wtrans_split<<<dim3(HH/32, HH/32, LL), dim3(32,32)>>>(n2w1, w3h, w3l, HH, HH);   // 9
    wtrans_split<<<dim3(DD/32, HH/32, LL), dim3(32,32)>>>(n2w2, w4h, w4l, HH, DD);   // 10

    for (int l = 0; l < LL; l++) {
        const bf16* w1hl = w1h + (size_t)l * HH * K1;
        const bf16* w1ll = w1l + (size_t)l * HH * K1;
        if (l > 0) {
            // Us/Uo from updated ov
            gemm_hmma<0,0,64><<<dim3(HH/BN, mO64), 256, SMEM64>>>(
                ovh, ovl, nullptr, nullptr, nullptr,
                w1hl, w1ll, K1, nullptr, nullptr, nullptr,
                Us, nullptr, nullptr, nullptr, nullptr, nullptr, NUM_O, HH, DD);
            gemm_hmma<0,0,64><<<dim3(HH/BN, mO64), 256, SMEM64>>>(
                ovh, ovl, nullptr, nullptr, nullptr,
                w1hl + 2*DD, w1ll + 2*DD, K1, nullptr, nullptr, nullptr,
                Uo, nullptr, nullptr, nullptr, nullptr, nullptr, NUM_O, HH, DD);
        }

        // pv GEMM + fused gather-add epilogue: h = relu(pv@Wp + Us[s] + Uo[o] + b1)
        gemm_hmma<0,5,128><<<dim3(HH/BN, mT), 256, SMEM128>>>(
            pvh, pvl, nullptr, nullptr, trip,
            w1hl + DD, w1ll + DD, K1, n1b1 + (size_t)l*HH, Us, Uo,
            nullptr, hh, hl, nullptr, nullptr, nullptr, NUM_T, HH, DD);

        zero_kernel<<<(NUM_O * HH + 255) / 256, 256>>>(pooled, NUM_O * HH);

        // GEMM2: fused smem-staged scatter
        gemm_hmma<0,3,128><<<dim3(N2/BN, mT), 256, SMEM128>>>(
            hh, hl, nullptr, nullptr, trip,
            w2h + (size_t)l*N2*HH, w2l + (size_t)l*N2*HH, HH, n1b2 + (size_t)l*N2,
            nullptr, nullptr,
            nullptr, nullptr, nullptr, pooled, pvh, pvl, NUM_T, N2, HH);

        // GEMM3: fused scale+split loader
        gemm_hmma<2,1,64><<<dim3(HH/BN, mO64), 256, SMEM64>>>(
            nullptr, nullptr, pooled, inv, nullptr,
            w3h + (size_t)l*HH*HH, w3l + (size_t)l*HH*HH, HH, n2b1 + (size_t)l*HH,
            nullptr, nullptr,
            nullptr, h2h, h2l, nullptr, nullptr, nullptr, NUM_O, HH, HH);

        // GEMM4: ov fp32 + bf16 pair
        gemm_hmma<0,2,64><<<dim3(DD/BN, mO64), 256, SMEM64>>>(
            h2h, h2l, nullptr, nullptr, nullptr,
            w4h + (size_t)l*DD*HH, w4l + (size_t)l*DD*HH, HH, n2b2 + (size_t)l*DD,
            nullptr, nullptr,
            ov, ovh, ovl, nullptr, nullptr, nullptr, NUM_O, DD, HH);
    }

    scores_kernel<<<(NUM_O * 32 + 255) / 256, 256>>>(ov, att_w, att_b, scores);
    segment_kernel<<<GG, 128>>>(scores, img, ov, gvec);
    concat_kernel<<<NUM_O, 256>>>(ov, gvec, img, out);
}

// round 10
// speedup vs baseline: 3.5427x; 1.0109x over previous
#include <cuda_runtime.h>
#include <cuda_bf16.h>
#include <math.h>
#include <stdint.h>

#define NUM_O   5000
#define NUM_T   20000
#define DD      128
#define HH      512
#define GG      64
#define LL      5
#define K1      (3*DD)        // 384
#define N2      (2*HH+DD)     // 1152

typedef __nv_bfloat16 bf16;

// ================= scratch =================
__device__ float g_ov    [NUM_O * DD];
__device__ float g_pooled[NUM_O * HH];
__device__ float g_counts[NUM_O];
__device__ float g_invcnt[NUM_O];
__device__ float g_scores[NUM_O];
__device__ float g_gvec  [GG * DD];
__device__ float g_U     [2 * NUM_O * HH];   // [Us | Uo]

__device__ bf16 g_ovh[NUM_O * DD], g_ovl[NUM_O * DD];
__device__ bf16 g_pvh[NUM_T * DD], g_pvl[NUM_T * DD];
__device__ bf16 g_hh [NUM_T * HH], g_hl [NUM_T * HH];
__device__ bf16 g_h2h[NUM_O * HH], g_h2l[NUM_O * HH];

__device__ bf16 g_w1h[LL * HH * K1], g_w1l[LL * HH * K1];
__device__ bf16 g_w2h[LL * N2 * HH], g_w2l[LL * N2 * HH];
__device__ bf16 g_w3h[LL * HH * HH], g_w3l[LL * HH * HH];
__device__ bf16 g_w4h[LL * DD * HH], g_w4l[LL * DD * HH];

__device__ __forceinline__ void f32split(float v, bf16& h, bf16& l) {
    h = __float2bfloat16(v);
    l = __float2bfloat16(v - __bfloat162float(h));
}
__device__ __forceinline__ uint32_t bfpack(bf16 a, bf16 b) {
    __nv_bfloat162 t; t.x = a; t.y = b;
    return *reinterpret_cast<uint32_t*>(&t);
}
__device__ __forceinline__ uint32_t smem_u32(const void* p) {
    uint32_t a;
    asm("{ .reg .u64 t; cvta.to.shared.u64 t, %1; cvt.u32.u64 %0, t; }" : "=r"(a) : "l"(p));
    return a;
}

// ================= glue =================
__global__ void zero_kernel(float* p, int n) {
    int i = blockIdx.x * blockDim.x + threadIdx.x;
    if (i < n) p[i] = 0.f;
}
// merged initial gathers: blockIdx.y==0 -> ov rows (first NUM_O blocks), ==1 -> pv rows
__global__ void gather_init(const float* __restrict__ obj_emb,
                            const float* __restrict__ pred_emb,
                            const int* __restrict__ objs,
                            const int* __restrict__ trip,
                            bf16* __restrict__ ovh, bf16* __restrict__ ovl,
                            bf16* __restrict__ pvh, bf16* __restrict__ pvl) {
    int i = blockIdx.x, d = threadIdx.x;
    if (blockIdx.y == 0) {
        if (i < NUM_O) {
            float v = obj_emb[objs[i] * DD + d];
            bf16 h, l; f32split(v, h, l);
            ovh[i * DD + d] = h; ovl[i * DD + d] = l;
        }
    } else {
        int p = trip[3 * i + 1];
        float v = pred_emb[p * DD + d];
        bf16 h, l; f32split(v, h, l);
        pvh[i * DD + d] = h; pvl[i * DD + d] = l;
    }
}
__global__ void count_kernel(const int* __restrict__ trip, float* __restrict__ counts) {
    int i = blockIdx.x * blockDim.x + threadIdx.x;
    if (i < NUM_T) {
        atomicAdd(&counts[trip[3 * i + 0]], 1.f);
        atomicAdd(&counts[trip[3 * i + 2]], 1.f);
    }
}
__global__ void inv_kernel(const float* __restrict__ counts, float* __restrict__ inv) {
    int i = blockIdx.x * blockDim.x + threadIdx.x;
    if (i < NUM_O) inv[i] = 1.f / fmaxf(counts[i], 1.f);
}
__global__ void wtrans_split(const float* __restrict__ w,
                             bf16* __restrict__ oh,
                             bf16* __restrict__ ol, int K, int N) {
    __shared__ float tile[32][33];
    int l = blockIdx.z;
    int k0 = blockIdx.y * 32, n0 = blockIdx.x * 32;
    const float* wl = w + (size_t)l * K * N;
    tile[threadIdx.y][threadIdx.x] = wl[(size_t)(k0 + threadIdx.y) * N + n0 + threadIdx.x];
    __syncthreads();
    int on = n0 + threadIdx.y, ok = k0 + threadIdx.x;
    float v = tile[threadIdx.x][threadIdx.y];
    bf16 h, lo; f32split(v, h, lo);
    size_t idx = ((size_t)l * N + on) * K + ok;
    oh[idx] = h; ol[idx] = lo;
}

// ================= HMMA GEMM =================
// C = A @ B^T (+bias, relu per OUT_MODE), 3-term bf16 split, fp32 accum.
// A_MODE 0: Ah/Al [M,K]. 2: fp32 Af * inv[row], split on the fly.
// OUT_MODE 0: raw fp32. 1: bias+relu bf16 pair. 2: bias+relu fp32 + bf16 pair.
//          3: smem-staged scatter (red.v4 + pv block). 5: relu(acc+bias+Us[s]+Uo[o]) bf16 pair.
// zBoff/zCoff: per-blockIdx.z element offsets applied to B and Cf (merged multi-GEMM launches).
#define BN   128
#define BK   32

#define CP_ASYNC16(dst, src, sz) \
    asm volatile("cp.async.cg.shared.global [%0], [%1], 16, %2;" :: "r"(dst), "l"(src), "r"(sz))
#define CP_COMMIT() asm volatile("cp.async.commit_group;")
#define LDSM_X4(R0,R1,R2,R3,ADDR) \
    asm volatile("ldmatrix.sync.aligned.m8n8.x4.shared.b16 {%0,%1,%2,%3}, [%4];" \
                 : "=r"(R0),"=r"(R1),"=r"(R2),"=r"(R3) : "r"(ADDR))
#define MMA16816(C,A0,A1,A2,A3,B0,B1) \
    asm volatile("mma.sync.aligned.m16n8k16.row.col.f32.bf16.bf16.f32 " \
                 "{%0,%1,%2,%3},{%4,%5,%6,%7},{%8,%9},{%0,%1,%2,%3};" \
                 : "+f"((C)[0]),"+f"((C)[1]),"+f"((C)[2]),"+f"((C)[3]) \
                 : "r"(A0),"r"(A1),"r"(A2),"r"(A3),"r"(B0),"r"(B1))
#define STS128(ADDR,A,B,C,D) \
    asm volatile("st.shared.v4.b32 [%0], {%1,%2,%3,%4};" :: "r"(ADDR),"r"(A),"r"(B),"r"(C),"r"(D))
#define REDV4(PTR,X,Y,Z,W) \
    asm volatile("red.global.add.v4.f32 [%0], {%1,%2,%3,%4};" :: "l"(PTR),"f"(X),"f"(Y),"f"(Z),"f"(W) : "memory")

__device__ __forceinline__ uint32_t sw_off(int row, int c) {
    return (uint32_t)(row * 64 + (((c ^ (row & 3))) << 4));
}

template <int A_MODE, int TBM>
__device__ __forceinline__ void ld_stage(
    uint32_t st,
    const bf16* __restrict__ Ah, const bf16* __restrict__ Al,
    const float* __restrict__ Af, const float* __restrict__ inv,
    const bf16* __restrict__ Bh, const bf16* __restrict__ Bl, int Bstride,
    int bm, int bn, int k0, int M, int K, int tid)
{
    constexpr uint32_t OFF_AL = TBM * 64;
    constexpr uint32_t OFF_BH = TBM * 128;
    constexpr uint32_t OFF_BL = TBM * 128 + 8192;
#pragma unroll
    for (int lin = tid; lin < TBM * 4; lin += 256) {
        int row = lin >> 2;
        int c   = lin & 3;
        uint32_t so = sw_off(row, c);
        int gr = bm + row;
        bool ok = gr < M;
        if (A_MODE == 2) {
            if (ok) {
                const float4* src = reinterpret_cast<const float4*>(Af + (size_t)gr * K + k0 + c * 8);
                float4 v0 = src[0], v1 = src[1];
                float s = __ldg(&inv[gr]);
                bf16 hb[8], lb[8];
                float vals[8] = {v0.x*s, v0.y*s, v0.z*s, v0.w*s, v1.x*s, v1.y*s, v1.z*s, v1.w*s};
#pragma unroll
                for (int j = 0; j < 8; j++) f32split(vals[j], hb[j], lb[j]);
                STS128(st + so, bfpack(hb[0],hb[1]), bfpack(hb[2],hb[3]), bfpack(hb[4],hb[5]), bfpack(hb[6],hb[7]));
                STS128(st + OFF_AL + so, bfpack(lb[0],lb[1]), bfpack(lb[2],lb[3]), bfpack(lb[4],lb[5]), bfpack(lb[6],lb[7]));
            } else {
                STS128(st + so, 0u, 0u, 0u, 0u);
                STS128(st + OFF_AL + so, 0u, 0u, 0u, 0u);
            }
        } else {
            uint32_t sz = ok ? 16u : 0u;
            size_t srow = ok ? (size_t)gr : 0;
            const char* sh = (const char*)(Ah + srow * K + k0 + c * 8);
            const char* sl = (const char*)(Al + srow * K + k0 + c * 8);
            CP_ASYNC16(st + so, sh, sz);
            CP_ASYNC16(st + OFF_AL + so, sl, sz);
        }
    }
#pragma unroll
    for (int lin = tid; lin < 512; lin += 256) {
        int row = lin >> 2;
        int c   = lin & 3;
        uint32_t so = sw_off(row, c);
        int gr = bn + row;
        const char* sh = (const char*)(Bh + (size_t)gr * Bstride + k0 + c * 8);
        const char* sl = (const char*)(Bl + (size_t)gr * Bstride + k0 + c * 8);
        CP_ASYNC16(st + OFF_BH + so, sh, 16u);
        CP_ASYNC16(st + OFF_BL + so, sl, 16u);
    }
}

template <int A_MODE, int OUT_MODE, int TBM>
__global__ void __launch_bounds__(256)
gemm_hmma(const bf16* __restrict__ Ah, const bf16* __restrict__ Al,
          const float* __restrict__ Af, const float* __restrict__ inv,
          const int* __restrict__ trip,
          const bf16* __restrict__ Bh, const bf16* __restrict__ Bl, int Bstride,
          const float* __restrict__ bias,
          const float* __restrict__ Us, const float* __restrict__ Uo,
          float* __restrict__ Cf,
          bf16* __restrict__ Ch, bf16* __restrict__ Cl,
          float* __restrict__ pooled,
          bf16* __restrict__ Pvh, bf16* __restrict__ Pvl,
          int zBoff, int zCoff,
          int M, int N, int K)
{
    constexpr uint32_t OFF_AL = TBM * 64;
    constexpr uint32_t OFF_BH = TBM * 128;
    constexpr uint32_t OFF_BL = TBM * 128 + 8192;
    constexpr uint32_t STAGE  = TBM * 128 + 16384;
    constexpr int NWM = (TBM == 128) ? 2 : 1;
    constexpr int NT  = (TBM == 128) ? 4 : 2;

    // merged multi-GEMM offsets (gridDim.z > 1)
    {
        size_t zb = (size_t)blockIdx.z * (size_t)zBoff;
        Bh += zb; Bl += zb;
        if (Cf) Cf += (size_t)blockIdx.z * (size_t)zCoff;
    }

    extern __shared__ char smem[];
    uint32_t sb = smem_u32(smem);

    int tid = threadIdx.x;
    int wid = tid >> 5, lane = tid & 31;
    int wm = (wid % NWM) * 64;
    int wn = (wid / NWM) * (NT * 8);
    int bm = blockIdx.y * TBM;
    int bn = blockIdx.x * BN;
    const int NC = K / BK;

    float acc[4][NT][4];
#pragma unroll
    for (int i = 0; i < 4; i++)
#pragma unroll
        for (int j = 0; j < NT; j++)
#pragma unroll
            for (int r = 0; r < 4; r++) acc[i][j][r] = 0.f;

    int lrow8 = (lane & 7) + ((lane >> 3) & 1) * 8;
    int lchunk = (lane >> 4);

    ld_stage<A_MODE, TBM>(sb, Ah, Al, Af, inv, Bh, Bl, Bstride, bm, bn, 0, M, K, tid);
    CP_COMMIT();

    for (int kc = 0; kc < NC; kc++) {
        if (kc + 1 < NC) {
            ld_stage<A_MODE, TBM>(sb + ((kc + 1) & 1) * STAGE, Ah, Al, Af, inv, Bh, Bl, Bstride,
                                  bm, bn, (kc + 1) * BK, M, K, tid);
            CP_COMMIT();
            asm volatile("cp.async.wait_group 1;");
        } else {
            asm volatile("cp.async.wait_group 0;");
        }
        __syncthreads();

        uint32_t sa = sb + (kc & 1) * STAGE;
#pragma unroll
        for (int ks = 0; ks < 2; ks++) {
            int c0 = ks * 2;
            uint32_t ah[4][4], al[4][4], bh[NT][2], bl[NT][2];
#pragma unroll
            for (int mt = 0; mt < 4; mt++) {
                int row = wm + mt * 16 + lrow8;
                LDSM_X4(ah[mt][0], ah[mt][1], ah[mt][2], ah[mt][3], sa + sw_off(row, c0 + lchunk));
            }
#pragma unroll
            for (int np = 0; np < NT / 2; np++) {
                int row = wn + np * 16 + lrow8;
                uint32_t r0, r1, r2, r3;
                LDSM_X4(r0, r1, r2, r3, sa + OFF_BH + sw_off(row, c0 + lchunk));
                bh[2*np][0] = r0; bh[2*np+1][0] = r1;
                bh[2*np][1] = r2; bh[2*np+1][1] = r3;
            }
#pragma unroll
            for (int mt = 0; mt < 4; mt++)
#pragma unroll
                for (int nt = 0; nt < NT; nt++)
                    MMA16816(acc[mt][nt], ah[mt][0], ah[mt][1], ah[mt][2], ah[mt][3],
                             bh[nt][0], bh[nt][1]);
#pragma unroll
            for (int np = 0; np < NT / 2; np++) {
                int row = wn + np * 16 + lrow8;
                uint32_t r0, r1, r2, r3;
                LDSM_X4(r0, r1, r2, r3, sa + OFF_BL + sw_off(row, c0 + lchunk));
                bl[2*np][0] = r0; bl[2*np+1][0] = r1;
                bl[2*np][1] = r2; bl[2*np+1][1] = r3;
            }
#pragma unroll
            for (int mt = 0; mt < 4; mt++)
#pragma unroll
                for (int nt = 0; nt < NT; nt++)
                    MMA16816(acc[mt][nt], ah[mt][0], ah[mt][1], ah[mt][2], ah[mt][3],
                             bl[nt][0], bl[nt][1]);
#pragma unroll
            for (int mt = 0; mt < 4; mt++) {
                int row = wm + mt * 16 + lrow8;
                LDSM_X4(al[mt][0], al[mt][1], al[mt][2], al[mt][3], sa + OFF_AL + sw_off(row, c0 + lchunk));
            }
#pragma unroll
            for (int mt = 0; mt < 4; mt++)
#pragma unroll
                for (int nt = 0; nt < NT; nt++)
                    MMA16816(acc[mt][nt], al[mt][0], al[mt][1], al[mt][2], al[mt][3],
                             bh[nt][0], bh[nt][1]);
        }
        __syncthreads();
    }

    int r = lane >> 2, q = lane & 3;

    if (OUT_MODE == 3) {
        // stage bias+relu'd tile to smem (128x128 fp32 = 64KB), then scatter
#pragma unroll
        for (int mt = 0; mt < 4; mt++) {
            int lr0 = wm + mt * 16 + r;
#pragma unroll
            for (int nt = 0; nt < NT; nt++) {
                int lc = wn + nt * 8 + q * 2;
                int col = bn + lc;
                float b0 = bias[col], b1 = bias[col + 1];
                float2 v0 = make_float2(fmaxf(acc[mt][nt][0] + b0, 0.f), fmaxf(acc[mt][nt][1] + b1, 0.f));
                float2 v1 = make_float2(fmaxf(acc[mt][nt][2] + b0, 0.f), fmaxf(acc[mt][nt][3] + b1, 0.f));
                *reinterpret_cast<float2*>(smem + ((size_t)lr0 * 128 + lc) * 4) = v0;
                *reinterpret_cast<float2*>(smem + ((size_t)(lr0 + 8) * 128 + lc) * 4) = v1;
            }
        }
        __syncthreads();
        int row = tid >> 1;
        int half = (tid & 1) * 64;
        int gr = bm + row;
        if (gr < M) {
            const float* srow = reinterpret_cast<const float*>(smem) + (size_t)row * 128 + half;
            if (bn == 512) {
#pragma unroll
                for (int i = 0; i < 16; i++) {
                    float4 v = *reinterpret_cast<const float4*>(srow + i * 4);
                    bf16 h0,l0,h1,l1,h2,l2,h3,l3;
                    f32split(v.x,h0,l0); f32split(v.y,h1,l1); f32split(v.z,h2,l2); f32split(v.w,h3,l3);
                    uint2 hp = make_uint2(bfpack(h0,h1), bfpack(h2,h3));
                    uint2 lp = make_uint2(bfpack(l0,l1), bfpack(l2,l3));
                    int pc = half + i * 4;
                    *reinterpret_cast<uint2*>(Pvh + (size_t)gr * DD + pc) = hp;
                    *reinterpret_cast<uint2*>(Pvl + (size_t)gr * DD + pc) = lp;
                }
            } else {
                int obj = __ldg(&trip[3 * gr + ((bn < 512) ? 0 : 2)]);
                float* dst = pooled + (size_t)obj * HH + ((bn < 512) ? bn : bn - 640) + half;
#pragma unroll
                for (int i = 0; i < 16; i++) {
                    float4 v = *reinterpret_cast<const float4*>(srow + i * 4);
                    REDV4(dst + i * 4, v.x, v.y, v.z, v.w);
                }
            }
        }
        return;
    }

#pragma unroll
    for (int mt = 0; mt < 4; mt++) {
        int row0 = bm + wm + mt * 16 + r;
        int row1 = row0 + 8;
        int s0 = 0, o0 = 0, s1 = 0, o1 = 0;
        if (OUT_MODE == 5) {
            if (row0 < M) { s0 = __ldg(&trip[3 * row0]); o0 = __ldg(&trip[3 * row0 + 2]); }
            if (row1 < M) { s1 = __ldg(&trip[3 * row1]); o1 = __ldg(&trip[3 * row1 + 2]); }
        }
#pragma unroll
        for (int nt = 0; nt < NT; nt++) {
            int col = bn + wn + nt * 8 + q * 2;
            if (OUT_MODE == 0) {
                if (row0 < M)
                    *reinterpret_cast<float2*>(Cf + (size_t)row0 * N + col) = make_float2(acc[mt][nt][0], acc[mt][nt][1]);
                if (row1 < M)
                    *reinterpret_cast<float2*>(Cf + (size_t)row1 * N + col) = make_float2(acc[mt][nt][2], acc[mt][nt][3]);
                continue;
            }
            float b0 = bias[col], b1 = bias[col + 1];
            float a00 = acc[mt][nt][0] + b0, a01 = acc[mt][nt][1] + b1;
            float a10 = acc[mt][nt][2] + b0, a11 = acc[mt][nt][3] + b1;
            if (OUT_MODE == 5) {
                if (row0 < M) {
                    float2 us = *reinterpret_cast<const float2*>(Us + (size_t)s0 * HH + col);
                    float2 uo = *reinterpret_cast<const float2*>(Uo + (size_t)o0 * HH + col);
                    a00 += us.x + uo.x; a01 += us.y + uo.y;
                }
                if (row1 < M) {
                    float2 us = *reinterpret_cast<const float2*>(Us + (size_t)s1 * HH + col);
                    float2 uo = *reinterpret_cast<const float2*>(Uo + (size_t)o1 * HH + col);
                    a10 += us.x + uo.x; a11 += us.y + uo.y;
                }
            }
            float v00 = fmaxf(a00, 0.f), v01 = fmaxf(a01, 0.f);
            float v10 = fmaxf(a10, 0.f), v11 = fmaxf(a11, 0.f);
            bf16 h0, l0, h1, l1;
            if (row0 < M) {
                if (OUT_MODE == 2)
                    *reinterpret_cast<float2*>(Cf + (size_t)row0 * N + col) = make_float2(v00, v01);
                f32split(v00, h0, l0); f32split(v01, h1, l1);
                *reinterpret_cast<uint32_t*>(Ch + (size_t)row0 * N + col) = bfpack(h0, h1);
                *reinterpret_cast<uint32_t*>(Cl + (size_t)row0 * N + col) = bfpack(l0, l1);
            }
            if (row1 < M) {
                if (OUT_MODE == 2)
                    *reinterpret_cast<float2*>(Cf + (size_t)row1 * N + col) = make_float2(v10, v11);
                f32split(v10, h0, l0); f32split(v11, h1, l1);
                *reinterpret_cast<uint32_t*>(Ch + (size_t)row1 * N + col) = bfpack(h0, h1);
                *reinterpret_cast<uint32_t*>(Cl + (size_t)row1 * N + col) = bfpack(l0, l1);
            }
        }
    }
}

// ================= attention epilogue =================
__global__ void scores_kernel(const float* __restrict__ ov,
                              const float* __restrict__ att_w,
                              const float* __restrict__ att_b,
                              float* __restrict__ scores) {
    int gid = blockIdx.x * blockDim.x + threadIdx.x;
    int w = gid >> 5, lane = gid & 31;
    if (w >= NUM_O) return;
    float sum = 0.f;
#pragma unroll
    for (int d = lane; d < DD; d += 32) sum += ov[(size_t)w * DD + d] * att_w[d];
#pragma unroll
    for (int off = 16; off; off >>= 1) sum += __shfl_down_sync(0xffffffff, sum, off);
    if (lane == 0) scores[w] = sum + att_b[0];
}

__global__ void segment_kernel(const float* __restrict__ scores,
                               const int* __restrict__ img,
                               const float* __restrict__ ov,
                               float* __restrict__ gvec) {
    int g = blockIdx.x, t = threadIdx.x;
    __shared__ float sred[128];
    __shared__ int ired[128];

    float m = -3.4e38f;
    int lo = NUM_O, hi = -1;
    for (int i = t; i < NUM_O; i += 128) {
        if (img[i] == g) {
            m = fmaxf(m, scores[i]);
            lo = min(lo, i);
            hi = max(hi, i);
        }
    }
    sred[t] = m; __syncthreads();
    for (int s = 64; s > 0; s >>= 1) { if (t < s) sred[t] = fmaxf(sred[t], sred[t + s]); __syncthreads(); }
    m = sred[0]; __syncthreads();
    ired[t] = lo; __syncthreads();
    for (int s = 64; s > 0; s >>= 1) { if (t < s) ired[t] = min(ired[t], ired[t + s]); __syncthreads(); }
    lo = ired[0]; __syncthreads();
    ired[t] = hi; __syncthreads();
    for (int s = 64; s > 0; s >>= 1) { if (t < s) ired[t] = max(ired[t], ired[t + s]); __syncthreads(); }
    hi = ired[0]; __syncthreads();

    float z = 0.f;
    for (int i = lo + t; i <= hi; i += 128)
        if (img[i] == g) z += expf(scores[i] - m);
    sred[t] = z; __syncthreads();
    for (int s = 64; s > 0; s >>= 1) { if (t < s) sred[t] += sred[t + s]; __syncthreads(); }
    z = sred[0];
    float invz = 1.f / z;

    float acc = 0.f;
    for (int i = lo; i <= hi; i++) {
        if (img[i] == g)
            acc += expf(scores[i] - m) * invz * ov[(size_t)i * DD + t];
    }
    gvec[g * DD + t] = acc;
}

__global__ void concat_kernel(const float* __restrict__ ov,
                              const float* __restrict__ gvec,
                              const int* __restrict__ img,
                              float* __restrict__ out) {
    int i = blockIdx.x, t = threadIdx.x;
    if (t < DD) out[(size_t)i * 256 + t] = ov[(size_t)i * DD + t];
    else        out[(size_t)i * 256 + t] = gvec[img[i] * DD + (t - DD)];
}

// ================= launch =================
extern "C" void kernel_launch(void* const* d_in, const int* in_sizes, int n_in,
                              void* d_out, int out_size) {
    const int*   objs     = (const int*)d_in[0];
    const int*   trip     = (const int*)d_in[1];
    const int*   img      = (const int*)d_in[2];
    const float* obj_emb  = (const float*)d_in[3];
    const float* pred_emb = (const float*)d_in[4];
    const float* n1w1     = (const float*)d_in[5];
    const float* n1b1     = (const float*)d_in[6];
    const float* n1w2     = (const float*)d_in[7];
    const float* n1b2     = (const float*)d_in[8];
    const float* n2w1     = (const float*)d_in[9];
    const float* n2b1     = (const float*)d_in[10];
    const float* n2w2     = (const float*)d_in[11];
    const float* n2b2     = (const float*)d_in[12];
    const float* att_w    = (const float*)d_in[13];
    const float* att_b    = (const float*)d_in[14];
    float* out = (float*)d_out;

    float *ov, *pooled, *counts, *inv, *scores, *gvec, *U;
    bf16 *ovh, *ovl, *pvh, *pvl, *hh, *hl, *h2h, *h2l;
    bf16 *w1h, *w1l, *w2h, *w2l, *w3h, *w3l, *w4h, *w4l;
    cudaGetSymbolAddress((void**)&ov,     g_ov);
    cudaGetSymbolAddress((void**)&pooled, g_pooled);
    cudaGetSymbolAddress((void**)&counts, g_counts);
    cudaGetSymbolAddress((void**)&inv,    g_invcnt);
    cudaGetSymbolAddress((void**)&scores, g_scores);
    cudaGetSymbolAddress((void**)&gvec,   g_gvec);
    cudaGetSymbolAddress((void**)&U,      g_U);
    cudaGetSymbolAddress((void**)&ovh, g_ovh); cudaGetSymbolAddress((void**)&ovl, g_ovl);
    cudaGetSymbolAddress((void**)&pvh, g_pvh); cudaGetSymbolAddress((void**)&pvl, g_pvl);
    cudaGetSymbolAddress((void**)&hh,  g_hh);  cudaGetSymbolAddress((void**)&hl,  g_hl);
    cudaGetSymbolAddress((void**)&h2h, g_h2h); cudaGetSymbolAddress((void**)&h2l, g_h2l);
    cudaGetSymbolAddress((void**)&w1h, g_w1h); cudaGetSymbolAddress((void**)&w1l, g_w1l);
    cudaGetSymbolAddress((void**)&w2h, g_w2h); cudaGetSymbolAddress((void**)&w2l, g_w2l);
    cudaGetSymbolAddress((void**)&w3h, g_w3h); cudaGetSymbolAddress((void**)&w3l, g_w3l);
    cudaGetSymbolAddress((void**)&w4h, g_w4h); cudaGetSymbolAddress((void**)&w4l, g_w4l);

    float* Us = U;
    float* Uo = U + (size_t)NUM_O * HH;

    const int SMEM128 = 65536;   // 2 stages x 32KB (== 64KB epi staging for OUT3)
    const int SMEM64  = 49152;   // 2 stages x 24KB
    cudaFuncSetAttribute(gemm_hmma<0,0,64>,  cudaFuncAttributeMaxDynamicSharedMemorySize, SMEM64);
    cudaFuncSetAttribute(gemm_hmma<0,5,128>, cudaFuncAttributeMaxDynamicSharedMemorySize, SMEM128);
    cudaFuncSetAttribute(gemm_hmma<0,3,128>, cudaFuncAttributeMaxDynamicSharedMemorySize, SMEM128);
    cudaFuncSetAttribute(gemm_hmma<2,1,64>,  cudaFuncAttributeMaxDynamicSharedMemorySize, SMEM64);
    cudaFuncSetAttribute(gemm_hmma<0,2,64>,  cudaFuncAttributeMaxDynamicSharedMemorySize, SMEM64);

    const int mT   = (NUM_T + 127) / 128;   // 157
    const int mO64 = (NUM_O + 63) / 64;     // 79

    // ---- prologue (index 3 = merged U GEMM, profiled by ncu) ----
    wtrans_split<<<dim3(HH/32, K1/32, LL), dim3(32,32)>>>(n1w1, w1h, w1l, K1, HH);   // 0
    gather_init<<<dim3(NUM_T, 2), DD>>>(obj_emb, pred_emb, objs, trip,
                                        ovh, ovl, pvh, pvl);                        // 1
    wtrans_split<<<dim3(N2/32, HH/32, LL), dim3(32,32)>>>(n1w2, w2h, w2l, HH, N2);   // 2

    // 3 (profiled): merged Us/Uo GEMM, z=0 -> Us (Ws = w1t[:,0:128]), z=1 -> Uo (Wo = w1t[:,256:384])
    gemm_hmma<0,0,64><<<dim3(HH/BN, mO64, 2), 256, SMEM64>>>(
        ovh, ovl, nullptr, nullptr, nullptr,
        w1h, w1l, K1, nullptr, nullptr, nullptr,
        U, nullptr, nullptr, nullptr, nullptr, nullptr,
        2*DD, NUM_O*HH, NUM_O, HH, DD);

    zero_kernel<<<(NUM_O + 255) / 256, 256>>>(counts, NUM_O);                        // 4
    count_kernel<<<(NUM_T + 255) / 256, 256>>>(trip, counts);                        // 5
    inv_kernel<<<(NUM_O + 255) / 256, 256>>>(counts, inv);                           // 6
    wtrans_split<<<dim3(HH/32, HH/32, LL), dim3(32,32)>>>(n2w1, w3h, w3l, HH, HH);   // 7
    wtrans_split<<<dim3(DD/32, HH/32, LL), dim3(32,32)>>>(n2w2, w4h, w4l, HH, DD);   // 8

    for (int l = 0; l < LL; l++) {
        const bf16* w1hl = w1h + (size_t)l * HH * K1;
        const bf16* w1ll = w1l + (size_t)l * HH * K1;
        if (l > 0) {
            gemm_hmma<0,0,64><<<dim3(HH/BN, mO64, 2), 256, SMEM64>>>(
                ovh, ovl, nullptr, nullptr, nullptr,
                w1hl, w1ll, K1, nullptr, nullptr, nullptr,
                U, nullptr, nullptr, nullptr, nullptr, nullptr,
                2*DD, NUM_O*HH, NUM_O, HH, DD);
        }

        // pv GEMM + fused gather-add epilogue: h = relu(pv@Wp + Us[s] + Uo[o] + b1)
        gemm_hmma<0,5,128><<<dim3(HH/BN, mT), 256, SMEM128>>>(
            pvh, pvl, nullptr, nullptr, trip,
            w1hl + DD, w1ll + DD, K1, n1b1 + (size_t)l*HH, Us, Uo,
            nullptr, hh, hl, nullptr, nullptr, nullptr,
            0, 0, NUM_T, HH, DD);

        zero_kernel<<<(NUM_O * HH + 255) / 256, 256>>>(pooled, NUM_O * HH);

        // GEMM2: fused smem-staged scatter
        gemm_hmma<0,3,128><<<dim3(N2/BN, mT), 256, SMEM128>>>(
            hh, hl, nullptr, nullptr, trip,
            w2h + (size_t)l*N2*HH, w2l + (size_t)l*N2*HH, HH, n1b2 + (size_t)l*N2,
            nullptr, nullptr,
            nullptr, nullptr, nullptr, pooled, pvh, pvl,
            0, 0, NUM_T, N2, HH);

        // GEMM3: fused scale+split loader
        gemm_hmma<2,1,64><<<dim3(HH/BN, mO64), 256, SMEM64>>>(
            nullptr, nullptr, pooled, inv, nullptr,
            w3h + (size_t)l*HH*HH, w3l + (size_t)l*HH*HH, HH, n2b1 + (size_t)l*HH,
            nullptr, nullptr,
            nullptr, h2h, h2l, nullptr, nullptr, nullptr,
            0, 0, NUM_O, HH, HH);

        // GEMM4: ov fp32 + bf16 pair
        gemm_hmma<0,2,64><<<dim3(DD/BN, mO64), 256, SMEM64>>>(
            h2h, h2l, nullptr, nullptr, nullptr,
            w4h + (size_t)l*DD*HH, w4l + (size_t)l*DD*HH, HH, n2b2 + (size_t)l*DD,
            nullptr, nullptr,
            ov, ovh, ovl, nullptr, nullptr, nullptr,
            0, 0, NUM_O, DD, HH);
    }

    scores_kernel<<<(NUM_O * 32 + 255) / 256, 256>>>(ov, att_w, att_b, scores);
    segment_kernel<<<GG, 128>>>(scores, img, ov, gvec);
    concat_kernel<<<NUM_O, 256>>>(ov, gvec, img, out);
}

// round 12
// speedup vs baseline: 3.9183x; 1.1060x over previous
#include <cuda_runtime.h>
#include <cuda_bf16.h>
#include <cuda_fp16.h>
#include <math.h>
#include <stdint.h>

#define NUM_O   5000
#define NUM_T   20000
#define DD      128
#define HH      512
#define GG      64
#define LL      5
#define K1      (3*DD)        // 384
#define N2      (2*HH+DD)     // 1152

typedef __nv_bfloat16 bf16;

// ================= scratch =================
__device__ float g_ov    [NUM_O * DD];
__device__ float g_pooled[NUM_O * HH];
__device__ float g_counts[NUM_O];
__device__ float g_invcnt[NUM_O];
__device__ float g_scores[NUM_O];
__device__ float g_gvec  [GG * DD];
__device__ float g_U     [2 * NUM_O * HH];   // [Us | Uo]

__device__ bf16   g_ovh[NUM_O * DD], g_ovl[NUM_O * DD];
__device__ bf16   g_pvh[NUM_T * DD], g_pvl[NUM_T * DD];
__device__ bf16   g_hh [NUM_T * HH], g_hl [NUM_T * HH];
__device__ bf16   g_h2h[NUM_O * HH], g_h2l[NUM_O * HH];

// row-scaled fp16 GEMM2 operands
__device__ __half g_h16[NUM_T * HH];
__device__ float  g_saq[20096];              // row scales (padded to 157*128, zero tail)
__device__ __half g_w2h16[LL * N2 * HH], g_w2l16[LL * N2 * HH];
__device__ float  g_sbq[LL * N2];

__device__ bf16   g_w1h[LL * HH * K1], g_w1l[LL * HH * K1];
__device__ bf16   g_w3h[LL * HH * HH], g_w3l[LL * HH * HH];
__device__ bf16   g_w4h[LL * DD * HH], g_w4l[LL * DD * HH];

__device__ __forceinline__ void f32split(float v, bf16& h, bf16& l) {
    h = __float2bfloat16(v);
    l = __float2bfloat16(v - __bfloat162float(h));
}
__device__ __forceinline__ uint32_t bfpack(bf16 a, bf16 b) {
    __nv_bfloat162 t; t.x = a; t.y = b;
    return *reinterpret_cast<uint32_t*>(&t);
}
__device__ __forceinline__ uint32_t smem_u32(const void* p) {
    uint32_t a;
    asm("{ .reg .u64 t; cvta.to.shared.u64 t, %1; cvt.u32.u64 %0, t; }" : "=r"(a) : "l"(p));
    return a;
}

// ================= glue =================
__global__ void zero_kernel(float* p, int n) {
    int i = blockIdx.x * blockDim.x + threadIdx.x;
    if (i < n) p[i] = 0.f;
}
__global__ void gather_init(const float* __restrict__ obj_emb,
                            const float* __restrict__ pred_emb,
                            const int* __restrict__ objs,
                            const int* __restrict__ trip,
                            bf16* __restrict__ ovh, bf16* __restrict__ ovl,
                            bf16* __restrict__ pvh, bf16* __restrict__ pvl) {
    int i = blockIdx.x, d = threadIdx.x;
    if (blockIdx.y == 0) {
        if (i < NUM_O) {
            float v = obj_emb[objs[i] * DD + d];
            bf16 h, l; f32split(v, h, l);
            ovh[i * DD + d] = h; ovl[i * DD + d] = l;
        }
    } else {
        int p = trip[3 * i + 1];
        float v = pred_emb[p * DD + d];
        bf16 h, l; f32split(v, h, l);
        pvh[i * DD + d] = h; pvl[i * DD + d] = l;
    }
}
__global__ void count_kernel(const int* __restrict__ trip, float* __restrict__ counts) {
    int i = blockIdx.x * blockDim.x + threadIdx.x;
    if (i < NUM_T) {
        atomicAdd(&counts[trip[3 * i + 0]], 1.f);
        atomicAdd(&counts[trip[3 * i + 2]], 1.f);
    }
}
__global__ void inv_kernel(const float* __restrict__ counts, float* __restrict__ inv) {
    int i = blockIdx.x * blockDim.x + threadIdx.x;
    if (i < NUM_O) inv[i] = 1.f / fmaxf(counts[i], 1.f);
}
__global__ void wtrans_split(const float* __restrict__ w,
                             bf16* __restrict__ oh,
                             bf16* __restrict__ ol, int K, int N) {
    __shared__ float tile[32][33];
    int l = blockIdx.z;
    int k0 = blockIdx.y * 32, n0 = blockIdx.x * 32;
    const float* wl = w + (size_t)l * K * N;
    tile[threadIdx.y][threadIdx.x] = wl[(size_t)(k0 + threadIdx.y) * N + n0 + threadIdx.x];
    __syncthreads();
    int on = n0 + threadIdx.y, ok = k0 + threadIdx.x;
    float v = tile[threadIdx.x][threadIdx.y];
    bf16 h, lo; f32split(v, h, lo);
    size_t idx = ((size_t)l * N + on) * K + ok;
    oh[idx] = h; ol[idx] = lo;
}

// w2 [L,K,N] fp32 -> row(n)-scaled fp16 hi/lo [L,N,K] + sbq[L,N]
__global__ void wquant_f16(const float* __restrict__ w,
                           __half* __restrict__ qbh, __half* __restrict__ qbl,
                           float* __restrict__ sbq, int K, int N) {
    extern __shared__ float ws[];   // 32 x (K+2)
    int l = blockIdx.y;
    int n0 = blockIdx.x * 32;
    int tx = threadIdx.x & 31, ty = threadIdx.x >> 5;   // 32 x 8
    const float* wl = w + (size_t)l * K * N;
    for (int k = ty; k < K; k += 8)
        ws[tx * (K + 2) + k] = wl[(size_t)k * N + n0 + tx];
    __syncthreads();
    int lane = threadIdx.x & 31, w8 = threadIdx.x >> 5;
    for (int p = 0; p < 4; p++) {
        int nl = p * 8 + w8;
        float mx = 0.f;
        for (int k = lane; k < K; k += 32) mx = fmaxf(mx, fabsf(ws[nl * (K + 2) + k]));
#pragma unroll
        for (int off = 16; off; off >>= 1) mx = fmaxf(mx, __shfl_xor_sync(0xffffffff, mx, off));
        float inv = mx > 1e-30f ? 2047.f / mx : 0.f;
        for (int k = lane; k < K; k += 32) {
            float vs = ws[nl * (K + 2) + k] * inv;
            __half h = __float2half(vs);
            __half lo = __float2half(vs - __half2float(h));
            size_t idx = ((size_t)l * N + n0 + nl) * K + k;
            qbh[idx] = h; qbl[idx] = lo;
        }
        if (lane == 0) sbq[(size_t)l * N + n0 + nl] = mx > 1e-30f ? mx / 2047.f : 0.f;
    }
}

// h (bf16 pair) -> row-scaled fp16 plane + saq. h >= 0 (relu).
__global__ void quant_rows_f16(const bf16* __restrict__ xh, const bf16* __restrict__ xl,
                               __half* __restrict__ q, float* __restrict__ saq) {
    int row = blockIdx.x, t = threadIdx.x;   // 128 threads, 512 cols
    __shared__ float red[128];
    const size_t base = (size_t)row * HH;
    float v[4]; float mx = 0.f;
#pragma unroll
    for (int j = 0; j < 4; j++) {
        int c = t + j * 128;
        v[j] = __bfloat162float(xh[base + c]) + __bfloat162float(xl[base + c]);
        mx = fmaxf(mx, v[j]);
    }
    red[t] = mx; __syncthreads();
    for (int s = 64; s > 0; s >>= 1) { if (t < s) red[t] = fmaxf(red[t], red[t + s]); __syncthreads(); }
    float s = red[0];
    float inv = s > 1e-30f ? 2047.f / s : 0.f;
#pragma unroll
    for (int j = 0; j < 4; j++) {
        int c = t + j * 128;
        q[base + c] = __float2half(v[j] * inv);
    }
    if (t == 0) saq[row] = s > 1e-30f ? s / 2047.f : 0.f;
}

// ================= HMMA GEMM =================
// C = A @ B^T (+bias, relu per OUT_MODE), split-precision, fp32 accum.
// A_MODE 0: Ah/Al [M,K] (Al unused when TERMS==2). 2: fp32 Af * inv[row], split on the fly.
// OUT_MODE 0: raw fp32. 1: bias+relu bf16 pair. 2: bias+relu fp32 + bf16 pair.
//          3: smem-staged scatter (red.v4 + pv block); when USEF16, dequant acc*Us[row]*Uo[col].
//          5: relu(acc+bias+Us[s]+Uo[o]) bf16 pair.
// TERMS: 3 = Ah*Bh + Ah*Bl + Al*Bh.  2 = Ah*Bh + Ah*Bl (A single plane).
// USEF16: 0 = bf16 mma, 1 = fp16 mma (pointers carry fp16 data, byte-layout identical).
#define BN   128
#define BK   32

#define CP_ASYNC16(dst, src, sz) \
    asm volatile("cp.async.cg.shared.global [%0], [%1], 16, %2;" :: "r"(dst), "l"(src), "r"(sz))
#define CP_COMMIT() asm volatile("cp.async.commit_group;")
#define LDSM_X4(R0,R1,R2,R3,ADDR) \
    asm volatile("ldmatrix.sync.aligned.m8n8.x4.shared.b16 {%0,%1,%2,%3}, [%4];" \
                 : "=r"(R0),"=r"(R1),"=r"(R2),"=r"(R3) : "r"(ADDR))
#define MMA16816(C,A0,A1,A2,A3,B0,B1) \
    asm volatile("mma.sync.aligned.m16n8k16.row.col.f32.bf16.bf16.f32 " \
                 "{%0,%1,%2,%3},{%4,%5,%6,%7},{%8,%9},{%0,%1,%2,%3};" \
                 : "+f"((C)[0]),"+f"((C)[1]),"+f"((C)[2]),"+f"((C)[3]) \
                 : "r"(A0),"r"(A1),"r"(A2),"r"(A3),"r"(B0),"r"(B1))
#define MMA16816F(C,A0,A1,A2,A3,B0,B1) \
    asm volatile("mma.sync.aligned.m16n8k16.row.col.f32.f16.f16.f32 " \
                 "{%0,%1,%2,%3},{%4,%5,%6,%7},{%8,%9},{%0,%1,%2,%3};" \
                 : "+f"((C)[0]),"+f"((C)[1]),"+f"((C)[2]),"+f"((C)[3]) \
                 : "r"(A0),"r"(A1),"r"(A2),"r"(A3),"r"(B0),"r"(B1))
#define STS128(ADDR,A,B,C,D) \
    asm volatile("st.shared.v4.b32 [%0], {%1,%2,%3,%4};" :: "r"(ADDR),"r"(A),"r"(B),"r"(C),"r"(D))
#define REDV4(PTR,X,Y,Z,W) \
    asm volatile("red.global.add.v4.f32 [%0], {%1,%2,%3,%4};" :: "l"(PTR),"f"(X),"f"(Y),"f"(Z),"f"(W) : "memory")

__device__ __forceinline__ uint32_t sw_off(int row, int c) {
    return (uint32_t)(row * 64 + (((c ^ (row & 3))) << 4));
}

template <int A_MODE, int TBM, int TERMS>
__device__ __forceinline__ void ld_stage(
    uint32_t st,
    const bf16* __restrict__ Ah, const bf16* __restrict__ Al,
    const float* __restrict__ Af, const float* __restrict__ inv,
    const bf16* __restrict__ Bh, const bf16* __restrict__ Bl, int Bstride,
    int bm, int bn, int k0, int M, int K, int tid)
{
    constexpr uint32_t OFF_AL = TBM * 64;
    constexpr uint32_t OFF_BH = TBM * 128;
    constexpr uint32_t OFF_BL = TBM * 128 + 8192;
#pragma unroll
    for (int lin = tid; lin < TBM * 4; lin += 256) {
        int row = lin >> 2;
        int c   = lin & 3;
        uint32_t so = sw_off(row, c);
        int gr = bm + row;
        bool ok = gr < M;
        if (A_MODE == 2) {
            if (ok) {
                const float4* src = reinterpret_cast<const float4*>(Af + (size_t)gr * K + k0 + c * 8);
                float4 v0 = src[0], v1 = src[1];
                float s = __ldg(&inv[gr]);
                bf16 hb[8], lb[8];
                float vals[8] = {v0.x*s, v0.y*s, v0.z*s, v0.w*s, v1.x*s, v1.y*s, v1.z*s, v1.w*s};
#pragma unroll
                for (int j = 0; j < 8; j++) f32split(vals[j], hb[j], lb[j]);
                STS128(st + so, bfpack(hb[0],hb[1]), bfpack(hb[2],hb[3]), bfpack(hb[4],hb[5]), bfpack(hb[6],hb[7]));
                STS128(st + OFF_AL + so, bfpack(lb[0],lb[1]), bfpack(lb[2],lb[3]), bfpack(lb[4],lb[5]), bfpack(lb[6],lb[7]));
            } else {
                STS128(st + so, 0u, 0u, 0u, 0u);
                STS128(st + OFF_AL + so, 0u, 0u, 0u, 0u);
            }
        } else {
            uint32_t sz = ok ? 16u : 0u;
            size_t srow = ok ? (size_t)gr : 0;
            const char* sh = (const char*)(Ah + srow * K + k0 + c * 8);
            CP_ASYNC16(st + so, sh, sz);
            if (TERMS == 3) {
                const char* sl = (const char*)(Al + srow * K + k0 + c * 8);
                CP_ASYNC16(st + OFF_AL + so, sl, sz);
            }
        }
    }
#pragma unroll
    for (int lin = tid; lin < 512; lin += 256) {
        int row = lin >> 2;
        int c   = lin & 3;
        uint32_t so = sw_off(row, c);
        int gr = bn + row;
        const char* sh = (const char*)(Bh + (size_t)gr * Bstride + k0 + c * 8);
        const char* sl = (const char*)(Bl + (size_t)gr * Bstride + k0 + c * 8);
        CP_ASYNC16(st + OFF_BH + so, sh, 16u);
        CP_ASYNC16(st + OFF_BL + so, sl, 16u);
    }
}

template <int A_MODE, int OUT_MODE, int TBM, int TERMS, int USEF16>
__global__ void __launch_bounds__(256)
gemm_hmma(const bf16* __restrict__ Ah, const bf16* __restrict__ Al,
          const float* __restrict__ Af, const float* __restrict__ inv,
          const int* __restrict__ trip,
          const bf16* __restrict__ Bh, const bf16* __restrict__ Bl, int Bstride,
          const float* __restrict__ bias,
          const float* __restrict__ Us, const float* __restrict__ Uo,
          float* __restrict__ Cf,
          bf16* __restrict__ Ch, bf16* __restrict__ Cl,
          float* __restrict__ pooled,
          bf16* __restrict__ Pvh, bf16* __restrict__ Pvl,
          int zBoff, int zCoff,
          int M, int N, int K)
{
    constexpr uint32_t OFF_AL = TBM * 64;
    constexpr uint32_t OFF_BH = TBM * 128;
    constexpr uint32_t OFF_BL = TBM * 128 + 8192;
    constexpr uint32_t STAGE  = TBM * 128 + 16384;
    constexpr int NWM = (TBM == 128) ? 2 : 1;
    constexpr int NT  = (TBM == 128) ? 4 : 2;

    {
        size_t zb = (size_t)blockIdx.z * (size_t)zBoff;
        Bh += zb; Bl += zb;
        if (Cf) Cf += (size_t)blockIdx.z * (size_t)zCoff;
    }

    extern __shared__ char smem[];
    uint32_t sb = smem_u32(smem);

    int tid = threadIdx.x;
    int wid = tid >> 5, lane = tid & 31;
    int wm = (wid % NWM) * 64;
    int wn = (wid / NWM) * (NT * 8);
    int bm = blockIdx.y * TBM;
    int bn = blockIdx.x * BN;
    const int NC = K / BK;

    float acc[4][NT][4];
#pragma unroll
    for (int i = 0; i < 4; i++)
#pragma unroll
        for (int j = 0; j < NT; j++)
#pragma unroll
            for (int r = 0; r < 4; r++) acc[i][j][r] = 0.f;

    int lrow8 = (lane & 7) + ((lane >> 3) & 1) * 8;
    int lchunk = (lane >> 4);

    ld_stage<A_MODE, TBM, TERMS>(sb, Ah, Al, Af, inv, Bh, Bl, Bstride, bm, bn, 0, M, K, tid);
    CP_COMMIT();

    for (int kc = 0; kc < NC; kc++) {
        if (kc + 1 < NC) {
            ld_stage<A_MODE, TBM, TERMS>(sb + ((kc + 1) & 1) * STAGE, Ah, Al, Af, inv, Bh, Bl, Bstride,
                                         bm, bn, (kc + 1) * BK, M, K, tid);
            CP_COMMIT();
            asm volatile("cp.async.wait_group 1;");
        } else {
            asm volatile("cp.async.wait_group 0;");
        }
        __syncthreads();

        uint32_t sa = sb + (kc & 1) * STAGE;
#pragma unroll
        for (int ks = 0; ks < 2; ks++) {
            int c0 = ks * 2;
            uint32_t ah[4][4], al[4][4], bh[NT][2], bl[NT][2];
#pragma unroll
            for (int mt = 0; mt < 4; mt++) {
                int row = wm + mt * 16 + lrow8;
                LDSM_X4(ah[mt][0], ah[mt][1], ah[mt][2], ah[mt][3], sa + sw_off(row, c0 + lchunk));
            }
#pragma unroll
            for (int np = 0; np < NT / 2; np++) {
                int row = wn + np * 16 + lrow8;
                uint32_t r0, r1, r2, r3;
                LDSM_X4(r0, r1, r2, r3, sa + OFF_BH + sw_off(row, c0 + lchunk));
                bh[2*np][0] = r0; bh[2*np+1][0] = r1;
                bh[2*np][1] = r2; bh[2*np+1][1] = r3;
            }
#pragma unroll
            for (int mt = 0; mt < 4; mt++)
#pragma unroll
                for (int nt = 0; nt < NT; nt++) {
                    if (USEF16) MMA16816F(acc[mt][nt], ah[mt][0], ah[mt][1], ah[mt][2], ah[mt][3],
                                          bh[nt][0], bh[nt][1]);
                    else        MMA16816(acc[mt][nt], ah[mt][0], ah[mt][1], ah[mt][2], ah[mt][3],
                                         bh[nt][0], bh[nt][1]);
                }
#pragma unroll
            for (int np = 0; np < NT / 2; np++) {
                int row = wn + np * 16 + lrow8;
                uint32_t r0, r1, r2, r3;
                LDSM_X4(r0, r1, r2, r3, sa + OFF_BL + sw_off(row, c0 + lchunk));
                bl[2*np][0] = r0; bl[2*np+1][0] = r1;
                bl[2*np][1] = r2; bl[2*np+1][1] = r3;
            }
#pragma unroll
            for (int mt = 0; mt < 4; mt++)
#pragma unroll
                for (int nt = 0; nt < NT; nt++) {
                    if (USEF16) MMA16816F(acc[mt][nt], ah[mt][0], ah[mt][1], ah[mt][2], ah[mt][3],
                                          bl[nt][0], bl[nt][1]);
                    else        MMA16816(acc[mt][nt], ah[mt][0], ah[mt][1], ah[mt][2], ah[mt][3],
                                         bl[nt][0], bl[nt][1]);
                }
            if (TERMS == 3) {
#pragma unroll
                for (int mt = 0; mt < 4; mt++) {
                    int row = wm + mt * 16 + lrow8;
                    LDSM_X4(al[mt][0], al[mt][1], al[mt][2], al[mt][3], sa + OFF_AL + sw_off(row, c0 + lchunk));
                }
#pragma unroll
                for (int mt = 0; mt < 4; mt++)
#pragma unroll
                    for (int nt = 0; nt < NT; nt++) {
                        if (USEF16) MMA16816F(acc[mt][nt], al[mt][0], al[mt][1], al[mt][2], al[mt][3],
                                              bh[nt][0], bh[nt][1]);
                        else        MMA16816(acc[mt][nt], al[mt][0], al[mt][1], al[mt][2], al[mt][3],
                                             bh[nt][0], bh[nt][1]);
                    }
            }
        }
        __syncthreads();
    }

    int r = lane >> 2, q = lane & 3;

    if (OUT_MODE == 3) {
        // dequant (if USEF16) + bias + relu -> smem staging [128][128] fp32, then scatter
#pragma unroll
        for (int mt = 0; mt < 4; mt++) {
            int lr0 = wm + mt * 16 + r;
            float sa0 = 1.f, sa1 = 1.f;
            if (USEF16) {
                sa0 = __ldg(&Us[bm + lr0]);
                sa1 = __ldg(&Us[bm + lr0 + 8]);
            }
#pragma unroll
            for (int nt = 0; nt < NT; nt++) {
                int lc = wn + nt * 8 + q * 2;
                int col = bn + lc;
                float b0 = bias[col], b1 = bias[col + 1];
                float sb0 = 1.f, sb1 = 1.f;
                if (USEF16) { sb0 = __ldg(&Uo[col]); sb1 = __ldg(&Uo[col + 1]); }
                float2 v0 = make_float2(fmaxf(acc[mt][nt][0] * sa0 * sb0 + b0, 0.f),
                                        fmaxf(acc[mt][nt][1] * sa0 * sb1 + b1, 0.f));
                float2 v1 = make_float2(fmaxf(acc[mt][nt][2] * sa1 * sb0 + b0, 0.f),
                                        fmaxf(acc[mt][nt][3] * sa1 * sb1 + b1, 0.f));
                *reinterpret_cast<float2*>(smem + ((size_t)lr0 * 128 + lc) * 4) = v0;
                *reinterpret_cast<float2*>(smem + ((size_t)(lr0 + 8) * 128 + lc) * 4) = v1;
            }
        }
        __syncthreads();
        int row = tid >> 1;
        int half = (tid & 1) * 64;
        int gr = bm + row;
        if (gr < M) {
            const float* srow = reinterpret_cast<const float*>(smem) + (size_t)row * 128 + half;
            if (bn == 512) {
#pragma unroll
                for (int i = 0; i < 16; i++) {
                    float4 v = *reinterpret_cast<const float4*>(srow + i * 4);
                    bf16 h0,l0,h1,l1,h2,l2,h3,l3;
                    f32split(v.x,h0,l0); f32split(v.y,h1,l1); f32split(v.z,h2,l2); f32split(v.w,h3,l3);
                    uint2 hp = make_uint2(bfpack(h0,h1), bfpack(h2,h3));
                    uint2 lp = make_uint2(bfpack(l0,l1), bfpack(l2,l3));
                    int pc = half + i * 4;
                    *reinterpret_cast<uint2*>(Pvh + (size_t)gr * DD + pc) = hp;
                    *reinterpret_cast<uint2*>(Pvl + (size_t)gr * DD + pc) = lp;
                }
            } else {
                int obj = __ldg(&trip[3 * gr + ((bn < 512) ? 0 : 2)]);
                float* dst = pooled + (size_t)obj * HH + ((bn < 512) ? bn : bn - 640) + half;
#pragma unroll
                for (int i = 0; i < 16; i++) {
                    float4 v = *reinterpret_cast<const float4*>(srow + i * 4);
                    REDV4(dst + i * 4, v.x, v.y, v.z, v.w);
                }
            }
        }
        return;
    }

#pragma unroll
    for (int mt = 0; mt < 4; mt++) {
        int row0 = bm + wm + mt * 16 + r;
        int row1 = row0 + 8;
        int s0 = 0, o0 = 0, s1 = 0, o1 = 0;
        if (OUT_MODE == 5) {
            if (row0 < M) { s0 = __ldg(&trip[3 * row0]); o0 = __ldg(&trip[3 * row0 + 2]); }
            if (row1 < M) { s1 = __ldg(&trip[3 * row1]); o1 = __ldg(&trip[3 * row1 + 2]); }
        }
#pragma unroll
        for (int nt = 0; nt < NT; nt++) {
            int col = bn + wn + nt * 8 + q * 2;
            if (OUT_MODE == 0) {
                if (row0 < M)
                    *reinterpret_cast<float2*>(Cf + (size_t)row0 * N + col) = make_float2(acc[mt][nt][0], acc[mt][nt][1]);
                if (row1 < M)
                    *reinterpret_cast<float2*>(Cf + (size_t)row1 * N + col) = make_float2(acc[mt][nt][2], acc[mt][nt][3]);
                continue;
            }
            float b0 = bias[col], b1 = bias[col + 1];
            float a00 = acc[mt][nt][0] + b0, a01 = acc[mt][nt][1] + b1;
            float a10 = acc[mt][nt][2] + b0, a11 = acc[mt][nt][3] + b1;
            if (OUT_MODE == 5) {
                if (row0 < M) {
                    float2 us = *reinterpret_cast<const float2*>(Us + (size_t)s0 * HH + col);
                    float2 uo = *reinterpret_cast<const float2*>(Uo + (size_t)o0 * HH + col);
                    a00 += us.x + uo.x; a01 += us.y + uo.y;
                }
                if (row1 < M) {
                    float2 us = *reinterpret_cast<const float2*>(Us + (size_t)s1 * HH + col);
                    float2 uo = *reinterpret_cast<const float2*>(Uo + (size_t)o1 * HH + col);
                    a10 += us.x + uo.x; a11 += us.y + uo.y;
                }
            }
            float v00 = fmaxf(a00, 0.f), v01 = fmaxf(a01, 0.f);
            float v10 = fmaxf(a10, 0.f), v11 = fmaxf(a11, 0.f);
            bf16 h0, l0, h1, l1;
            if (row0 < M) {
                if (OUT_MODE == 2)
                    *reinterpret_cast<float2*>(Cf + (size_t)row0 * N + col) = make_float2(v00, v01);
                f32split(v00, h0, l0); f32split(v01, h1, l1);
                *reinterpret_cast<uint32_t*>(Ch + (size_t)row0 * N + col) = bfpack(h0, h1);
                *reinterpret_cast<uint32_t*>(Cl + (size_t)row0 * N + col) = bfpack(l0, l1);
            }
            if (row1 < M) {
                if (OUT_MODE == 2)
                    *reinterpret_cast<float2*>(Cf + (size_t)row1 * N + col) = make_float2(v10, v11);
                f32split(v10, h0, l0); f32split(v11, h1, l1);
                *reinterpret_cast<uint32_t*>(Ch + (size_t)row1 * N + col) = bfpack(h0, h1);
                *reinterpret_cast<uint32_t*>(Cl + (size_t)row1 * N + col) = bfpack(l0, l1);
            }
        }
    }
}

// ================= attention epilogue =================
__global__ void scores_kernel(const float* __restrict__ ov,
                              const float* __restrict__ att_w,
                              const float* __restrict__ att_b,
                              float* __restrict__ scores) {
    int gid = blockIdx.x * blockDim.x + threadIdx.x;
    int w = gid >> 5, lane = gid & 31;
    if (w >= NUM_O) return;
    float sum = 0.f;
#pragma unroll
    for (int d = lane; d < DD; d += 32) sum += ov[(size_t)w * DD + d] * att_w[d];
#pragma unroll
    for (int off = 16; off; off >>= 1) sum += __shfl_down_sync(0xffffffff, sum, off);
    if (lane == 0) scores[w] = sum + att_b[0];
}

__global__ void segment_kernel(const float* __restrict__ scores,
                               const int* __restrict__ img,
                               const float* __restrict__ ov,
                               float* __restrict__ gvec) {
    int g = blockIdx.x, t = threadIdx.x;
    __shared__ float sred[128];
    __shared__ int ired[128];

    float m = -3.4e38f;
    int lo = NUM_O, hi = -1;
    for (int i = t; i < NUM_O; i += 128) {
        if (img[i] == g) {
            m = fmaxf(m, scores[i]);
            lo = min(lo, i);
            hi = max(hi, i);
        }
    }
    sred[t] = m; __syncthreads();
    for (int s = 64; s > 0; s >>= 1) { if (t < s) sred[t] = fmaxf(sred[t], sred[t + s]); __syncthreads(); }
    m = sred[0]; __syncthreads();
    ired[t] = lo; __syncthreads();
    for (int s = 64; s > 0; s >>= 1) { if (t < s) ired[t] = min(ired[t], ired[t + s]); __syncthreads(); }
    lo = ired[0]; __syncthreads();
    ired[t] = hi; __syncthreads();
    for (int s = 64; s > 0; s >>= 1) { if (t < s) ired[t] = max(ired[t], ired[t + s]); __syncthreads(); }
    hi = ired[0]; __syncthreads();

    float z = 0.f;
    for (int i = lo + t; i <= hi; i += 128)
        if (img[i] == g) z += expf(scores[i] - m);
    sred[t] = z; __syncthreads();
    for (int s = 64; s > 0; s >>= 1) { if (t < s) sred[t] += sred[t + s]; __syncthreads(); }
    z = sred[0];
    float invz = 1.f / z;

    float acc = 0.f;
    for (int i = lo; i <= hi; i++) {
        if (img[i] == g)
            acc += expf(scores[i] - m) * invz * ov[(size_t)i * DD + t];
    }
    gvec[g * DD + t] = acc;
}

__global__ void concat_kernel(const float* __restrict__ ov,
                              const float* __restrict__ gvec,
                              const int* __restrict__ img,
                              float* __restrict__ out) {
    int i = blockIdx.x, t = threadIdx.x;
    if (t < DD) out[(size_t)i * 256 + t] = ov[(size_t)i * DD + t];
    else        out[(size_t)i * 256 + t] = gvec[img[i] * DD + (t - DD)];
}

// ================= launch =================
extern "C" void kernel_launch(void* const* d_in, const int* in_sizes, int n_in,
                              void* d_out, int out_size) {
    const int*   objs     = (const int*)d_in[0];
    const int*   trip     = (const int*)d_in[1];
    const int*   img      = (const int*)d_in[2];
    const float* obj_emb  = (const float*)d_in[3];
    const float* pred_emb = (const float*)d_in[4];
    const float* n1w1     = (const float*)d_in[5];
    const float* n1b1     = (const float*)d_in[6];
    const float* n1w2     = (const float*)d_in[7];
    const float* n1b2     = (const float*)d_in[8];
    const float* n2w1     = (const float*)d_in[9];
    const float* n2b1     = (const float*)d_in[10];
    const float* n2w2     = (const float*)d_in[11];
    const float* n2b2     = (const float*)d_in[12];
    const float* att_w    = (const float*)d_in[13];
    const float* att_b    = (const float*)d_in[14];
    float* out = (float*)d_out;

    float *ov, *pooled, *counts, *inv, *scores, *gvec, *U, *saq, *sbq;
    bf16 *ovh, *ovl, *pvh, *pvl, *hh, *hl, *h2h, *h2l;
    bf16 *w1h, *w1l, *w3h, *w3l, *w4h, *w4l;
    __half *h16, *w2h16, *w2l16;
    cudaGetSymbolAddress((void**)&ov,     g_ov);
    cudaGetSymbolAddress((void**)&pooled, g_pooled);
    cudaGetSymbolAddress((void**)&counts, g_counts);
    cudaGetSymbolAddress((void**)&inv,    g_invcnt);
    cudaGetSymbolAddress((void**)&scores, g_scores);
    cudaGetSymbolAddress((void**)&gvec,   g_gvec);
    cudaGetSymbolAddress((void**)&U,      g_U);
    cudaGetSymbolAddress((void**)&saq,    g_saq);
    cudaGetSymbolAddress((void**)&sbq,    g_sbq);
    cudaGetSymbolAddress((void**)&ovh, g_ovh); cudaGetSymbolAddress((void**)&ovl, g_ovl);
    cudaGetSymbolAddress((void**)&pvh, g_pvh); cudaGetSymbolAddress((void**)&pvl, g_pvl);
    cudaGetSymbolAddress((void**)&hh,  g_hh);  cudaGetSymbolAddress((void**)&hl,  g_hl);
    cudaGetSymbolAddress((void**)&h16, g_h16);
    cudaGetSymbolAddress((void**)&h2h, g_h2h); cudaGetSymbolAddress((void**)&h2l, g_h2l);
    cudaGetSymbolAddress((void**)&w1h, g_w1h); cudaGetSymbolAddress((void**)&w1l, g_w1l);
    cudaGetSymbolAddress((void**)&w2h16, g_w2h16); cudaGetSymbolAddress((void**)&w2l16, g_w2l16);
    cudaGetSymbolAddress((void**)&w3h, g_w3h); cudaGetSymbolAddress((void**)&w3l, g_w3l);
    cudaGetSymbolAddress((void**)&w4h, g_w4h); cudaGetSymbolAddress((void**)&w4l, g_w4l);

    float* Us = U;
    float* Uo = U + (size_t)NUM_O * HH;

    const int SMEM128 = 65536;   // 2 stages x 32KB (== 64KB epi staging for OUT3)
    const int SMEM64  = 49152;   // 2 stages x 24KB
    const int SMEMWQ  = 32 * (HH + 2) * 4;   // 65792
    cudaFuncSetAttribute(gemm_hmma<0,0,64,3,0>,  cudaFuncAttributeMaxDynamicSharedMemorySize, SMEM64);
    cudaFuncSetAttribute(gemm_hmma<0,5,128,3,0>, cudaFuncAttributeMaxDynamicSharedMemorySize, SMEM128);
    cudaFuncSetAttribute(gemm_hmma<0,3,128,2,1>, cudaFuncAttributeMaxDynamicSharedMemorySize, SMEM128);
    cudaFuncSetAttribute(gemm_hmma<2,1,64,3,0>,  cudaFuncAttributeMaxDynamicSharedMemorySize, SMEM64);
    cudaFuncSetAttribute(gemm_hmma<0,2,64,3,0>,  cudaFuncAttributeMaxDynamicSharedMemorySize, SMEM64);
    cudaFuncSetAttribute(wquant_f16,             cudaFuncAttributeMaxDynamicSharedMemorySize, SMEMWQ);

    const int mT   = (NUM_T + 127) / 128;   // 157
    const int mO64 = (NUM_O + 63) / 64;     // 79

    // ---- prologue (index 3 = merged U GEMM, profiled by ncu) ----
    wtrans_split<<<dim3(HH/32, K1/32, LL), dim3(32,32)>>>(n1w1, w1h, w1l, K1, HH);   // 0
    gather_init<<<dim3(NUM_T, 2), DD>>>(obj_emb, pred_emb, objs, trip,
                                        ovh, ovl, pvh, pvl);                        // 1
    wquant_f16<<<dim3(N2/32, LL), 256, SMEMWQ>>>(n1w2, w2h16, w2l16, sbq, HH, N2);   // 2

    gemm_hmma<0,0,64,3,0><<<dim3(HH/BN, mO64, 2), 256, SMEM64>>>(                     // 3 (profiled)
        ovh, ovl, nullptr, nullptr, nullptr,
        w1h, w1l, K1, nullptr, nullptr, nullptr,
        U, nullptr, nullptr, nullptr, nullptr, nullptr,
        2*DD, NUM_O*HH, NUM_O, HH, DD);

    zero_kernel<<<(NUM_O + 255) / 256, 256>>>(counts, NUM_O);                        // 4
    count_kernel<<<(NUM_T + 255) / 256, 256>>>(trip, counts);                        // 5
    inv_kernel<<<(NUM_O + 255) / 256, 256>>>(counts, inv);                           // 6
    wtrans_split<<<dim3(HH/32, HH/32, LL), dim3(32,32)>>>(n2w1, w3h, w3l, HH, HH);   // 7
    wtrans_split<<<dim3(DD/32, HH/32, LL), dim3(32,32)>>>(n2w2, w4h, w4l, HH, DD);   // 8

    for (int l = 0; l < LL; l++) {
        const bf16* w1hl = w1h + (size_t)l * HH * K1;
        const bf16* w1ll = w1l + (size_t)l * HH * K1;
        if (l > 0) {
            gemm_hmma<0,0,64,3,0><<<dim3(HH/BN, mO64, 2), 256, SMEM64>>>(
                ovh, ovl, nullptr, nullptr, nullptr,
                w1hl, w1ll, K1, nullptr, nullptr, nullptr,
                U, nullptr, nullptr, nullptr, nullptr, nullptr,
                2*DD, NUM_O*HH, NUM_O, HH, DD);
        }

        // pv GEMM + fused gather-add epilogue: h = relu(pv@Wp + Us[s] + Uo[o] + b1), bf16 pair
        gemm_hmma<0,5,128,3,0><<<dim3(HH/BN, mT), 256, SMEM128>>>(
            pvh, pvl, nullptr, nullptr, trip,
            w1hl + DD, w1ll + DD, K1, n1b1 + (size_t)l*HH, Us, Uo,
            nullptr, hh, hl, nullptr, nullptr, nullptr,
            0, 0, NUM_T, HH, DD);

        // row-scaled fp16 quantization of h
        quant_rows_f16<<<NUM_T, 128>>>(hh, hl, h16, saq);

        zero_kernel<<<(NUM_O * HH + 255) / 256, 256>>>(pooled, NUM_O * HH);

        // GEMM2: fp16 2-term row-scaled (Ah*Bh + Ah*Bl), dequant + fused scatter
        gemm_hmma<0,3,128,2,1><<<dim3(N2/BN, mT), 256, SMEM128>>>(
            (const bf16*)h16, nullptr, nullptr, nullptr, trip,
            (const bf16*)(w2h16 + (size_t)l*N2*HH), (const bf16*)(w2l16 + (size_t)l*N2*HH), HH,
            n1b2 + (size_t)l*N2,
            saq, sbq + (size_t)l*N2,
            nullptr, nullptr, nullptr, pooled, pvh, pvl,
            0, 0, NUM_T, N2, HH);

        // GEMM3: fused scale+split loader
        gemm_hmma<2,1,64,3,0><<<dim3(HH/BN, mO64), 256, SMEM64>>>(
            nullptr, nullptr, pooled, inv, nullptr,
            w3h + (size_t)l*HH*HH, w3l + (size_t)l*HH*HH, HH, n2b1 + (size_t)l*HH,
            nullptr, nullptr,
            nullptr, h2h, h2l, nullptr, nullptr, nullptr,
            0, 0, NUM_O, HH, HH);

        // GEMM4: ov fp32 + bf16 pair
        gemm_hmma<0,2,64,3,0><<<dim3(DD/BN, mO64), 256, SMEM64>>>(
            h2h, h2l, nullptr, nullptr, nullptr,
            w4h + (size_t)l*DD*HH, w4l + (size_t)l*DD*HH, HH, n2b2 + (size_t)l*DD,
            nullptr, nullptr,
            ov, ovh, ovl, nullptr, nullptr, nullptr,
            0, 0, NUM_O, DD, HH);
    }

    scores_kernel<<<(NUM_O * 32 + 255) / 256, 256>>>(ov, att_w, att_b, scores);
    segment_kernel<<<GG, 128>>>(scores, img, ov, gvec);
    concat_kernel<<<NUM_O, 256>>>(ov, gvec, img, out);
}

// round 13
// speedup vs baseline: 4.6470x; 1.1860x over previous
#include <cuda_runtime.h>
#include <cuda_bf16.h>
#include <cuda_fp16.h>
#include <math.h>
#include <stdint.h>

#define NUM_O   5000
#define NUM_T   20000
#define DD      128
#define HH      512
#define GG      64
#define LL      5
#define K1      (3*DD)        // 384
#define N2      (2*HH+DD)     // 1152

typedef __nv_bfloat16 bf16;

// ================= scratch =================
__device__ float g_ov    [NUM_O * DD];
__device__ float g_pooled[NUM_O * HH];
__device__ float g_counts[NUM_O];
__device__ float g_invcnt[NUM_O];
__device__ float g_scores[NUM_O];
__device__ float g_gvec  [GG * DD];
__device__ float g_U     [2 * NUM_O * HH];   // [Us | Uo]

__device__ bf16   g_ovh[NUM_O * DD], g_ovl[NUM_O * DD];
__device__ bf16   g_pvh[NUM_T * DD], g_pvl[NUM_T * DD];
__device__ bf16   g_hh [NUM_T * HH], g_hl [NUM_T * HH];
__device__ bf16   g_h2h[NUM_O * HH], g_h2l[NUM_O * HH];

// row-scaled fp16 GEMM2 operands
__device__ __half g_h16[NUM_T * HH];
__device__ float  g_saq[20096];              // row scales (padded, zero tail)
__device__ __half g_w2h16[LL * N2 * HH];
__device__ float  g_sbq[LL * N2];

__device__ bf16   g_w1h[LL * HH * K1], g_w1l[LL * HH * K1];
__device__ bf16   g_w3h[LL * HH * HH], g_w3l[LL * HH * HH];
__device__ bf16   g_w4h[LL * DD * HH], g_w4l[LL * DD * HH];

__device__ __forceinline__ void f32split(float v, bf16& h, bf16& l) {
    h = __float2bfloat16(v);
    l = __float2bfloat16(v - __bfloat162float(h));
}
__device__ __forceinline__ uint32_t bfpack(bf16 a, bf16 b) {
    __nv_bfloat162 t; t.x = a; t.y = b;
    return *reinterpret_cast<uint32_t*>(&t);
}
__device__ __forceinline__ uint32_t smem_u32(const void* p) {
    uint32_t a;
    asm("{ .reg .u64 t; cvta.to.shared.u64 t, %1; cvt.u32.u64 %0, t; }" : "=r"(a) : "l"(p));
    return a;
}

// ================= glue =================
__global__ void zero_kernel(float* p, int n) {
    int i = blockIdx.x * blockDim.x + threadIdx.x;
    if (i < n) p[i] = 0.f;
}
__global__ void gather_init(const float* __restrict__ obj_emb,
                            const float* __restrict__ pred_emb,
                            const int* __restrict__ objs,
                            const int* __restrict__ trip,
                            bf16* __restrict__ ovh, bf16* __restrict__ ovl,
                            bf16* __restrict__ pvh, bf16* __restrict__ pvl) {
    int i = blockIdx.x, d = threadIdx.x;
    if (blockIdx.y == 0) {
        if (i < NUM_O) {
            float v = obj_emb[objs[i] * DD + d];
            bf16 h, l; f32split(v, h, l);
            ovh[i * DD + d] = h; ovl[i * DD + d] = l;
        }
    } else {
        int p = trip[3 * i + 1];
        float v = pred_emb[p * DD + d];
        bf16 h, l; f32split(v, h, l);
        pvh[i * DD + d] = h; pvl[i * DD + d] = l;
    }
}
__global__ void count_kernel(const int* __restrict__ trip, float* __restrict__ counts) {
    int i = blockIdx.x * blockDim.x + threadIdx.x;
    if (i < NUM_T) {
        atomicAdd(&counts[trip[3 * i + 0]], 1.f);
        atomicAdd(&counts[trip[3 * i + 2]], 1.f);
    }
}
__global__ void inv_kernel(const float* __restrict__ counts, float* __restrict__ inv) {
    int i = blockIdx.x * blockDim.x + threadIdx.x;
    if (i < NUM_O) inv[i] = 1.f / fmaxf(counts[i], 1.f);
}
__global__ void wtrans_split(const float* __restrict__ w,
                             bf16* __restrict__ oh,
                             bf16* __restrict__ ol, int K, int N) {
    __shared__ float tile[32][33];
    int l = blockIdx.z;
    int k0 = blockIdx.y * 32, n0 = blockIdx.x * 32;
    const float* wl = w + (size_t)l * K * N;
    tile[threadIdx.y][threadIdx.x] = wl[(size_t)(k0 + threadIdx.y) * N + n0 + threadIdx.x];
    __syncthreads();
    int on = n0 + threadIdx.y, ok = k0 + threadIdx.x;
    float v = tile[threadIdx.x][threadIdx.y];
    bf16 h, lo; f32split(v, h, lo);
    size_t idx = ((size_t)l * N + on) * K + ok;
    oh[idx] = h; ol[idx] = lo;
}

// w2 [L,K,N] fp32 -> row(n)-scaled fp16 [L,N,K] + sbq[L,N]  (single plane)
__global__ void wquant_f16(const float* __restrict__ w,
                           __half* __restrict__ qbh,
                           float* __restrict__ sbq, int K, int N) {
    extern __shared__ float ws[];   // 32 x (K+2)
    int l = blockIdx.y;
    int n0 = blockIdx.x * 32;
    int tx = threadIdx.x & 31, ty = threadIdx.x >> 5;   // 32 x 8
    const float* wl = w + (size_t)l * K * N;
    for (int k = ty; k < K; k += 8)
        ws[tx * (K + 2) + k] = wl[(size_t)k * N + n0 + tx];
    __syncthreads();
    int lane = threadIdx.x & 31, w8 = threadIdx.x >> 5;
    for (int p = 0; p < 4; p++) {
        int nl = p * 8 + w8;
        float mx = 0.f;
        for (int k = lane; k < K; k += 32) mx = fmaxf(mx, fabsf(ws[nl * (K + 2) + k]));
#pragma unroll
        for (int off = 16; off; off >>= 1) mx = fmaxf(mx, __shfl_xor_sync(0xffffffff, mx, off));
        float inv = mx > 1e-30f ? 2047.f / mx : 0.f;
        for (int k = lane; k < K; k += 32) {
            size_t idx = ((size_t)l * N + n0 + nl) * K + k;
            qbh[idx] = __float2half(ws[nl * (K + 2) + k] * inv);
        }
        if (lane == 0) sbq[(size_t)l * N + n0 + nl] = mx > 1e-30f ? mx / 2047.f : 0.f;
    }
}

// h (bf16 pair) -> row-scaled fp16 plane + saq. h >= 0 (relu).
__global__ void quant_rows_f16(const bf16* __restrict__ xh, const bf16* __restrict__ xl,
                               __half* __restrict__ q, float* __restrict__ saq) {
    int row = blockIdx.x, t = threadIdx.x;   // 128 threads, 512 cols
    __shared__ float red[128];
    const size_t base = (size_t)row * HH;
    float v[4]; float mx = 0.f;
#pragma unroll
    for (int j = 0; j < 4; j++) {
        int c = t + j * 128;
        v[j] = __bfloat162float(xh[base + c]) + __bfloat162float(xl[base + c]);
        mx = fmaxf(mx, v[j]);
    }
    red[t] = mx; __syncthreads();
    for (int s = 64; s > 0; s >>= 1) { if (t < s) red[t] = fmaxf(red[t], red[t + s]); __syncthreads(); }
    float s = red[0];
    float inv = s > 1e-30f ? 2047.f / s : 0.f;
#pragma unroll
    for (int j = 0; j < 4; j++) {
        int c = t + j * 128;
        q[base + c] = __float2half(v[j] * inv);
    }
    if (t == 0) saq[row] = s > 1e-30f ? s / 2047.f : 0.f;
}

// ================= HMMA GEMM =================
// TERMS: 3 = Ah*Bh + Ah*Bl + Al*Bh.  2 = Ah*Bh + Ah*Bl.  1 = Ah*Bh.
// USEF16: 0 bf16 mma, 1 fp16 mma. OUT3+USEF16 dequants acc*Us[row]*Uo[col].
#define BN   128
#define BK   32

#define CP_ASYNC16(dst, src, sz) \
    asm volatile("cp.async.cg.shared.global [%0], [%1], 16, %2;" :: "r"(dst), "l"(src), "r"(sz))
#define CP_COMMIT() asm volatile("cp.async.commit_group;")
#define LDSM_X4(R0,R1,R2,R3,ADDR) \
    asm volatile("ldmatrix.sync.aligned.m8n8.x4.shared.b16 {%0,%1,%2,%3}, [%4];" \
                 : "=r"(R0),"=r"(R1),"=r"(R2),"=r"(R3) : "r"(ADDR))
#define MMA16816(C,A0,A1,A2,A3,B0,B1) \
    asm volatile("mma.sync.aligned.m16n8k16.row.col.f32.bf16.bf16.f32 " \
                 "{%0,%1,%2,%3},{%4,%5,%6,%7},{%8,%9},{%0,%1,%2,%3};" \
                 : "+f"((C)[0]),"+f"((C)[1]),"+f"((C)[2]),"+f"((C)[3]) \
                 : "r"(A0),"r"(A1),"r"(A2),"r"(A3),"r"(B0),"r"(B1))
#define MMA16816F(C,A0,A1,A2,A3,B0,B1) \
    asm volatile("mma.sync.aligned.m16n8k16.row.col.f32.f16.f16.f32 " \
                 "{%0,%1,%2,%3},{%4,%5,%6,%7},{%8,%9},{%0,%1,%2,%3};" \
                 : "+f"((C)[0]),"+f"((C)[1]),"+f"((C)[2]),"+f"((C)[3]) \
                 : "r"(A0),"r"(A1),"r"(A2),"r"(A3),"r"(B0),"r"(B1))
#define STS128(ADDR,A,B,C,D) \
    asm volatile("st.shared.v4.b32 [%0], {%1,%2,%3,%4};" :: "r"(ADDR),"r"(A),"r"(B),"r"(C),"r"(D))
#define REDV4(PTR,X,Y,Z,W) \
    asm volatile("red.global.add.v4.f32 [%0], {%1,%2,%3,%4};" :: "l"(PTR),"f"(X),"f"(Y),"f"(Z),"f"(W) : "memory")

__device__ __forceinline__ uint32_t sw_off(int row, int c) {
    return (uint32_t)(row * 64 + (((c ^ (row & 3))) << 4));
}

template <int A_MODE, int TBM, int TERMS>
__device__ __forceinline__ void ld_stage(
    uint32_t st,
    const bf16* __restrict__ Ah, const bf16* __restrict__ Al,
    const float* __restrict__ Af, const float* __restrict__ inv,
    const bf16* __restrict__ Bh, const bf16* __restrict__ Bl, int Bstride,
    int bm, int bn, int k0, int M, int K, int tid)
{
    constexpr uint32_t OFF_AL = TBM * 64;
    constexpr uint32_t OFF_BH = TBM * 128;
    constexpr uint32_t OFF_BL = TBM * 128 + 8192;
#pragma unroll
    for (int lin = tid; lin < TBM * 4; lin += 256) {
        int row = lin >> 2;
        int c   = lin & 3;
        uint32_t so = sw_off(row, c);
        int gr = bm + row;
        bool ok = gr < M;
        if (A_MODE == 2) {
            if (ok) {
                const float4* src = reinterpret_cast<const float4*>(Af + (size_t)gr * K + k0 + c * 8);
                float4 v0 = src[0], v1 = src[1];
                float s = __ldg(&inv[gr]);
                bf16 hb[8], lb[8];
                float vals[8] = {v0.x*s, v0.y*s, v0.z*s, v0.w*s, v1.x*s, v1.y*s, v1.z*s, v1.w*s};
#pragma unroll
                for (int j = 0; j < 8; j++) f32split(vals[j], hb[j], lb[j]);
                STS128(st + so, bfpack(hb[0],hb[1]), bfpack(hb[2],hb[3]), bfpack(hb[4],hb[5]), bfpack(hb[6],hb[7]));
                STS128(st + OFF_AL + so, bfpack(lb[0],lb[1]), bfpack(lb[2],lb[3]), bfpack(lb[4],lb[5]), bfpack(lb[6],lb[7]));
            } else {
                STS128(st + so, 0u, 0u, 0u, 0u);
                STS128(st + OFF_AL + so, 0u, 0u, 0u, 0u);
            }
        } else {
            uint32_t sz = ok ? 16u : 0u;
            size_t srow = ok ? (size_t)gr : 0;
            const char* sh = (const char*)(Ah + srow * K + k0 + c * 8);
            CP_ASYNC16(st + so, sh, sz);
            if (TERMS == 3) {
                const char* sl = (const char*)(Al + srow * K + k0 + c * 8);
                CP_ASYNC16(st + OFF_AL + so, sl, sz);
            }
        }
    }
#pragma unroll
    for (int lin = tid; lin < 512; lin += 256) {
        int row = lin >> 2;
        int c   = lin & 3;
        uint32_t so = sw_off(row, c);
        int gr = bn + row;
        const char* sh = (const char*)(Bh + (size_t)gr * Bstride + k0 + c * 8);
        CP_ASYNC16(st + OFF_BH + so, sh, 16u);
        if (TERMS >= 2) {
            const char* sl = (const char*)(Bl + (size_t)gr * Bstride + k0 + c * 8);
            CP_ASYNC16(st + OFF_BL + so, sl, 16u);
        }
    }
}

template <int A_MODE, int OUT_MODE, int TBM, int TERMS, int USEF16>
__global__ void __launch_bounds__(256)
gemm_hmma(const bf16* __restrict__ Ah, const bf16* __restrict__ Al,
          const float* __restrict__ Af, const float* __restrict__ inv,
          const int* __restrict__ trip,
          const bf16* __restrict__ Bh, const bf16* __restrict__ Bl, int Bstride,
          const float* __restrict__ bias,
          const float* __restrict__ Us, const float* __restrict__ Uo,
          float* __restrict__ Cf,
          bf16* __restrict__ Ch, bf16* __restrict__ Cl,
          float* __restrict__ pooled,
          bf16* __restrict__ Pvh, bf16* __restrict__ Pvl,
          int zBoff, int zCoff,
          int M, int N, int K)
{
    constexpr uint32_t OFF_AL = TBM * 64;
    constexpr uint32_t OFF_BH = TBM * 128;
    constexpr uint32_t OFF_BL = TBM * 128 + 8192;
    constexpr uint32_t STAGE  = TBM * 128 + 16384;
    constexpr int NWM = (TBM == 128) ? 2 : 1;
    constexpr int NT  = (TBM == 128) ? 4 : 2;

    {
        size_t zb = (size_t)blockIdx.z * (size_t)zBoff;
        Bh += zb; Bl += zb;
        if (Cf) Cf += (size_t)blockIdx.z * (size_t)zCoff;
    }

    extern __shared__ char smem[];
    uint32_t sb = smem_u32(smem);

    int tid = threadIdx.x;
    int wid = tid >> 5, lane = tid & 31;
    int wm = (wid % NWM) * 64;
    int wn = (wid / NWM) * (NT * 8);
    int bm = blockIdx.y * TBM;
    int bn = blockIdx.x * BN;
    const int NC = K / BK;

    float acc[4][NT][4];
#pragma unroll
    for (int i = 0; i < 4; i++)
#pragma unroll
        for (int j = 0; j < NT; j++)
#pragma unroll
            for (int r = 0; r < 4; r++) acc[i][j][r] = 0.f;

    int lrow8 = (lane & 7) + ((lane >> 3) & 1) * 8;
    int lchunk = (lane >> 4);

    ld_stage<A_MODE, TBM, TERMS>(sb, Ah, Al, Af, inv, Bh, Bl, Bstride, bm, bn, 0, M, K, tid);
    CP_COMMIT();

    for (int kc = 0; kc < NC; kc++) {
        if (kc + 1 < NC) {
            ld_stage<A_MODE, TBM, TERMS>(sb + ((kc + 1) & 1) * STAGE, Ah, Al, Af, inv, Bh, Bl, Bstride,
                                         bm, bn, (kc + 1) * BK, M, K, tid);
            CP_COMMIT();
            asm volatile("cp.async.wait_group 1;");
        } else {
            asm volatile("cp.async.wait_group 0;");
        }
        __syncthreads();

        uint32_t sa = sb + (kc & 1) * STAGE;
#pragma unroll
        for (int ks = 0; ks < 2; ks++) {
            int c0 = ks * 2;
            uint32_t ah[4][4], al[4][4], bh[NT][2], bl[NT][2];
#pragma unroll
            for (int mt = 0; mt < 4; mt++) {
                int row = wm + mt * 16 + lrow8;
                LDSM_X4(ah[mt][0], ah[mt][1], ah[mt][2], ah[mt][3], sa + sw_off(row, c0 + lchunk));
            }
#pragma unroll
            for (int np = 0; np < NT / 2; np++) {
                int row = wn + np * 16 + lrow8;
                uint32_t r0, r1, r2, r3;
                LDSM_X4(r0, r1, r2, r3, sa + OFF_BH + sw_off(row, c0 + lchunk));
                bh[2*np][0] = r0; bh[2*np+1][0] = r1;
                bh[2*np][1] = r2; bh[2*np+1][1] = r3;
            }
#pragma unroll
            for (int mt = 0; mt < 4; mt++)
#pragma unroll
                for (int nt = 0; nt < NT; nt++) {
                    if (USEF16) MMA16816F(acc[mt][nt], ah[mt][0], ah[mt][1], ah[mt][2], ah[mt][3],
                                          bh[nt][0], bh[nt][1]);
                    else        MMA16816(acc[mt][nt], ah[mt][0], ah[mt][1], ah[mt][2], ah[mt][3],
                                         bh[nt][0], bh[nt][1]);
                }
            if (TERMS >= 2) {
#pragma unroll
                for (int np = 0; np < NT / 2; np++) {
                    int row = wn + np * 16 + lrow8;
                    uint32_t r0, r1, r2, r3;
                    LDSM_X4(r0, r1, r2, r3, sa + OFF_BL + sw_off(row, c0 + lchunk));
                    bl[2*np][0] = r0; bl[2*np+1][0] = r1;
                    bl[2*np][1] = r2; bl[2*np+1][1] = r3;
                }
#pragma unroll
                for (int mt = 0; mt < 4; mt++)
#pragma unroll
                    for (int nt = 0; nt < NT; nt++) {
                        if (USEF16) MMA16816F(acc[mt][nt], ah[mt][0], ah[mt][1], ah[mt][2], ah[mt][3],
                                              bl[nt][0], bl[nt][1]);
                        else        MMA16816(acc[mt][nt], ah[mt][0], ah[mt][1], ah[mt][2], ah[mt][3],
                                             bl[nt][0], bl[nt][1]);
                    }
            }
            if (TERMS == 3) {
#pragma unroll
                for (int mt = 0; mt < 4; mt++) {
                    int row = wm + mt * 16 + lrow8;
                    LDSM_X4(al[mt][0], al[mt][1], al[mt][2], al[mt][3], sa + OFF_AL + sw_off(row, c0 + lchunk));
                }
#pragma unroll
                for (int mt = 0; mt < 4; mt++)
#pragma unroll
                    for (int nt = 0; nt < NT; nt++) {
                        if (USEF16) MMA16816F(acc[mt][nt], al[mt][0], al[mt][1], al[mt][2], al[mt][3],
                                              bh[nt][0], bh[nt][1]);
                        else        MMA16816(acc[mt][nt], al[mt][0], al[mt][1], al[mt][2], al[mt][3],
                                             bh[nt][0], bh[nt][1]);
                    }
            }
        }
        __syncthreads();
    }

    int r = lane >> 2, q = lane & 3;

    if (OUT_MODE == 3) {
#pragma unroll
        for (int mt = 0; mt < 4; mt++) {
            int lr0 = wm + mt * 16 + r;
            float sa0 = 1.f, sa1 = 1.f;
            if (USEF16) {
                sa0 = __ldg(&Us[bm + lr0]);
                sa1 = __ldg(&Us[bm + lr0 + 8]);
            }
#pragma unroll
            for (int nt = 0; nt < NT; nt++) {
                int lc = wn + nt * 8 + q * 2;
                int col = bn + lc;
                float b0 = bias[col], b1 = bias[col + 1];
                float sb0 = 1.f, sb1 = 1.f;
                if (USEF16) { sb0 = __ldg(&Uo[col]); sb1 = __ldg(&Uo[col + 1]); }
                float2 v0 = make_float2(fmaxf(acc[mt][nt][0] * sa0 * sb0 + b0, 0.f),
                                        fmaxf(acc[mt][nt][1] * sa0 * sb1 + b1, 0.f));
                float2 v1 = make_float2(fmaxf(acc[mt][nt][2] * sa1 * sb0 + b0, 0.f),
                                        fmaxf(acc[mt][nt][3] * sa1 * sb1 + b1, 0.f));
                *reinterpret_cast<float2*>(smem + ((size_t)lr0 * 128 + lc) * 4) = v0;
                *reinterpret_cast<float2*>(smem + ((size_t)(lr0 + 8) * 128 + lc) * 4) = v1;
            }
        }
        __syncthreads();
        int row = tid >> 1;
        int half = (tid & 1) * 64;
        int gr = bm + row;
        if (gr < M) {
            const float* srow = reinterpret_cast<const float*>(smem) + (size_t)row * 128 + half;
            if (bn == 512) {
#pragma unroll
                for (int i = 0; i < 16; i++) {
                    float4 v = *reinterpret_cast<const float4*>(srow + i * 4);
                    bf16 h0,l0,h1,l1,h2,l2,h3,l3;
                    f32split(v.x,h0,l0); f32split(v.y,h1,l1); f32split(v.z,h2,l2); f32split(v.w,h3,l3);
                    uint2 hp = make_uint2(bfpack(h0,h1), bfpack(h2,h3));
                    uint2 lp = make_uint2(bfpack(l0,l1), bfpack(l2,l3));
                    int pc = half + i * 4;
                    *reinterpret_cast<uint2*>(Pvh + (size_t)gr * DD + pc) = hp;
                    *reinterpret_cast<uint2*>(Pvl + (size_t)gr * DD + pc) = lp;
                }
            } else {
                int obj = __ldg(&trip[3 * gr + ((bn < 512) ? 0 : 2)]);
                float* dst = pooled + (size_t)obj * HH + ((bn < 512) ? bn : bn - 640) + half;
#pragma unroll
                for (int i = 0; i < 16; i++) {
                    float4 v = *reinterpret_cast<const float4*>(srow + i * 4);
                    REDV4(dst + i * 4, v.x, v.y, v.z, v.w);
                }
            }
        }
        return;
    }

#pragma unroll
    for (int mt = 0; mt < 4; mt++) {
        int row0 = bm + wm + mt * 16 + r;
        int row1 = row0 + 8;
        int s0 = 0, o0 = 0, s1 = 0, o1 = 0;
        if (OUT_MODE == 5) {
            if (row0 < M) { s0 = __ldg(&trip[3 * row0]); o0 = __ldg(&trip[3 * row0 + 2]); }
            if (row1 < M) { s1 = __ldg(&trip[3 * row1]); o1 = __ldg(&trip[3 * row1 + 2]); }
        }
#pragma unroll
        for (int nt = 0; nt < NT; nt++) {
            int col = bn + wn + nt * 8 + q * 2;
            if (OUT_MODE == 0) {
                if (row0 < M)
                    *reinterpret_cast<float2*>(Cf + (size_t)row0 * N + col) = make_float2(acc[mt][nt][0], acc[mt][nt][1]);
                if (row1 < M)
                    *reinterpret_cast<float2*>(Cf + (size_t)row1 * N + col) = make_float2(acc[mt][nt][2], acc[mt][nt][3]);
                continue;
            }
            float b0 = bias[col], b1 = bias[col + 1];
            float a00 = acc[mt][nt][0] + b0, a01 = acc[mt][nt][1] + b1;
            float a10 = acc[mt][nt][2] + b0, a11 = acc[mt][nt][3] + b1;
            if (OUT_MODE == 5) {
                if (row0 < M) {
                    float2 us = *reinterpret_cast<const float2*>(Us + (size_t)s0 * HH + col);
                    float2 uo = *reinterpret_cast<const float2*>(Uo + (size_t)o0 * HH + col);
                    a00 += us.x + uo.x; a01 += us.y + uo.y;
                }
                if (row1 < M) {
                    float2 us = *reinterpret_cast<const float2*>(Us + (size_t)s1 * HH + col);
                    float2 uo = *reinterpret_cast<const float2*>(Uo + (size_t)o1 * HH + col);
                    a10 += us.x + uo.x; a11 += us.y + uo.y;
                }
            }
            float v00 = fmaxf(a00, 0.f), v01 = fmaxf(a01, 0.f);
            float v10 = fmaxf(a10, 0.f), v11 = fmaxf(a11, 0.f);
            bf16 h0, l0, h1, l1;
            if (row0 < M) {
                if (OUT_MODE == 2)
                    *reinterpret_cast<float2*>(Cf + (size_t)row0 * N + col) = make_float2(v00, v01);
                f32split(v00, h0, l0); f32split(v01, h1, l1);
                *reinterpret_cast<uint32_t*>(Ch + (size_t)row0 * N + col) = bfpack(h0, h1);
                *reinterpret_cast<uint32_t*>(Cl + (size_t)row0 * N + col) = bfpack(l0, l1);
            }
            if (row1 < M) {
                if (OUT_MODE == 2)
                    *reinterpret_cast<float2*>(Cf + (size_t)row1 * N + col) = make_float2(v10, v11);
                f32split(v10, h0, l0); f32split(v11, h1, l1);
                *reinterpret_cast<uint32_t*>(Ch + (size_t)row1 * N + col) = bfpack(h0, h1);
                *reinterpret_cast<uint32_t*>(Cl + (size_t)row1 * N + col) = bfpack(l0, l1);
            }
        }
    }
}

// ================= attention epilogue =================
__global__ void scores_kernel(const float* __restrict__ ov,
                              const float* __restrict__ att_w,
                              const float* __restrict__ att_b,
                              float* __restrict__ scores) {
    int gid = blockIdx.x * blockDim.x + threadIdx.x;
    int w = gid >> 5, lane = gid & 31;
    if (w >= NUM_O) return;
    float sum = 0.f;
#pragma unroll
    for (int d = lane; d < DD; d += 32) sum += ov[(size_t)w * DD + d] * att_w[d];
#pragma unroll
    for (int off = 16; off; off >>= 1) sum += __shfl_down_sync(0xffffffff, sum, off);
    if (lane == 0) scores[w] = sum + att_b[0];
}

__global__ void segment_kernel(const float* __restrict__ scores,
                               const int* __restrict__ img,
                               const float* __restrict__ ov,
                               float* __restrict__ gvec) {
    int g = blockIdx.x, t = threadIdx.x;
    __shared__ float sred[128];
    __shared__ int ired[128];

    float m = -3.4e38f;
    int lo = NUM_O, hi = -1;
    for (int i = t; i < NUM_O; i += 128) {
        if (img[i] == g) {
            m = fmaxf(m, scores[i]);
            lo = min(lo, i);
            hi = max(hi, i);
        }
    }
    sred[t] = m; __syncthreads();
    for (int s = 64; s > 0; s >>= 1) { if (t < s) sred[t] = fmaxf(sred[t], sred[t + s]); __syncthreads(); }
    m = sred[0]; __syncthreads();
    ired[t] = lo; __syncthreads();
    for (int s = 64; s > 0; s >>= 1) { if (t < s) ired[t] = min(ired[t], ired[t + s]); __syncthreads(); }
    lo = ired[0]; __syncthreads();
    ired[t] = hi; __syncthreads();
    for (int s = 64; s > 0; s >>= 1) { if (t < s) ired[t] = max(ired[t], ired[t + s]); __syncthreads(); }
    hi = ired[0]; __syncthreads();

    float z = 0.f;
    for (int i = lo + t; i <= hi; i += 128)
        if (img[i] == g) z += expf(scores[i] - m);
    sred[t] = z; __syncthreads();
    for (int s = 64; s > 0; s >>= 1) { if (t < s) sred[t] += sred[t + s]; __syncthreads(); }
    z = sred[0];
    float invz = 1.f / z;

    float acc = 0.f;
    for (int i = lo; i <= hi; i++) {
        if (img[i] == g)
            acc += expf(scores[i] - m) * invz * ov[(size_t)i * DD + t];
    }
    gvec[g * DD + t] = acc;
}

__global__ void concat_kernel(const float* __restrict__ ov,
                              const float* __restrict__ gvec,
                              const int* __restrict__ img,
                              float* __restrict__ out) {
    int i = blockIdx.x, t = threadIdx.x;
    if (t < DD) out[(size_t)i * 256 + t] = ov[(size_t)i * DD + t];
    else        out[(size_t)i * 256 + t] = gvec[img[i] * DD + (t - DD)];
}

// ================= launch =================
extern "C" void kernel_launch(void* const* d_in, const int* in_sizes, int n_in,
                              void* d_out, int out_size) {
    const int*   objs     = (const int*)d_in[0];
    const int*   trip     = (const int*)d_in[1];
    const int*   img      = (const int*)d_in[2];
    const float* obj_emb  = (const float*)d_in[3];
    const float* pred_emb = (const float*)d_in[4];
    const float* n1w1     = (const float*)d_in[5];
    const float* n1b1     = (const float*)d_in[6];
    const float* n1w2     = (const float*)d_in[7];
    const float* n1b2     = (const float*)d_in[8];
    const float* n2w1     = (const float*)d_in[9];
    const float* n2b1     = (const float*)d_in[10];
    const float* n2w2     = (const float*)d_in[11];
    const float* n2b2     = (const float*)d_in[12];
    const float* att_w    = (const float*)d_in[13];
    const float* att_b    = (const float*)d_in[14];
    float* out = (float*)d_out;

    float *ov, *pooled, *counts, *inv, *scores, *gvec, *U, *saq, *sbq;
    bf16 *ovh, *ovl, *pvh, *pvl, *hh, *hl, *h2h, *h2l;
    bf16 *w1h, *w1l, *w3h, *w3l, *w4h, *w4l;
    __half *h16, *w2h16;
    cudaGetSymbolAddress((void**)&ov,     g_ov);
    cudaGetSymbolAddress((void**)&pooled, g_pooled);
    cudaGetSymbolAddress((void**)&counts, g_counts);
    cudaGetSymbolAddress((void**)&inv,    g_invcnt);
    cudaGetSymbolAddress((void**)&scores, g_scores);
    cudaGetSymbolAddress((void**)&gvec,   g_gvec);
    cudaGetSymbolAddress((void**)&U,      g_U);
    cudaGetSymbolAddress((void**)&saq,    g_saq);
    cudaGetSymbolAddress((void**)&sbq,    g_sbq);
    cudaGetSymbolAddress((void**)&ovh, g_ovh); cudaGetSymbolAddress((void**)&ovl, g_ovl);
    cudaGetSymbolAddress((void**)&pvh, g_pvh); cudaGetSymbolAddress((void**)&pvl, g_pvl);
    cudaGetSymbolAddress((void**)&hh,  g_hh);  cudaGetSymbolAddress((void**)&hl,  g_hl);
    cudaGetSymbolAddress((void**)&h16, g_h16);
    cudaGetSymbolAddress((void**)&h2h, g_h2h); cudaGetSymbolAddress((void**)&h2l, g_h2l);
    cudaGetSymbolAddress((void**)&w1h, g_w1h); cudaGetSymbolAddress((void**)&w1l, g_w1l);
    cudaGetSymbolAddress((void**)&w2h16, g_w2h16);
    cudaGetSymbolAddress((void**)&w3h, g_w3h); cudaGetSymbolAddress((void**)&w3l, g_w3l);
    cudaGetSymbolAddress((void**)&w4h, g_w4h); cudaGetSymbolAddress((void**)&w4l, g_w4l);

    float* Us = U;
    float* Uo = U + (size_t)NUM_O * HH;

    const int SMEM128 = 65536;
    const int SMEM64  = 49152;
    const int SMEMWQ  = 32 * (HH + 2) * 4;
    cudaFuncSetAttribute(gemm_hmma<0,0,64,3,0>,  cudaFuncAttributeMaxDynamicSharedMemorySize, SMEM64);
    cudaFuncSetAttribute(gemm_hmma<0,5,128,3,0>, cudaFuncAttributeMaxDynamicSharedMemorySize, SMEM128);
    cudaFuncSetAttribute(gemm_hmma<0,3,128,1,1>, cudaFuncAttributeMaxDynamicSharedMemorySize, SMEM128);
    cudaFuncSetAttribute(gemm_hmma<2,1,64,3,0>,  cudaFuncAttributeMaxDynamicSharedMemorySize, SMEM64);
    cudaFuncSetAttribute(gemm_hmma<0,2,64,3,0>,  cudaFuncAttributeMaxDynamicSharedMemorySize, SMEM64);
    cudaFuncSetAttribute(wquant_f16,             cudaFuncAttributeMaxDynamicSharedMemorySize, SMEMWQ);

    const int mT   = (NUM_T + 127) / 128;   // 157
    const int mO64 = (NUM_O + 63) / 64;     // 79

    // ---- prologue (index 3 = merged U GEMM, profiled by ncu) ----
    wtrans_split<<<dim3(HH/32, K1/32, LL), dim3(32,32)>>>(n1w1, w1h, w1l, K1, HH);   // 0
    gather_init<<<dim3(NUM_T, 2), DD>>>(obj_emb, pred_emb, objs, trip,
                                        ovh, ovl, pvh, pvl);                        // 1
    wquant_f16<<<dim3(N2/32, LL), 256, SMEMWQ>>>(n1w2, w2h16, sbq, HH, N2);          // 2

    gemm_hmma<0,0,64,3,0><<<dim3(HH/BN, mO64, 2), 256, SMEM64>>>(                     // 3 (profiled)
        ovh, ovl, nullptr, nullptr, nullptr,
        w1h, w1l, K1, nullptr, nullptr, nullptr,
        U, nullptr, nullptr, nullptr, nullptr, nullptr,
        2*DD, NUM_O*HH, NUM_O, HH, DD);

    zero_kernel<<<(NUM_O + 255) / 256, 256>>>(counts, NUM_O);                        // 4
    count_kernel<<<(NUM_T + 255) / 256, 256>>>(trip, counts);                        // 5
    inv_kernel<<<(NUM_O + 255) / 256, 256>>>(counts, inv);                           // 6
    wtrans_split<<<dim3(HH/32, HH/32, LL), dim3(32,32)>>>(n2w1, w3h, w3l, HH, HH);   // 7
    wtrans_split<<<dim3(DD/32, HH/32, LL), dim3(32,32)>>>(n2w2, w4h, w4l, HH, DD);   // 8

    for (int l = 0; l < LL; l++) {
        const bf16* w1hl = w1h + (size_t)l * HH * K1;
        const bf16* w1ll = w1l + (size_t)l * HH * K1;
        if (l > 0) {
            gemm_hmma<0,0,64,3,0><<<dim3(HH/BN, mO64, 2), 256, SMEM64>>>(
                ovh, ovl, nullptr, nullptr, nullptr,
                w1hl, w1ll, K1, nullptr, nullptr, nullptr,
                U, nullptr, nullptr, nullptr, nullptr, nullptr,
                2*DD, NUM_O*HH, NUM_O, HH, DD);
        }

        // pv GEMM + fused gather-add epilogue: h = relu(pv@Wp + Us[s] + Uo[o] + b1), bf16 pair
        gemm_hmma<0,5,128,3,0><<<dim3(HH/BN, mT), 256, SMEM128>>>(
            pvh, pvl, nullptr, nullptr, trip,
            w1hl + DD, w1ll + DD, K1, n1b1 + (size_t)l*HH, Us, Uo,
            nullptr, hh, hl, nullptr, nullptr, nullptr,
            0, 0, NUM_T, HH, DD);

        // row-scaled fp16 quantization of h
        quant_rows_f16<<<NUM_T, 128>>>(hh, hl, h16, saq);

        zero_kernel<<<(NUM_O * HH + 255) / 256, 256>>>(pooled, NUM_O * HH);

        // GEMM2: fp16 1-term row-scaled (Ah*Bh), dequant + fused scatter
        gemm_hmma<0,3,128,1,1><<<dim3(N2/BN, mT), 256, SMEM128>>>(
            (const bf16*)h16, nullptr, nullptr, nullptr, trip,
            (const bf16*)(w2h16 + (size_t)l*N2*HH), nullptr, HH,
            n1b2 + (size_t)l*N2,
            saq, sbq + (size_t)l*N2,
            nullptr, nullptr, nullptr, pooled, pvh, pvl,
            0, 0, NUM_T, N2, HH);

        // GEMM3: fused scale+split loader
        gemm_hmma<2,1,64,3,0><<<dim3(HH/BN, mO64), 256, SMEM64>>>(
            nullptr, nullptr, pooled, inv, nullptr,
            w3h + (size_t)l*HH*HH, w3l + (size_t)l*HH*HH, HH, n2b1 + (size_t)l*HH,
            nullptr, nullptr,
            nullptr, h2h, h2l, nullptr, nullptr, nullptr,
            0, 0, NUM_O, HH, HH);

        // GEMM4: ov fp32 + bf16 pair
        gemm_hmma<0,2,64,3,0><<<dim3(DD/BN, mO64), 256, SMEM64>>>(
            h2h, h2l, nullptr, nullptr, nullptr,
            w4h + (size_t)l*DD*HH, w4l + (size_t)l*DD*HH, HH, n2b2 + (size_t)l*DD,
            nullptr, nullptr,
            ov, ovh, ovl, nullptr, nullptr, nullptr,
            0, 0, NUM_O, DD, HH);
    }

    scores_kernel<<<(NUM_O * 32 + 255) / 256, 256>>>(ov, att_w, att_b, scores);
    segment_kernel<<<GG, 128>>>(scores, img, ov, gvec);
    concat_kernel<<<NUM_O, 256>>>(ov, gvec, img, out);
}

// round 14
// speedup vs baseline: 4.8380x; 1.0411x over previous
#include <cuda_runtime.h>
#include <cuda_bf16.h>
#include <cuda_fp16.h>
#include <math.h>
#include <stdint.h>

#define NUM_O   5000
#define NUM_T   20000
#define DD      128
#define HH      512
#define GG      64
#define LL      5
#define K1      (3*DD)        // 384
#define N2      (2*HH+DD)     // 1152

typedef __nv_bfloat16 bf16;

// ================= scratch =================
__device__ float g_ov    [NUM_O * DD];
__device__ float g_pooled[NUM_O * HH];
__device__ float g_counts[NUM_O];
__device__ float g_invcnt[NUM_O];
__device__ float g_scores[NUM_O];
__device__ float g_gvec  [GG * DD];
__device__ float g_U     [2 * NUM_O * HH];   // [Us | Uo]

__device__ bf16   g_ovh[NUM_O * DD], g_ovl[NUM_O * DD];
__device__ bf16   g_pvh[NUM_T * DD], g_pvl[NUM_T * DD];
__device__ bf16   g_hh [NUM_T * HH], g_hl [NUM_T * HH];
__device__ bf16   g_h2h[NUM_O * HH], g_h2l[NUM_O * HH];

// row-scaled fp16 operands
__device__ __half g_h16[NUM_T * HH];
__device__ float  g_saq[20096];
__device__ __half g_pv16[NUM_T * DD];
__device__ float  g_spq[20096];
__device__ __half g_p16[NUM_O * HH];
__device__ float  g_spl[5120];
__device__ __half g_w2h16[LL * N2 * HH];
__device__ float  g_sbq2[LL * N2];
__device__ __half g_w1p16[LL * HH * DD];
__device__ float  g_sbq1p[LL * HH];
__device__ __half g_w316[LL * HH * HH];
__device__ float  g_sbq3[LL * HH];

__device__ bf16   g_w1h[LL * HH * K1], g_w1l[LL * HH * K1];
__device__ bf16   g_w4h[LL * DD * HH], g_w4l[LL * DD * HH];

__device__ __forceinline__ void f32split(float v, bf16& h, bf16& l) {
    h = __float2bfloat16(v);
    l = __float2bfloat16(v - __bfloat162float(h));
}
__device__ __forceinline__ uint32_t bfpack(bf16 a, bf16 b) {
    __nv_bfloat162 t; t.x = a; t.y = b;
    return *reinterpret_cast<uint32_t*>(&t);
}
__device__ __forceinline__ uint32_t smem_u32(const void* p) {
    uint32_t a;
    asm("{ .reg .u64 t; cvta.to.shared.u64 t, %1; cvt.u32.u64 %0, t; }" : "=r"(a) : "l"(p));
    return a;
}

// ================= glue =================
__global__ void zero_kernel(float* p, int n) {
    int i = blockIdx.x * blockDim.x + threadIdx.x;
    if (i < n) p[i] = 0.f;
}
__global__ void gather_init(const float* __restrict__ obj_emb,
                            const float* __restrict__ pred_emb,
                            const int* __restrict__ objs,
                            const int* __restrict__ trip,
                            bf16* __restrict__ ovh, bf16* __restrict__ ovl,
                            bf16* __restrict__ pvh, bf16* __restrict__ pvl) {
    int i = blockIdx.x, d = threadIdx.x;
    if (blockIdx.y == 0) {
        if (i < NUM_O) {
            float v = obj_emb[objs[i] * DD + d];
            bf16 h, l; f32split(v, h, l);
            ovh[i * DD + d] = h; ovl[i * DD + d] = l;
        }
    } else {
        int p = trip[3 * i + 1];
        float v = pred_emb[p * DD + d];
        bf16 h, l; f32split(v, h, l);
        pvh[i * DD + d] = h; pvl[i * DD + d] = l;
    }
}
__global__ void count_kernel(const int* __restrict__ trip, float* __restrict__ counts) {
    int i = blockIdx.x * blockDim.x + threadIdx.x;
    if (i < NUM_T) {
        atomicAdd(&counts[trip[3 * i + 0]], 1.f);
        atomicAdd(&counts[trip[3 * i + 2]], 1.f);
    }
}
__global__ void inv_kernel(const float* __restrict__ counts, float* __restrict__ inv) {
    int i = blockIdx.x * blockDim.x + threadIdx.x;
    if (i < NUM_O) inv[i] = 1.f / fmaxf(counts[i], 1.f);
}
__global__ void wtrans_split(const float* __restrict__ w,
                             bf16* __restrict__ oh,
                             bf16* __restrict__ ol, int K, int N) {
    __shared__ float tile[32][33];
    int l = blockIdx.z;
    int k0 = blockIdx.y * 32, n0 = blockIdx.x * 32;
    const float* wl = w + (size_t)l * K * N;
    tile[threadIdx.y][threadIdx.x] = wl[(size_t)(k0 + threadIdx.y) * N + n0 + threadIdx.x];
    __syncthreads();
    int on = n0 + threadIdx.y, ok = k0 + threadIdx.x;
    float v = tile[threadIdx.x][threadIdx.y];
    bf16 h, lo; f32split(v, h, lo);
    size_t idx = ((size_t)l * N + on) * K + ok;
    oh[idx] = h; ol[idx] = lo;
}

// w [L(lstride), K, N] slice -> row(n)-scaled fp16 [L,N,K] + sbq[L,N]
__global__ void wquant_f16(const float* __restrict__ w,
                           __half* __restrict__ qbh,
                           float* __restrict__ sbq, int K, int N, int lstride) {
    extern __shared__ float ws[];   // 32 x (K+2)
    int l = blockIdx.y;
    int n0 = blockIdx.x * 32;
    int tx = threadIdx.x & 31, ty = threadIdx.x >> 5;
    const float* wl = w + (size_t)l * lstride;
    for (int k = ty; k < K; k += 8)
        ws[tx * (K + 2) + k] = wl[(size_t)k * N + n0 + tx];
    __syncthreads();
    int lane = threadIdx.x & 31, w8 = threadIdx.x >> 5;
    for (int p = 0; p < 4; p++) {
        int nl = p * 8 + w8;
        float mx = 0.f;
        for (int k = lane; k < K; k += 32) mx = fmaxf(mx, fabsf(ws[nl * (K + 2) + k]));
#pragma unroll
        for (int off = 16; off; off >>= 1) mx = fmaxf(mx, __shfl_xor_sync(0xffffffff, mx, off));
        float inv = mx > 1e-30f ? 2047.f / mx : 0.f;
        for (int k = lane; k < K; k += 32) {
            size_t idx = ((size_t)l * N + n0 + nl) * K + k;
            qbh[idx] = __float2half(ws[nl * (K + 2) + k] * inv);
        }
        if (lane == 0) sbq[(size_t)l * N + n0 + nl] = mx > 1e-30f ? mx / 2047.f : 0.f;
    }
}

// bf16-pair rows -> row-scaled fp16 + scale. COLS elems/row, 128 threads.
template <int COLS>
__global__ void quant_rows_f16(const bf16* __restrict__ xh, const bf16* __restrict__ xl,
                               __half* __restrict__ q, float* __restrict__ saq) {
    int row = blockIdx.x, t = threadIdx.x;
    __shared__ float red[128];
    const size_t base = (size_t)row * COLS;
    constexpr int J = COLS / 128;
    float v[J]; float mx = 0.f;
#pragma unroll
    for (int j = 0; j < J; j++) {
        int c = t + j * 128;
        v[j] = __bfloat162float(xh[base + c]) + __bfloat162float(xl[base + c]);
        mx = fmaxf(mx, fabsf(v[j]));
    }
    red[t] = mx; __syncthreads();
    for (int s = 64; s > 0; s >>= 1) { if (t < s) red[t] = fmaxf(red[t], red[t + s]); __syncthreads(); }
    float s = red[0];
    float inv = s > 1e-30f ? 2047.f / s : 0.f;
#pragma unroll
    for (int j = 0; j < J; j++) {
        int c = t + j * 128;
        q[base + c] = __float2half(v[j] * inv);
    }
    if (t == 0) saq[row] = s > 1e-30f ? s / 2047.f : 0.f;
}

// pooled*invcnt rows -> row-scaled fp16 + scale. 512 cols, 128 threads.
__global__ void quant_pooled_f16(const float* __restrict__ pooled, const float* __restrict__ invc,
                                 __half* __restrict__ q, float* __restrict__ spl) {
    int row = blockIdx.x, t = threadIdx.x;
    __shared__ float red[128];
    const size_t base = (size_t)row * HH;
    float ic = invc[row];
    float v[4]; float mx = 0.f;
#pragma unroll
    for (int j = 0; j < 4; j++) {
        int c = t + j * 128;
        v[j] = pooled[base + c] * ic;
        mx = fmaxf(mx, fabsf(v[j]));
    }
    red[t] = mx; __syncthreads();
    for (int s = 64; s > 0; s >>= 1) { if (t < s) red[t] = fmaxf(red[t], red[t + s]); __syncthreads(); }
    float s = red[0];
    float inv = s > 1e-30f ? 2047.f / s : 0.f;
#pragma unroll
    for (int j = 0; j < 4; j++) {
        int c = t + j * 128;
        q[base + c] = __float2half(v[j] * inv);
    }
    if (t == 0) spl[row] = s > 1e-30f ? s / 2047.f : 0.f;
}

// ================= HMMA GEMM =================
// TERMS: 3 = Ah*Bh + Ah*Bl + Al*Bh.  2 = Ah*Bh + Ah*Bl.  1 = Ah*Bh.
// USEF16: fp16 mma. DEQ: OUT1/OUT5 dequant acc*Af[row]*inv[col] before bias.
// OUT3+USEF16 dequants acc*Us[row]*Uo[col] (legacy slots).
#define BN   128
#define BK   32

#define CP_ASYNC16(dst, src, sz) \
    asm volatile("cp.async.cg.shared.global [%0], [%1], 16, %2;" :: "r"(dst), "l"(src), "r"(sz))
#define CP_COMMIT() asm volatile("cp.async.commit_group;")
#define LDSM_X4(R0,R1,R2,R3,ADDR) \
    asm volatile("ldmatrix.sync.aligned.m8n8.x4.shared.b16 {%0,%1,%2,%3}, [%4];" \
                 : "=r"(R0),"=r"(R1),"=r"(R2),"=r"(R3) : "r"(ADDR))
#define MMA16816(C,A0,A1,A2,A3,B0,B1) \
    asm volatile("mma.sync.aligned.m16n8k16.row.col.f32.bf16.bf16.f32 " \
                 "{%0,%1,%2,%3},{%4,%5,%6,%7},{%8,%9},{%0,%1,%2,%3};" \
                 : "+f"((C)[0]),"+f"((C)[1]),"+f"((C)[2]),"+f"((C)[3]) \
                 : "r"(A0),"r"(A1),"r"(A2),"r"(A3),"r"(B0),"r"(B1))
#define MMA16816F(C,A0,A1,A2,A3,B0,B1) \
    asm volatile("mma.sync.aligned.m16n8k16.row.col.f32.f16.f16.f32 " \
                 "{%0,%1,%2,%3},{%4,%5,%6,%7},{%8,%9},{%0,%1,%2,%3};" \
                 : "+f"((C)[0]),"+f"((C)[1]),"+f"((C)[2]),"+f"((C)[3]) \
                 : "r"(A0),"r"(A1),"r"(A2),"r"(A3),"r"(B0),"r"(B1))
#define STS128(ADDR,A,B,C,D) \
    asm volatile("st.shared.v4.b32 [%0], {%1,%2,%3,%4};" :: "r"(ADDR),"r"(A),"r"(B),"r"(C),"r"(D))
#define REDV4(PTR,X,Y,Z,W) \
    asm volatile("red.global.add.v4.f32 [%0], {%1,%2,%3,%4};" :: "l"(PTR),"f"(X),"f"(Y),"f"(Z),"f"(W) : "memory")

__device__ __forceinline__ uint32_t sw_off(int row, int c) {
    return (uint32_t)(row * 64 + (((c ^ (row & 3))) << 4));
}

template <int TBM, int TERMS>
__device__ __forceinline__ void ld_stage(
    uint32_t st,
    const bf16* __restrict__ Ah, const bf16* __restrict__ Al,
    const bf16* __restrict__ Bh, const bf16* __restrict__ Bl, int Bstride,
    int bm, int bn, int k0, int M, int K, int tid)
{
    constexpr uint32_t OFF_AL = TBM * 64;
    constexpr uint32_t OFF_BH = TBM * 128;
    constexpr uint32_t OFF_BL = TBM * 128 + 8192;
#pragma unroll
    for (int lin = tid; lin < TBM * 4; lin += 256) {
        int row = lin >> 2;
        int c   = lin & 3;
        uint32_t so = sw_off(row, c);
        int gr = bm + row;
        bool ok = gr < M;
        uint32_t sz = ok ? 16u : 0u;
        size_t srow = ok ? (size_t)gr : 0;
        const char* sh = (const char*)(Ah + srow * K + k0 + c * 8);
        CP_ASYNC16(st + so, sh, sz);
        if (TERMS == 3) {
            const char* sl = (const char*)(Al + srow * K + k0 + c * 8);
            CP_ASYNC16(st + OFF_AL + so, sl, sz);
        }
    }
#pragma unroll
    for (int lin = tid; lin < 512; lin += 256) {
        int row = lin >> 2;
        int c   = lin & 3;
        uint32_t so = sw_off(row, c);
        int gr = bn + row;
        const char* sh = (const char*)(Bh + (size_t)gr * Bstride + k0 + c * 8);
        CP_ASYNC16(st + OFF_BH + so, sh, 16u);
        if (TERMS >= 2) {
            const char* sl = (const char*)(Bl + (size_t)gr * Bstride + k0 + c * 8);
            CP_ASYNC16(st + OFF_BL + so, sl, 16u);
        }
    }
}

template <int OUT_MODE, int TBM, int TERMS, int USEF16, int DEQ>
__global__ void __launch_bounds__(256)
gemm_hmma(const bf16* __restrict__ Ah, const bf16* __restrict__ Al,
          const float* __restrict__ Af, const float* __restrict__ inv,   // DEQ scales: Af=row, inv=col
          const int* __restrict__ trip,
          const bf16* __restrict__ Bh, const bf16* __restrict__ Bl, int Bstride,
          const float* __restrict__ bias,
          const float* __restrict__ Us, const float* __restrict__ Uo,
          float* __restrict__ Cf,
          bf16* __restrict__ Ch, bf16* __restrict__ Cl,
          float* __restrict__ pooled,
          bf16* __restrict__ Pvh, bf16* __restrict__ Pvl,
          int zBoff, int zCoff,
          int M, int N, int K)
{
    constexpr uint32_t OFF_AL = TBM * 64;
    constexpr uint32_t OFF_BH = TBM * 128;
    constexpr uint32_t OFF_BL = TBM * 128 + 8192;
    constexpr uint32_t STAGE  = TBM * 128 + 16384;
    constexpr int NWM = (TBM == 128) ? 2 : 1;
    constexpr int NT  = (TBM == 128) ? 4 : 2;

    {
        size_t zb = (size_t)blockIdx.z * (size_t)zBoff;
        Bh += zb; Bl += zb;
        if (Cf) Cf += (size_t)blockIdx.z * (size_t)zCoff;
    }

    extern __shared__ char smem[];
    uint32_t sb = smem_u32(smem);

    int tid = threadIdx.x;
    int wid = tid >> 5, lane = tid & 31;
    int wm = (wid % NWM) * 64;
    int wn = (wid / NWM) * (NT * 8);
    int bm = blockIdx.y * TBM;
    int bn = blockIdx.x * BN;
    const int NC = K / BK;

    float acc[4][NT][4];
#pragma unroll
    for (int i = 0; i < 4; i++)
#pragma unroll
        for (int j = 0; j < NT; j++)
#pragma unroll
            for (int r = 0; r < 4; r++) acc[i][j][r] = 0.f;

    int lrow8 = (lane & 7) + ((lane >> 3) & 1) * 8;
    int lchunk = (lane >> 4);

    ld_stage<TBM, TERMS>(sb, Ah, Al, Bh, Bl, Bstride, bm, bn, 0, M, K, tid);
    CP_COMMIT();

    for (int kc = 0; kc < NC; kc++) {
        if (kc + 1 < NC) {
            ld_stage<TBM, TERMS>(sb + ((kc + 1) & 1) * STAGE, Ah, Al, Bh, Bl, Bstride,
                                 bm, bn, (kc + 1) * BK, M, K, tid);
            CP_COMMIT();
            asm volatile("cp.async.wait_group 1;");
        } else {
            asm volatile("cp.async.wait_group 0;");
        }
        __syncthreads();

        uint32_t sa = sb + (kc & 1) * STAGE;
#pragma unroll
        for (int ks = 0; ks < 2; ks++) {
            int c0 = ks * 2;
            uint32_t ah[4][4], al[4][4], bh[NT][2], bl[NT][2];
#pragma unroll
            for (int mt = 0; mt < 4; mt++) {
                int row = wm + mt * 16 + lrow8;
                LDSM_X4(ah[mt][0], ah[mt][1], ah[mt][2], ah[mt][3], sa + sw_off(row, c0 + lchunk));
            }
#pragma unroll
            for (int np = 0; np < NT / 2; np++) {
                int row = wn + np * 16 + lrow8;
                uint32_t r0, r1, r2, r3;
                LDSM_X4(r0, r1, r2, r3, sa + OFF_BH + sw_off(row, c0 + lchunk));
                bh[2*np][0] = r0; bh[2*np+1][0] = r1;
                bh[2*np][1] = r2; bh[2*np+1][1] = r3;
            }
#pragma unroll
            for (int mt = 0; mt < 4; mt++)
#pragma unroll
                for (int nt = 0; nt < NT; nt++) {
                    if (USEF16) MMA16816F(acc[mt][nt], ah[mt][0], ah[mt][1], ah[mt][2], ah[mt][3],
                                          bh[nt][0], bh[nt][1]);
                    else        MMA16816(acc[mt][nt], ah[mt][0], ah[mt][1], ah[mt][2], ah[mt][3],
                                         bh[nt][0], bh[nt][1]);
                }
            if (TERMS >= 2) {
#pragma unroll
                for (int np = 0; np < NT / 2; np++) {
                    int row = wn + np * 16 + lrow8;
                    uint32_t r0, r1, r2, r3;
                    LDSM_X4(r0, r1, r2, r3, sa + OFF_BL + sw_off(row, c0 + lchunk));
                    bl[2*np][0] = r0; bl[2*np+1][0] = r1;
                    bl[2*np][1] = r2; bl[2*np+1][1] = r3;
                }
#pragma unroll
                for (int mt = 0; mt < 4; mt++)
#pragma unroll
                    for (int nt = 0; nt < NT; nt++) {
                        if (USEF16) MMA16816F(acc[mt][nt], ah[mt][0], ah[mt][1], ah[mt][2], ah[mt][3],
                                              bl[nt][0], bl[nt][1]);
                        else        MMA16816(acc[mt][nt], ah[mt][0], ah[mt][1], ah[mt][2], ah[mt][3],
                                             bl[nt][0], bl[nt][1]);
                    }
            }
            if (TERMS == 3) {
#pragma unroll
                for (int mt = 0; mt < 4; mt++) {
                    int row = wm + mt * 16 + lrow8;
                    LDSM_X4(al[mt][0], al[mt][1], al[mt][2], al[mt][3], sa + OFF_AL + sw_off(row, c0 + lchunk));
                }
#pragma unroll
                for (int mt = 0; mt < 4; mt++)
#pragma unroll
                    for (int nt = 0; nt < NT; nt++) {
                        if (USEF16) MMA16816F(acc[mt][nt], al[mt][0], al[mt][1], al[mt][2], al[mt][3],
                                              bh[nt][0], bh[nt][1]);
                        else        MMA16816(acc[mt][nt], al[mt][0], al[mt][1], al[mt][2], al[mt][3],
                                             bh[nt][0], bh[nt][1]);
                    }
            }
        }
        __syncthreads();
    }

    int r = lane >> 2, q = lane & 3;

    if (OUT_MODE == 3) {
#pragma unroll
        for (int mt = 0; mt < 4; mt++) {
            int lr0 = wm + mt * 16 + r;
            float sa0 = 1.f, sa1 = 1.f;
            if (USEF16) {
                sa0 = __ldg(&Us[bm + lr0]);
                sa1 = __ldg(&Us[bm + lr0 + 8]);
            }
#pragma unroll
            for (int nt = 0; nt < NT; nt++) {
                int lc = wn + nt * 8 + q * 2;
                int col = bn + lc;
                float b0 = bias[col], b1 = bias[col + 1];
                float sb0 = 1.f, sb1 = 1.f;
                if (USEF16) { sb0 = __ldg(&Uo[col]); sb1 = __ldg(&Uo[col + 1]); }
                float2 v0 = make_float2(fmaxf(acc[mt][nt][0] * sa0 * sb0 + b0, 0.f),
                                        fmaxf(acc[mt][nt][1] * sa0 * sb1 + b1, 0.f));
                float2 v1 = make_float2(fmaxf(acc[mt][nt][2] * sa1 * sb0 + b0, 0.f),
                                        fmaxf(acc[mt][nt][3] * sa1 * sb1 + b1, 0.f));
                *reinterpret_cast<float2*>(smem + ((size_t)lr0 * 128 + lc) * 4) = v0;
                *reinterpret_cast<float2*>(smem + ((size_t)(lr0 + 8) * 128 + lc) * 4) = v1;
            }
        }
        __syncthreads();
        int row = tid >> 1;
        int half = (tid & 1) * 64;
        int gr = bm + row;
        if (gr < M) {
            const float* srow = reinterpret_cast<const float*>(smem) + (size_t)row * 128 + half;
            if (bn == 512) {
#pragma unroll
                for (int i = 0; i < 16; i++) {
                    float4 v = *reinterpret_cast<const float4*>(srow + i * 4);
                    bf16 h0,l0,h1,l1,h2,l2,h3,l3;
                    f32split(v.x,h0,l0); f32split(v.y,h1,l1); f32split(v.z,h2,l2); f32split(v.w,h3,l3);
                    uint2 hp = make_uint2(bfpack(h0,h1), bfpack(h2,h3));
                    uint2 lp = make_uint2(bfpack(l0,l1), bfpack(l2,l3));
                    int pc = half + i * 4;
                    *reinterpret_cast<uint2*>(Pvh + (size_t)gr * DD + pc) = hp;
                    *reinterpret_cast<uint2*>(Pvl + (size_t)gr * DD + pc) = lp;
                }
            } else {
                int obj = __ldg(&trip[3 * gr + ((bn < 512) ? 0 : 2)]);
                float* dst = pooled + (size_t)obj * HH + ((bn < 512) ? bn : bn - 640) + half;
#pragma unroll
                for (int i = 0; i < 16; i++) {
                    float4 v = *reinterpret_cast<const float4*>(srow + i * 4);
                    REDV4(dst + i * 4, v.x, v.y, v.z, v.w);
                }
            }
        }
        return;
    }

#pragma unroll
    for (int mt = 0; mt < 4; mt++) {
        int row0 = bm + wm + mt * 16 + r;
        int row1 = row0 + 8;
        int s0 = 0, o0 = 0, s1 = 0, o1 = 0;
        if (OUT_MODE == 5) {
            if (row0 < M) { s0 = __ldg(&trip[3 * row0]); o0 = __ldg(&trip[3 * row0 + 2]); }
            if (row1 < M) { s1 = __ldg(&trip[3 * row1]); o1 = __ldg(&trip[3 * row1 + 2]); }
        }
        float sa0 = 1.f, sa1 = 1.f;
        if (DEQ) {
            if (row0 < M) sa0 = __ldg(&Af[row0]);
            if (row1 < M) sa1 = __ldg(&Af[row1]);
        }
#pragma unroll
        for (int nt = 0; nt < NT; nt++) {
            int col = bn + wn + nt * 8 + q * 2;
            if (OUT_MODE == 0) {
                if (row0 < M)
                    *reinterpret_cast<float2*>(Cf + (size_t)row0 * N + col) = make_float2(acc[mt][nt][0], acc[mt][nt][1]);
                if (row1 < M)
                    *reinterpret_cast<float2*>(Cf + (size_t)row1 * N + col) = make_float2(acc[mt][nt][2], acc[mt][nt][3]);
                continue;
            }
            float b0 = bias[col], b1 = bias[col + 1];
            float sb0 = 1.f, sb1 = 1.f;
            if (DEQ) { sb0 = __ldg(&inv[col]); sb1 = __ldg(&inv[col + 1]); }
            float a00 = acc[mt][nt][0] * sa0 * sb0 + b0, a01 = acc[mt][nt][1] * sa0 * sb1 + b1;
            float a10 = acc[mt][nt][2] * sa1 * sb0 + b0, a11 = acc[mt][nt][3] * sa1 * sb1 + b1;
            if (OUT_MODE == 5) {
                if (row0 < M) {
                    float2 us = *reinterpret_cast<const float2*>(Us + (size_t)s0 * HH + col);
                    float2 uo = *reinterpret_cast<const float2*>(Uo + (size_t)o0 * HH + col);
                    a00 += us.x + uo.x; a01 += us.y + uo.y;
                }
                if (row1 < M) {
                    float2 us = *reinterpret_cast<const float2*>(Us + (size_t)s1 * HH + col);
                    float2 uo = *reinterpret_cast<const float2*>(Uo + (size_t)o1 * HH + col);
                    a10 += us.x + uo.x; a11 += us.y + uo.y;
                }
            }
            float v00 = fmaxf(a00, 0.f), v01 = fmaxf(a01, 0.f);
            float v10 = fmaxf(a10, 0.f), v11 = fmaxf(a11, 0.f);
            bf16 h0, l0, h1, l1;
            if (row0 < M) {
                if (OUT_MODE == 2)
                    *reinterpret_cast<float2*>(Cf + (size_t)row0 * N + col) = make_float2(v00, v01);
                f32split(v00, h0, l0); f32split(v01, h1, l1);
                *reinterpret_cast<uint32_t*>(Ch + (size_t)row0 * N + col) = bfpack(h0, h1);
                *reinterpret_cast<uint32_t*>(Cl + (size_t)row0 * N + col) = bfpack(l0, l1);
            }
            if (row1 < M) {
                if (OUT_MODE == 2)
                    *reinterpret_cast<float2*>(Cf + (size_t)row1 * N + col) = make_float2(v10, v11);
                f32split(v10, h0, l0); f32split(v11, h1, l1);
                *reinterpret_cast<uint32_t*>(Ch + (size_t)row1 * N + col) = bfpack(h0, h1);
                *reinterpret_cast<uint32_t*>(Cl + (size_t)row1 * N + col) = bfpack(l0, l1);
            }
        }
    }
}

// ================= attention epilogue =================
__global__ void scores_kernel(const float* __restrict__ ov,
                              const float* __restrict__ att_w,
                              const float* __restrict__ att_b,
                              float* __restrict__ scores) {
    int gid = blockIdx.x * blockDim.x + threadIdx.x;
    int w = gid >> 5, lane = gid & 31;
    if (w >= NUM_O) return;
    float sum = 0.f;
#pragma unroll
    for (int d = lane; d < DD; d += 32) sum += ov[(size_t)w * DD + d] * att_w[d];
#pragma unroll
    for (int off = 16; off; off >>= 1) sum += __shfl_down_sync(0xffffffff, sum, off);
    if (lane == 0) scores[w] = sum + att_b[0];
}

__global__ void segment_kernel(const float* __restrict__ scores,
                               const int* __restrict__ img,
                               const float* __restrict__ ov,
                               float* __restrict__ gvec) {
    int g = blockIdx.x, t = threadIdx.x;
    __shared__ float sred[128];
    __shared__ int ired[128];

    float m = -3.4e38f;
    int lo = NUM_O, hi = -1;
    for (int i = t; i < NUM_O; i += 128) {
        if (img[i] == g) {
            m = fmaxf(m, scores[i]);
            lo = min(lo, i);
            hi = max(hi, i);
        }
    }
    sred[t] = m; __syncthreads();
    for (int s = 64; s > 0; s >>= 1) { if (t < s) sred[t] = fmaxf(sred[t], sred[t + s]); __syncthreads(); }
    m = sred[0]; __syncthreads();
    ired[t] = lo; __syncthreads();
    for (int s = 64; s > 0; s >>= 1) { if (t < s) ired[t] = min(ired[t], ired[t + s]); __syncthreads(); }
    lo = ired[0]; __syncthreads();
    ired[t] = hi; __syncthreads();
    for (int s = 64; s > 0; s >>= 1) { if (t < s) ired[t] = max(ired[t], ired[t + s]); __syncthreads(); }
    hi = ired[0]; __syncthreads();

    float z = 0.f;
    for (int i = lo + t; i <= hi; i += 128)
        if (img[i] == g) z += expf(scores[i] - m);
    sred[t] = z; __syncthreads();
    for (int s = 64; s > 0; s >>= 1) { if (t < s) sred[t] += sred[t + s]; __syncthreads(); }
    z = sred[0];
    float invz = 1.f / z;

    float acc = 0.f;
    for (int i = lo; i <= hi; i++) {
        if (img[i] == g)
            acc += expf(scores[i] - m) * invz * ov[(size_t)i * DD + t];
    }
    gvec[g * DD + t] = acc;
}

__global__ void concat_kernel(const float* __restrict__ ov,
                              const float* __restrict__ gvec,
                              const int* __restrict__ img,
                              float* __restrict__ out) {
    int i = blockIdx.x, t = threadIdx.x;
    if (t < DD) out[(size_t)i * 256 + t] = ov[(size_t)i * DD + t];
    else        out[(size_t)i * 256 + t] = gvec[img[i] * DD + (t - DD)];
}

// ================= launch =================
extern "C" void kernel_launch(void* const* d_in, const int* in_sizes, int n_in,
                              void* d_out, int out_size) {
    const int*   objs     = (const int*)d_in[0];
    const int*   trip     = (const int*)d_in[1];
    const int*   img      = (const int*)d_in[2];
    const float* obj_emb  = (const float*)d_in[3];
    const float* pred_emb = (const float*)d_in[4];
    const float* n1w1     = (const float*)d_in[5];
    const float* n1b1     = (const float*)d_in[6];
    const float* n1w2     = (const float*)d_in[7];
    const float* n1b2     = (const float*)d_in[8];
    const float* n2w1     = (const float*)d_in[9];
    const float* n2b1     = (const float*)d_in[10];
    const float* n2w2     = (const float*)d_in[11];
    const float* n2b2     = (const float*)d_in[12];
    const float* att_w    = (const float*)d_in[13];
    const float* att_b    = (const float*)d_in[14];
    float* out = (float*)d_out;

    float *ov, *pooled, *counts, *inv, *scores, *gvec, *U;
    float *saq, *spq, *spl, *sbq2, *sbq1p, *sbq3;
    bf16 *ovh, *ovl, *pvh, *pvl, *hh, *hl, *h2h, *h2l;
    bf16 *w1h, *w1l, *w4h, *w4l;
    __half *h16, *pv16, *p16, *w2h16, *w1p16, *w316;
    cudaGetSymbolAddress((void**)&ov,     g_ov);
    cudaGetSymbolAddress((void**)&pooled, g_pooled);
    cudaGetSymbolAddress((void**)&counts, g_counts);
    cudaGetSymbolAddress((void**)&inv,    g_invcnt);
    cudaGetSymbolAddress((void**)&scores, g_scores);
    cudaGetSymbolAddress((void**)&gvec,   g_gvec);
    cudaGetSymbolAddress((void**)&U,      g_U);
    cudaGetSymbolAddress((void**)&saq,    g_saq);
    cudaGetSymbolAddress((void**)&spq,    g_spq);
    cudaGetSymbolAddress((void**)&spl,    g_spl);
    cudaGetSymbolAddress((void**)&sbq2,   g_sbq2);
    cudaGetSymbolAddress((void**)&sbq1p,  g_sbq1p);
    cudaGetSymbolAddress((void**)&sbq3,   g_sbq3);
    cudaGetSymbolAddress((void**)&ovh, g_ovh); cudaGetSymbolAddress((void**)&ovl, g_ovl);
    cudaGetSymbolAddress((void**)&pvh, g_pvh); cudaGetSymbolAddress((void**)&pvl, g_pvl);
    cudaGetSymbolAddress((void**)&hh,  g_hh);  cudaGetSymbolAddress((void**)&hl,  g_hl);
    cudaGetSymbolAddress((void**)&h2h, g_h2h); cudaGetSymbolAddress((void**)&h2l, g_h2l);
    cudaGetSymbolAddress((void**)&h16, g_h16);
    cudaGetSymbolAddress((void**)&pv16, g_pv16);
    cudaGetSymbolAddress((void**)&p16,  g_p16);
    cudaGetSymbolAddress((void**)&w1h, g_w1h); cudaGetSymbolAddress((void**)&w1l, g_w1l);
    cudaGetSymbolAddress((void**)&w2h16, g_w2h16);
    cudaGetSymbolAddress((void**)&w1p16, g_w1p16);
    cudaGetSymbolAddress((void**)&w316,  g_w316);
    cudaGetSymbolAddress((void**)&w4h, g_w4h); cudaGetSymbolAddress((void**)&w4l, g_w4l);

    float* Us = U;
    float* Uo = U + (size_t)NUM_O * HH;

    const int SMEM128 = 65536;
    const int SMEM64  = 49152;
    const int SMEMWQ  = 32 * (HH + 2) * 4;
    cudaFuncSetAttribute(gemm_hmma<0,64,3,0,0>,  cudaFuncAttributeMaxDynamicSharedMemorySize, SMEM64);
    cudaFuncSetAttribute(gemm_hmma<5,128,1,1,1>, cudaFuncAttributeMaxDynamicSharedMemorySize, SMEM128);
    cudaFuncSetAttribute(gemm_hmma<3,128,1,1,0>, cudaFuncAttributeMaxDynamicSharedMemorySize, SMEM128);
    cudaFuncSetAttribute(gemm_hmma<1,64,1,1,1>,  cudaFuncAttributeMaxDynamicSharedMemorySize, SMEM64);
    cudaFuncSetAttribute(gemm_hmma<2,64,3,0,0>,  cudaFuncAttributeMaxDynamicSharedMemorySize, SMEM64);
    cudaFuncSetAttribute(wquant_f16,             cudaFuncAttributeMaxDynamicSharedMemorySize, SMEMWQ);

    const int mT   = (NUM_T + 127) / 128;   // 157
    const int mO64 = (NUM_O + 63) / 64;     // 79

    // ---- prologue (index 3 = merged U GEMM, profiled by ncu) ----
    wtrans_split<<<dim3(HH/32, K1/32, LL), dim3(32,32)>>>(n1w1, w1h, w1l, K1, HH);    // 0
    gather_init<<<dim3(NUM_T, 2), DD>>>(obj_emb, pred_emb, objs, trip,
                                        ovh, ovl, pvh, pvl);                         // 1
    wquant_f16<<<dim3(N2/32, LL), 256, SMEMWQ>>>(n1w2, w2h16, sbq2, HH, N2, HH*N2);   // 2

    gemm_hmma<0,64,3,0,0><<<dim3(HH/BN, mO64, 2), 256, SMEM64>>>(                     // 3 (profiled)
        ovh, ovl, nullptr, nullptr, nullptr,
        w1h, w1l, K1, nullptr, nullptr, nullptr,
        U, nullptr, nullptr, nullptr, nullptr, nullptr,
        2*DD, NUM_O*HH, NUM_O, HH, DD);

    wquant_f16<<<dim3(HH/32, LL), 256, SMEMWQ>>>(n1w1 + (size_t)DD*HH, w1p16, sbq1p,
                                                 DD, HH, K1*HH);                      // 4
    wquant_f16<<<dim3(HH/32, LL), 256, SMEMWQ>>>(n2w1, w316, sbq3, HH, HH, HH*HH);    // 5
    zero_kernel<<<(NUM_O + 255) / 256, 256>>>(counts, NUM_O);                         // 6
    count_kernel<<<(NUM_T + 255) / 256, 256>>>(trip, counts);                         // 7
    inv_kernel<<<(NUM_O + 255) / 256, 256>>>(counts, inv);                            // 8
    wtrans_split<<<dim3(DD/32, HH/32, LL), dim3(32,32)>>>(n2w2, w4h, w4l, HH, DD);    // 9

    for (int l = 0; l < LL; l++) {
        if (l > 0) {
            gemm_hmma<0,64,3,0,0><<<dim3(HH/BN, mO64, 2), 256, SMEM64>>>(
                ovh, ovl, nullptr, nullptr, nullptr,
                w1h + (size_t)l*HH*K1, w1l + (size_t)l*HH*K1, K1, nullptr, nullptr, nullptr,
                U, nullptr, nullptr, nullptr, nullptr, nullptr,
                2*DD, NUM_O*HH, NUM_O, HH, DD);
        }

        // quantize pv rows to fp16
        quant_rows_f16<DD><<<NUM_T, 128>>>(pvh, pvl, pv16, spq);

        // pv GEMM: fp16 1-term row-scaled + dequant + gather-add epilogue
        gemm_hmma<5,128,1,1,1><<<dim3(HH/BN, mT), 256, SMEM128>>>(
            (const bf16*)pv16, nullptr, spq, sbq1p + (size_t)l*HH, trip,
            (const bf16*)(w1p16 + (size_t)l*HH*DD), nullptr, DD,
            n1b1 + (size_t)l*HH, Us, Uo,
            nullptr, hh, hl, nullptr, nullptr, nullptr,
            0, 0, NUM_T, HH, DD);

        // quantize h rows to fp16
        quant_rows_f16<HH><<<NUM_T, 128>>>(hh, hl, h16, saq);

        zero_kernel<<<(NUM_O * HH + 255) / 256, 256>>>(pooled, NUM_O * HH);

        // GEMM2: fp16 1-term row-scaled, dequant + fused scatter
        gemm_hmma<3,128,1,1,0><<<dim3(N2/BN, mT), 256, SMEM128>>>(
            (const bf16*)h16, nullptr, nullptr, nullptr, trip,
            (const bf16*)(w2h16 + (size_t)l*N2*HH), nullptr, HH,
            n1b2 + (size_t)l*N2,
            saq, sbq2 + (size_t)l*N2,
            nullptr, nullptr, nullptr, pooled, pvh, pvl,
            0, 0, NUM_T, N2, HH);

        // quantize pooled*inv rows to fp16
        quant_pooled_f16<<<NUM_O, 128>>>(pooled, inv, p16, spl);

        // GEMM3: fp16 1-term row-scaled + dequant
        gemm_hmma<1,64,1,1,1><<<dim3(HH/BN, mO64), 256, SMEM64>>>(
            (const bf16*)p16, nullptr, spl, sbq3 + (size_t)l*HH, nullptr,
            (const bf16*)(w316 + (size_t)l*HH*HH), nullptr, HH,
            n2b1 + (size_t)l*HH, nullptr, nullptr,
            nullptr, h2h, h2l, nullptr, nullptr, nullptr,
            0, 0, NUM_O, HH, HH);

        // GEMM4: ov fp32 + bf16 pair (3-term bf16)
        gemm_hmma<2,64,3,0,0><<<dim3(DD/BN, mO64), 256, SMEM64>>>(
            h2h, h2l, nullptr, nullptr, nullptr,
            w4h + (size_t)l*DD*HH, w4l + (size_t)l*DD*HH, HH, n2b2 + (size_t)l*DD,
            nullptr, nullptr,
            ov, ovh, ovl, nullptr, nullptr, nullptr,
            0, 0, NUM_O, DD, HH);
    }

    scores_kernel<<<(NUM_O * 32 + 255) / 256, 256>>>(ov, att_w, att_b, scores);
    segment_kernel<<<GG, 128>>>(scores, img, ov, gvec);
    concat_kernel<<<NUM_O, 256>>>(ov, gvec, img, out);
}

// round 15
// speedup vs baseline: 4.9950x; 1.0325x over previous
#include <cuda_runtime.h>
#include <cuda_bf16.h>
#include <cuda_fp16.h>
#include <math.h>
#include <stdint.h>

#define NUM_O   5000
#define NUM_T   20000
#define DD      128
#define HH      512
#define GG      64
#define LL      5
#define K1      (3*DD)        // 384
#define N2      (2*HH+DD)     // 1152

typedef __nv_bfloat16 bf16;

// ================= scratch =================
__device__ float g_ov    [NUM_O * DD];
__device__ float g_pooled[NUM_O * HH];
__device__ float g_counts[NUM_O];
__device__ float g_invcnt[NUM_O];
__device__ float g_scores[NUM_O];
__device__ float g_gvec  [GG * DD];
__device__ float g_U     [2 * NUM_O * HH];   // [Us | Uo]

__device__ bf16   g_ovh[NUM_O * DD], g_ovl[NUM_O * DD];
__device__ bf16   g_hh [NUM_T * HH], g_hl [NUM_T * HH];
__device__ bf16   g_h2h[NUM_O * HH], g_h2l[NUM_O * HH];

// row-scaled fp16 operands
__device__ __half g_h16[NUM_T * HH];
__device__ float  g_saq[20096];
__device__ __half g_pv16[NUM_T * DD];
__device__ float  g_spq[20096];
__device__ __half g_p16[NUM_O * HH];
__device__ float  g_spl[5120];
__device__ __half g_w2h16[LL * N2 * HH];
__device__ float  g_sbq2[LL * N2];
__device__ __half g_w1p16[LL * HH * DD];
__device__ float  g_sbq1p[LL * HH];
__device__ __half g_w316[LL * HH * HH];
__device__ float  g_sbq3[LL * HH];

__device__ bf16   g_w1h[LL * HH * K1], g_w1l[LL * HH * K1];
__device__ bf16   g_w4h[LL * DD * HH], g_w4l[LL * DD * HH];

__device__ __forceinline__ void f32split(float v, bf16& h, bf16& l) {
    h = __float2bfloat16(v);
    l = __float2bfloat16(v - __bfloat162float(h));
}
__device__ __forceinline__ uint32_t bfpack(bf16 a, bf16 b) {
    __nv_bfloat162 t; t.x = a; t.y = b;
    return *reinterpret_cast<uint32_t*>(&t);
}
__device__ __forceinline__ uint32_t smem_u32(const void* p) {
    uint32_t a;
    asm("{ .reg .u64 t; cvta.to.shared.u64 t, %1; cvt.u32.u64 %0, t; }" : "=r"(a) : "l"(p));
    return a;
}

// ================= glue =================
__global__ void zero_kernel(float* p, int n) {
    int i = blockIdx.x * blockDim.x + threadIdx.x;
    if (i < n) p[i] = 0.f;
}
// blockIdx.y==0: ov gather (bf16 pair). ==1: pv gather -> row-scaled fp16 + spq.
__global__ void gather_init(const float* __restrict__ obj_emb,
                            const float* __restrict__ pred_emb,
                            const int* __restrict__ objs,
                            const int* __restrict__ trip,
                            bf16* __restrict__ ovh, bf16* __restrict__ ovl,
                            __half* __restrict__ pv16, float* __restrict__ spq) {
    int i = blockIdx.x, d = threadIdx.x;
    if (blockIdx.y == 0) {
        if (i < NUM_O) {
            float v = obj_emb[objs[i] * DD + d];
            bf16 h, l; f32split(v, h, l);
            ovh[i * DD + d] = h; ovl[i * DD + d] = l;
        }
    } else {
        __shared__ float red[128];
        int p = trip[3 * i + 1];
        float v = pred_emb[p * DD + d];
        red[d] = fabsf(v); __syncthreads();
        for (int s = 64; s > 0; s >>= 1) { if (d < s) red[d] = fmaxf(red[d], red[d + s]); __syncthreads(); }
        float mx = red[0];
        float inv = mx > 1e-30f ? 2047.f / mx : 0.f;
        pv16[i * DD + d] = __float2half(v * inv);
        if (d == 0) spq[i] = mx > 1e-30f ? mx / 2047.f : 0.f;
    }
}
__global__ void count_kernel(const int* __restrict__ trip, float* __restrict__ counts) {
    int i = blockIdx.x * blockDim.x + threadIdx.x;
    if (i < NUM_T) {
        atomicAdd(&counts[trip[3 * i + 0]], 1.f);
        atomicAdd(&counts[trip[3 * i + 2]], 1.f);
    }
}
__global__ void inv_kernel(const float* __restrict__ counts, float* __restrict__ inv) {
    int i = blockIdx.x * blockDim.x + threadIdx.x;
    if (i < NUM_O) inv[i] = 1.f / fmaxf(counts[i], 1.f);
}
__global__ void wtrans_split(const float* __restrict__ w,
                             bf16* __restrict__ oh,
                             bf16* __restrict__ ol, int K, int N) {
    __shared__ float tile[32][33];
    int l = blockIdx.z;
    int k0 = blockIdx.y * 32, n0 = blockIdx.x * 32;
    const float* wl = w + (size_t)l * K * N;
    tile[threadIdx.y][threadIdx.x] = wl[(size_t)(k0 + threadIdx.y) * N + n0 + threadIdx.x];
    __syncthreads();
    int on = n0 + threadIdx.y, ok = k0 + threadIdx.x;
    float v = tile[threadIdx.x][threadIdx.y];
    bf16 h, lo; f32split(v, h, lo);
    size_t idx = ((size_t)l * N + on) * K + ok;
    oh[idx] = h; ol[idx] = lo;
}

// w [L(lstride), K, N] slice -> row(n)-scaled fp16 [L,N,K] + sbq[L,N]
__global__ void wquant_f16(const float* __restrict__ w,
                           __half* __restrict__ qbh,
                           float* __restrict__ sbq, int K, int N, int lstride) {
    extern __shared__ float ws[];
    int l = blockIdx.y;
    int n0 = blockIdx.x * 32;
    int tx = threadIdx.x & 31, ty = threadIdx.x >> 5;
    const float* wl = w + (size_t)l * lstride;
    for (int k = ty; k < K; k += 8)
        ws[tx * (K + 2) + k] = wl[(size_t)k * N + n0 + tx];
    __syncthreads();
    int lane = threadIdx.x & 31, w8 = threadIdx.x >> 5;
    for (int p = 0; p < 4; p++) {
        int nl = p * 8 + w8;
        float mx = 0.f;
        for (int k = lane; k < K; k += 32) mx = fmaxf(mx, fabsf(ws[nl * (K + 2) + k]));
#pragma unroll
        for (int off = 16; off; off >>= 1) mx = fmaxf(mx, __shfl_xor_sync(0xffffffff, mx, off));
        float inv = mx > 1e-30f ? 2047.f / mx : 0.f;
        for (int k = lane; k < K; k += 32) {
            size_t idx = ((size_t)l * N + n0 + nl) * K + k;
            qbh[idx] = __float2half(ws[nl * (K + 2) + k] * inv);
        }
        if (lane == 0) sbq[(size_t)l * N + n0 + nl] = mx > 1e-30f ? mx / 2047.f : 0.f;
    }
}

// bf16-pair rows -> row-scaled fp16 + scale. COLS elems/row, 128 threads.
template <int COLS>
__global__ void quant_rows_f16(const bf16* __restrict__ xh, const bf16* __restrict__ xl,
                               __half* __restrict__ q, float* __restrict__ saq) {
    int row = blockIdx.x, t = threadIdx.x;
    __shared__ float red[128];
    const size_t base = (size_t)row * COLS;
    constexpr int J = COLS / 128;
    float v[J]; float mx = 0.f;
#pragma unroll
    for (int j = 0; j < J; j++) {
        int c = t + j * 128;
        v[j] = __bfloat162float(xh[base + c]) + __bfloat162float(xl[base + c]);
        mx = fmaxf(mx, fabsf(v[j]));
    }
    red[t] = mx; __syncthreads();
    for (int s = 64; s > 0; s >>= 1) { if (t < s) red[t] = fmaxf(red[t], red[t + s]); __syncthreads(); }
    float s = red[0];
    float inv = s > 1e-30f ? 2047.f / s : 0.f;
#pragma unroll
    for (int j = 0; j < J; j++) {
        int c = t + j * 128;
        q[base + c] = __float2half(v[j] * inv);
    }
    if (t == 0) saq[row] = s > 1e-30f ? s / 2047.f : 0.f;
}

// pooled*invcnt rows -> row-scaled fp16 + scale. 512 cols, 128 threads.
__global__ void quant_pooled_f16(const float* __restrict__ pooled, const float* __restrict__ invc,
                                 __half* __restrict__ q, float* __restrict__ spl) {
    int row = blockIdx.x, t = threadIdx.x;
    __shared__ float red[128];
    const size_t base = (size_t)row * HH;
    float ic = invc[row];
    float v[4]; float mx = 0.f;
#pragma unroll
    for (int j = 0; j < 4; j++) {
        int c = t + j * 128;
        v[j] = pooled[base + c] * ic;
        mx = fmaxf(mx, fabsf(v[j]));
    }
    red[t] = mx; __syncthreads();
    for (int s = 64; s > 0; s >>= 1) { if (t < s) red[t] = fmaxf(red[t], red[t + s]); __syncthreads(); }
    float s = red[0];
    float inv = s > 1e-30f ? 2047.f / s : 0.f;
#pragma unroll
    for (int j = 0; j < 4; j++) {
        int c = t + j * 128;
        q[base + c] = __float2half(v[j] * inv);
    }
    if (t == 0) spl[row] = s > 1e-30f ? s / 2047.f : 0.f;
}

// ================= HMMA GEMM =================
// TERMS: 3 = Ah*Bh + Ah*Bl + Al*Bh.  2 = +Ah*Bl only.  1 = Ah*Bh.
// USEF16: fp16 mma. DEQ: dequant acc*Af[row]*inv[col] before bias (OUT1/OUT5).
// OUT3+USEF16 dequants acc*Us[row]*Uo[col]; pv block emits row-scaled fp16 into Pvh(=pv16)
// with scales into Pvl (reinterpreted float* spq).
#define BN   128
#define BK   32

#define CP_ASYNC16(dst, src, sz) \
    asm volatile("cp.async.cg.shared.global [%0], [%1], 16, %2;" :: "r"(dst), "l"(src), "r"(sz))
#define CP_COMMIT() asm volatile("cp.async.commit_group;")
#define LDSM_X4(R0,R1,R2,R3,ADDR) \
    asm volatile("ldmatrix.sync.aligned.m8n8.x4.shared.b16 {%0,%1,%2,%3}, [%4];" \
                 : "=r"(R0),"=r"(R1),"=r"(R2),"=r"(R3) : "r"(ADDR))
#define MMA16816(C,A0,A1,A2,A3,B0,B1) \
    asm volatile("mma.sync.aligned.m16n8k16.row.col.f32.bf16.bf16.f32 " \
                 "{%0,%1,%2,%3},{%4,%5,%6,%7},{%8,%9},{%0,%1,%2,%3};" \
                 : "+f"((C)[0]),"+f"((C)[1]),"+f"((C)[2]),"+f"((C)[3]) \
                 : "r"(A0),"r"(A1),"r"(A2),"r"(A3),"r"(B0),"r"(B1))
#define MMA16816F(C,A0,A1,A2,A3,B0,B1) \
    asm volatile("mma.sync.aligned.m16n8k16.row.col.f32.f16.f16.f32 " \
                 "{%0,%1,%2,%3},{%4,%5,%6,%7},{%8,%9},{%0,%1,%2,%3};" \
                 : "+f"((C)[0]),"+f"((C)[1]),"+f"((C)[2]),"+f"((C)[3]) \
                 : "r"(A0),"r"(A1),"r"(A2),"r"(A3),"r"(B0),"r"(B1))
#define STS128(ADDR,A,B,C,D) \
    asm volatile("st.shared.v4.b32 [%0], {%1,%2,%3,%4};" :: "r"(ADDR),"r"(A),"r"(B),"r"(C),"r"(D))
#define REDV4(PTR,X,Y,Z,W) \
    asm volatile("red.global.add.v4.f32 [%0], {%1,%2,%3,%4};" :: "l"(PTR),"f"(X),"f"(Y),"f"(Z),"f"(W) : "memory")

__device__ __forceinline__ uint32_t sw_off(int row, int c) {
    return (uint32_t)(row * 64 + (((c ^ (row & 3))) << 4));
}

template <int TBM, int TERMS>
__device__ __forceinline__ void ld_stage(
    uint32_t st,
    const bf16* __restrict__ Ah, const bf16* __restrict__ Al,
    const bf16* __restrict__ Bh, const bf16* __restrict__ Bl, int Bstride,
    int bm, int bn, int k0, int M, int K, int tid)
{
    constexpr uint32_t OFF_AL = TBM * 64;
    constexpr uint32_t OFF_BH = TBM * 128;
    constexpr uint32_t OFF_BL = TBM * 128 + 8192;
#pragma unroll
    for (int lin = tid; lin < TBM * 4; lin += 256) {
        int row = lin >> 2;
        int c   = lin & 3;
        uint32_t so = sw_off(row, c);
        int gr = bm + row;
        bool ok = gr < M;
        uint32_t sz = ok ? 16u : 0u;
        size_t srow = ok ? (size_t)gr : 0;
        const char* sh = (const char*)(Ah + srow * K + k0 + c * 8);
        CP_ASYNC16(st + so, sh, sz);
        if (TERMS == 3) {
            const char* sl = (const char*)(Al + srow * K + k0 + c * 8);
            CP_ASYNC16(st + OFF_AL + so, sl, sz);
        }
    }
#pragma unroll
    for (int lin = tid; lin < 512; lin += 256) {
        int row = lin >> 2;
        int c   = lin & 3;
        uint32_t so = sw_off(row, c);
        int gr = bn + row;
        const char* sh = (const char*)(Bh + (size_t)gr * Bstride + k0 + c * 8);
        CP_ASYNC16(st + OFF_BH + so, sh, 16u);
        if (TERMS >= 2) {
            const char* sl = (const char*)(Bl + (size_t)gr * Bstride + k0 + c * 8);
            CP_ASYNC16(st + OFF_BL + so, sl, 16u);
        }
    }
}

template <int OUT_MODE, int TBM, int TERMS, int USEF16, int DEQ>
__global__ void __launch_bounds__(256)
gemm_hmma(const bf16* __restrict__ Ah, const bf16* __restrict__ Al,
          const float* __restrict__ Af, const float* __restrict__ inv,
          const int* __restrict__ trip,
          const bf16* __restrict__ Bh, const bf16* __restrict__ Bl, int Bstride,
          const float* __restrict__ bias,
          const float* __restrict__ Us, const float* __restrict__ Uo,
          float* __restrict__ Cf,
          bf16* __restrict__ Ch, bf16* __restrict__ Cl,
          float* __restrict__ pooled,
          bf16* __restrict__ Pvh, bf16* __restrict__ Pvl,
          int zBoff, int zCoff,
          int M, int N, int K)
{
    constexpr uint32_t OFF_AL = TBM * 64;
    constexpr uint32_t OFF_BH = TBM * 128;
    constexpr uint32_t OFF_BL = TBM * 128 + 8192;
    constexpr uint32_t STAGE  = TBM * 128 + 16384;
    constexpr int NWM = (TBM == 128) ? 2 : 1;
    constexpr int NT  = (TBM == 128) ? 4 : 2;

    {
        size_t zb = (size_t)blockIdx.z * (size_t)zBoff;
        Bh += zb; Bl += zb;
        if (Cf) Cf += (size_t)blockIdx.z * (size_t)zCoff;
    }

    extern __shared__ char smem[];
    uint32_t sb = smem_u32(smem);

    int tid = threadIdx.x;
    int wid = tid >> 5, lane = tid & 31;
    int wm = (wid % NWM) * 64;
    int wn = (wid / NWM) * (NT * 8);
    int bm = blockIdx.y * TBM;
    int bn = blockIdx.x * BN;
    const int NC = K / BK;

    float acc[4][NT][4];
#pragma unroll
    for (int i = 0; i < 4; i++)
#pragma unroll
        for (int j = 0; j < NT; j++)
#pragma unroll
            for (int r = 0; r < 4; r++) acc[i][j][r] = 0.f;

    int lrow8 = (lane & 7) + ((lane >> 3) & 1) * 8;
    int lchunk = (lane >> 4);

    ld_stage<TBM, TERMS>(sb, Ah, Al, Bh, Bl, Bstride, bm, bn, 0, M, K, tid);
    CP_COMMIT();

    for (int kc = 0; kc < NC; kc++) {
        if (kc + 1 < NC) {
            ld_stage<TBM, TERMS>(sb + ((kc + 1) & 1) * STAGE, Ah, Al, Bh, Bl, Bstride,
                                 bm, bn, (kc + 1) * BK, M, K, tid);
            CP_COMMIT();
            asm volatile("cp.async.wait_group 1;");
        } else {
            asm volatile("cp.async.wait_group 0;");
        }
        __syncthreads();

        uint32_t sa = sb + (kc & 1) * STAGE;
#pragma unroll
        for (int ks = 0; ks < 2; ks++) {
            int c0 = ks * 2;
            uint32_t ah[4][4], al[4][4], bh[NT][2], bl[NT][2];
#pragma unroll
            for (int mt = 0; mt < 4; mt++) {
                int row = wm + mt * 16 + lrow8;
                LDSM_X4(ah[mt][0], ah[mt][1], ah[mt][2], ah[mt][3], sa + sw_off(row, c0 + lchunk));
            }
#pragma unroll
            for (int np = 0; np < NT / 2; np++) {
                int row = wn + np * 16 + lrow8;
                uint32_t r0, r1, r2, r3;
                LDSM_X4(r0, r1, r2, r3, sa + OFF_BH + sw_off(row, c0 + lchunk));
                bh[2*np][0] = r0; bh[2*np+1][0] = r1;
                bh[2*np][1] = r2; bh[2*np+1][1] = r3;
            }
#pragma unroll
            for (int mt = 0; mt < 4; mt++)
#pragma unroll
                for (int nt = 0; nt < NT; nt++) {
                    if (USEF16) MMA16816F(acc[mt][nt], ah[mt][0], ah[mt][1], ah[mt][2], ah[mt][3],
                                          bh[nt][0], bh[nt][1]);
                    else        MMA16816(acc[mt][nt], ah[mt][0], ah[mt][1], ah[mt][2], ah[mt][3],
                                         bh[nt][0], bh[nt][1]);
                }
            if (TERMS >= 2) {
#pragma unroll
                for (int np = 0; np < NT / 2; np++) {
                    int row = wn + np * 16 + lrow8;
                    uint32_t r0, r1, r2, r3;
                    LDSM_X4(r0, r1, r2, r3, sa + OFF_BL + sw_off(row, c0 + lchunk));
                    bl[2*np][0] = r0; bl[2*np+1][0] = r1;
                    bl[2*np][1] = r2; bl[2*np+1][1] = r3;
                }
#pragma unroll
                for (int mt = 0; mt < 4; mt++)
#pragma unroll
                    for (int nt = 0; nt < NT; nt++) {
                        if (USEF16) MMA16816F(acc[mt][nt], ah[mt][0], ah[mt][1], ah[mt][2], ah[mt][3],
                                              bl[nt][0], bl[nt][1]);
                        else        MMA16816(acc[mt][nt], ah[mt][0], ah[mt][1], ah[mt][2], ah[mt][3],
                                             bl[nt][0], bl[nt][1]);
                    }
            }
            if (TERMS == 3) {
#pragma unroll
                for (int mt = 0; mt < 4; mt++) {
                    int row = wm + mt * 16 + lrow8;
                    LDSM_X4(al[mt][0], al[mt][1], al[mt][2], al[mt][3], sa + OFF_AL + sw_off(row, c0 + lchunk));
                }
#pragma unroll
                for (int mt = 0; mt < 4; mt++)
#pragma unroll
                    for (int nt = 0; nt < NT; nt++) {
                        if (USEF16) MMA16816F(acc[mt][nt], al[mt][0], al[mt][1], al[mt][2], al[mt][3],
                                              bh[nt][0], bh[nt][1]);
                        else        MMA16816(acc[mt][nt], al[mt][0], al[mt][1], al[mt][2], al[mt][3],
                                             bh[nt][0], bh[nt][1]);
                    }
            }
        }
        __syncthreads();
    }

    int r = lane >> 2, q = lane & 3;

    if (OUT_MODE == 3) {
#pragma unroll
        for (int mt = 0; mt < 4; mt++) {
            int lr0 = wm + mt * 16 + r;
            float sa0 = 1.f, sa1 = 1.f;
            if (USEF16) {
                sa0 = __ldg(&Us[bm + lr0]);
                sa1 = __ldg(&Us[bm + lr0 + 8]);
            }
#pragma unroll
            for (int nt = 0; nt < NT; nt++) {
                int lc = wn + nt * 8 + q * 2;
                int col = bn + lc;
                float b0 = bias[col], b1 = bias[col + 1];
                float sb0 = 1.f, sb1 = 1.f;
                if (USEF16) { sb0 = __ldg(&Uo[col]); sb1 = __ldg(&Uo[col + 1]); }
                float2 v0 = make_float2(fmaxf(acc[mt][nt][0] * sa0 * sb0 + b0, 0.f),
                                        fmaxf(acc[mt][nt][1] * sa0 * sb1 + b1, 0.f));
                float2 v1 = make_float2(fmaxf(acc[mt][nt][2] * sa1 * sb0 + b0, 0.f),
                                        fmaxf(acc[mt][nt][3] * sa1 * sb1 + b1, 0.f));
                *reinterpret_cast<float2*>(smem + ((size_t)lr0 * 128 + lc) * 4) = v0;
                *reinterpret_cast<float2*>(smem + ((size_t)(lr0 + 8) * 128 + lc) * 4) = v1;
            }
        }
        __syncthreads();
        int row = tid >> 1;
        int half = (tid & 1) * 64;
        int gr = bm + row;
        if (gr < M) {
            const float* srow = reinterpret_cast<const float*>(smem) + (size_t)row * 128 + half;
            if (bn == 512) {
                // full pv row in staging: compute row max over all 128 cols, emit fp16 + scale
                const float* full = reinterpret_cast<const float*>(smem) + (size_t)row * 128;
                float mx = 0.f;
#pragma unroll
                for (int i = 0; i < 32; i++) {
                    float4 v = *reinterpret_cast<const float4*>(full + i * 4);
                    mx = fmaxf(mx, fmaxf(fmaxf(v.x, v.y), fmaxf(v.z, v.w)));
                }
                float invs = mx > 1e-30f ? 2047.f / mx : 0.f;
                __half* Pv16 = reinterpret_cast<__half*>(Pvh);
#pragma unroll
                for (int i = 0; i < 16; i++) {
                    float4 v = *reinterpret_cast<const float4*>(srow + i * 4);
                    __half2 a, b;
                    a.x = __float2half(v.x * invs); a.y = __float2half(v.y * invs);
                    b.x = __float2half(v.z * invs); b.y = __float2half(v.w * invs);
                    int pc = half + i * 4;
                    *reinterpret_cast<__half2*>(Pv16 + (size_t)gr * DD + pc) = a;
                    *reinterpret_cast<__half2*>(Pv16 + (size_t)gr * DD + pc + 2) = b;
                }
                if ((tid & 1) == 0)
                    reinterpret_cast<float*>(Pvl)[gr] = mx > 1e-30f ? mx / 2047.f : 0.f;
            } else {
                int obj = __ldg(&trip[3 * gr + ((bn < 512) ? 0 : 2)]);
                float* dst = pooled + (size_t)obj * HH + ((bn < 512) ? bn : bn - 640) + half;
#pragma unroll
                for (int i = 0; i < 16; i++) {
                    float4 v = *reinterpret_cast<const float4*>(srow + i * 4);
                    REDV4(dst + i * 4, v.x, v.y, v.z, v.w);
                }
            }
        }
        return;
    }

#pragma unroll
    for (int mt = 0; mt < 4; mt++) {
        int row0 = bm + wm + mt * 16 + r;
        int row1 = row0 + 8;
        int s0 = 0, o0 = 0, s1 = 0, o1 = 0;
        if (OUT_MODE == 5) {
            if (row0 < M) { s0 = __ldg(&trip[3 * row0]); o0 = __ldg(&trip[3 * row0 + 2]); }
            if (row1 < M) { s1 = __ldg(&trip[3 * row1]); o1 = __ldg(&trip[3 * row1 + 2]); }
        }
        float sa0 = 1.f, sa1 = 1.f;
        if (DEQ) {
            if (row0 < M) sa0 = __ldg(&Af[row0]);
            if (row1 < M) sa1 = __ldg(&Af[row1]);
        }
#pragma unroll
        for (int nt = 0; nt < NT; nt++) {
            int col = bn + wn + nt * 8 + q * 2;
            if (OUT_MODE == 0) {
                if (row0 < M)
                    *reinterpret_cast<float2*>(Cf + (size_t)row0 * N + col) = make_float2(acc[mt][nt][0], acc[mt][nt][1]);
                if (row1 < M)
                    *reinterpret_cast<float2*>(Cf + (size_t)row1 * N + col) = make_float2(acc[mt][nt][2], acc[mt][nt][3]);
                continue;
            }
            float b0 = bias[col], b1 = bias[col + 1];
            float sb0 = 1.f, sb1 = 1.f;
            if (DEQ) { sb0 = __ldg(&inv[col]); sb1 = __ldg(&inv[col + 1]); }
            float a00 = acc[mt][nt][0] * sa0 * sb0 + b0, a01 = acc[mt][nt][1] * sa0 * sb1 + b1;
            float a10 = acc[mt][nt][2] * sa1 * sb0 + b0, a11 = acc[mt][nt][3] * sa1 * sb1 + b1;
            if (OUT_MODE == 5) {
                if (row0 < M) {
                    float2 us = *reinterpret_cast<const float2*>(Us + (size_t)s0 * HH + col);
                    float2 uo = *reinterpret_cast<const float2*>(Uo + (size_t)o0 * HH + col);
                    a00 += us.x + uo.x; a01 += us.y + uo.y;
                }
                if (row1 < M) {
                    float2 us = *reinterpret_cast<const float2*>(Us + (size_t)s1 * HH + col);
                    float2 uo = *reinterpret_cast<const float2*>(Uo + (size_t)o1 * HH + col);
                    a10 += us.x + uo.x; a11 += us.y + uo.y;
                }
            }
            float v00 = fmaxf(a00, 0.f), v01 = fmaxf(a01, 0.f);
            float v10 = fmaxf(a10, 0.f), v11 = fmaxf(a11, 0.f);
            bf16 h0, l0, h1, l1;
            if (row0 < M) {
                if (OUT_MODE == 2)
                    *reinterpret_cast<float2*>(Cf + (size_t)row0 * N + col) = make_float2(v00, v01);
                f32split(v00, h0, l0); f32split(v01, h1, l1);
                *reinterpret_cast<uint32_t*>(Ch + (size_t)row0 * N + col) = bfpack(h0, h1);
                *reinterpret_cast<uint32_t*>(Cl + (size_t)row0 * N + col) = bfpack(l0, l1);
            }
            if (row1 < M) {
                if (OUT_MODE == 2)
                    *reinterpret_cast<float2*>(Cf + (size_t)row1 * N + col) = make_float2(v10, v11);
                f32split(v10, h0, l0); f32split(v11, h1, l1);
                *reinterpret_cast<uint32_t*>(Ch + (size_t)row1 * N + col) = bfpack(h0, h1);
                *reinterpret_cast<uint32_t*>(Cl + (size_t)row1 * N + col) = bfpack(l0, l1);
            }
        }
    }
}

// ================= attention epilogue =================
__global__ void scores_kernel(const float* __restrict__ ov,
                              const float* __restrict__ att_w,
                              const float* __restrict__ att_b,
                              float* __restrict__ scores) {
    int gid = blockIdx.x * blockDim.x + threadIdx.x;
    int w = gid >> 5, lane = gid & 31;
    if (w >= NUM_O) return;
    float sum = 0.f;
#pragma unroll
    for (int d = lane; d < DD; d += 32) sum += ov[(size_t)w * DD + d] * att_w[d];
#pragma unroll
    for (int off = 16; off; off >>= 1) sum += __shfl_down_sync(0xffffffff, sum, off);
    if (lane == 0) scores[w] = sum + att_b[0];
}

__global__ void segment_kernel(const float* __restrict__ scores,
                               const int* __restrict__ img,
                               const float* __restrict__ ov,
                               float* __restrict__ gvec) {
    int g = blockIdx.x, t = threadIdx.x;
    __shared__ float sred[128];
    __shared__ int ired[128];

    float m = -3.4e38f;
    int lo = NUM_O, hi = -1;
    for (int i = t; i < NUM_O; i += 128) {
        if (img[i] == g) {
            m = fmaxf(m, scores[i]);
            lo = min(lo, i);
            hi = max(hi, i);
        }
    }
    sred[t] = m; __syncthreads();
    for (int s = 64; s > 0; s >>= 1) { if (t < s) sred[t] = fmaxf(sred[t], sred[t + s]); __syncthreads(); }
    m = sred[0]; __syncthreads();
    ired[t] = lo; __syncthreads();
    for (int s = 64; s > 0; s >>= 1) { if (t < s) ired[t] = min(ired[t], ired[t + s]); __syncthreads(); }
    lo = ired[0]; __syncthreads();
    ired[t] = hi; __syncthreads();
    for (int s = 64; s > 0; s >>= 1) { if (t < s) ired[t] = max(ired[t], ired[t + s]); __syncthreads(); }
    hi = ired[0]; __syncthreads();

    float z = 0.f;
    for (int i = lo + t; i <= hi; i += 128)
        if (img[i] == g) z += expf(scores[i] - m);
    sred[t] = z; __syncthreads();
    for (int s = 64; s > 0; s >>= 1) { if (t < s) sred[t] += sred[t + s]; __syncthreads(); }
    z = sred[0];
    float invz = 1.f / z;

    float acc = 0.f;
    for (int i = lo; i <= hi; i++) {
        if (img[i] == g)
            acc += expf(scores[i] - m) * invz * ov[(size_t)i * DD + t];
    }
    gvec[g * DD + t] = acc;
}

__global__ void concat_kernel(const float* __restrict__ ov,
                              const float* __restrict__ gvec,
                              const int* __restrict__ img,
                              float* __restrict__ out) {
    int i = blockIdx.x, t = threadIdx.x;
    if (t < DD) out[(size_t)i * 256 + t] = ov[(size_t)i * DD + t];
    else        out[(size_t)i * 256 + t] = gvec[img[i] * DD + (t - DD)];
}

// ================= launch =================
extern "C" void kernel_launch(void* const* d_in, const int* in_sizes, int n_in,
                              void* d_out, int out_size) {
    const int*   objs     = (const int*)d_in[0];
    const int*   trip     = (const int*)d_in[1];
    const int*   img      = (const int*)d_in[2];
    const float* obj_emb  = (const float*)d_in[3];
    const float* pred_emb = (const float*)d_in[4];
    const float* n1w1     = (const float*)d_in[5];
    const float* n1b1     = (const float*)d_in[6];
    const float* n1w2     = (const float*)d_in[7];
    const float* n1b2     = (const float*)d_in[8];
    const float* n2w1     = (const float*)d_in[9];
    const float* n2b1     = (const float*)d_in[10];
    const float* n2w2     = (const float*)d_in[11];
    const float* n2b2     = (const float*)d_in[12];
    const float* att_w    = (const float*)d_in[13];
    const float* att_b    = (const float*)d_in[14];
    float* out = (float*)d_out;

    float *ov, *pooled, *counts, *inv, *scores, *gvec, *U;
    float *saq, *spq, *spl, *sbq2, *sbq1p, *sbq3;
    bf16 *ovh, *ovl, *hh, *hl, *h2h, *h2l;
    bf16 *w1h, *w1l, *w4h, *w4l;
    __half *h16, *pv16, *p16, *w2h16, *w1p16, *w316;
    cudaGetSymbolAddress((void**)&ov,     g_ov);
    cudaGetSymbolAddress((void**)&pooled, g_pooled);
    cudaGetSymbolAddress((void**)&counts, g_counts);
    cudaGetSymbolAddress((void**)&inv,    g_invcnt);
    cudaGetSymbolAddress((void**)&scores, g_scores);
    cudaGetSymbolAddress((void**)&gvec,   g_gvec);
    cudaGetSymbolAddress((void**)&U,      g_U);
    cudaGetSymbolAddress((void**)&saq,    g_saq);
    cudaGetSymbolAddress((void**)&spq,    g_spq);
    cudaGetSymbolAddress((void**)&spl,    g_spl);
    cudaGetSymbolAddress((void**)&sbq2,   g_sbq2);
    cudaGetSymbolAddress((void**)&sbq1p,  g_sbq1p);
    cudaGetSymbolAddress((void**)&sbq3,   g_sbq3);
    cudaGetSymbolAddress((void**)&ovh, g_ovh); cudaGetSymbolAddress((void**)&ovl, g_ovl);
    cudaGetSymbolAddress((void**)&hh,  g_hh);  cudaGetSymbolAddress((void**)&hl,  g_hl);
    cudaGetSymbolAddress((void**)&h2h, g_h2h); cudaGetSymbolAddress((void**)&h2l, g_h2l);
    cudaGetSymbolAddress((void**)&h16, g_h16);
    cudaGetSymbolAddress((void**)&pv16, g_pv16);
    cudaGetSymbolAddress((void**)&p16,  g_p16);
    cudaGetSymbolAddress((void**)&w1h, g_w1h); cudaGetSymbolAddress((void**)&w1l, g_w1l);
    cudaGetSymbolAddress((void**)&w2h16, g_w2h16);
    cudaGetSymbolAddress((void**)&w1p16, g_w1p16);
    cudaGetSymbolAddress((void**)&w316,  g_w316);
    cudaGetSymbolAddress((void**)&w4h, g_w4h); cudaGetSymbolAddress((void**)&w4l, g_w4l);

    float* Us = U;
    float* Uo = U + (size_t)NUM_O * HH;

    const int SMEM128 = 65536;
    const int SMEM64  = 49152;
    const int SMEMWQ  = 32 * (HH + 2) * 4;
    cudaFuncSetAttribute(gemm_hmma<0,64,3,0,0>,  cudaFuncAttributeMaxDynamicSharedMemorySize, SMEM64);
    cudaFuncSetAttribute(gemm_hmma<5,128,1,1,1>, cudaFuncAttributeMaxDynamicSharedMemorySize, SMEM128);
    cudaFuncSetAttribute(gemm_hmma<3,128,1,1,0>, cudaFuncAttributeMaxDynamicSharedMemorySize, SMEM128);
    cudaFuncSetAttribute(gemm_hmma<1,64,1,1,1>,  cudaFuncAttributeMaxDynamicSharedMemorySize, SMEM64);
    cudaFuncSetAttribute(gemm_hmma<2,64,3,0,0>,  cudaFuncAttributeMaxDynamicSharedMemorySize, SMEM64);
    cudaFuncSetAttribute(wquant_f16,             cudaFuncAttributeMaxDynamicSharedMemorySize, SMEMWQ);

    const int mT   = (NUM_T + 127) / 128;   // 157
    const int mO64 = (NUM_O + 63) / 64;     // 79

    // ---- prologue (index 3 = merged U GEMM, profiled by ncu) ----
    wtrans_split<<<dim3(HH/32, K1/32, LL), dim3(32,32)>>>(n1w1, w1h, w1l, K1, HH);    // 0
    gather_init<<<dim3(NUM_T, 2), DD>>>(obj_emb, pred_emb, objs, trip,
                                        ovh, ovl, pv16, spq);                         // 1
    wquant_f16<<<dim3(N2/32, LL), 256, SMEMWQ>>>(n1w2, w2h16, sbq2, HH, N2, HH*N2);   // 2

    gemm_hmma<0,64,3,0,0><<<dim3(HH/BN, mO64, 2), 256, SMEM64>>>(                     // 3 (profiled)
        ovh, ovl, nullptr, nullptr, nullptr,
        w1h, w1l, K1, nullptr, nullptr, nullptr,
        U, nullptr, nullptr, nullptr, nullptr, nullptr,
        2*DD, NUM_O*HH, NUM_O, HH, DD);

    wquant_f16<<<dim3(HH/32, LL), 256, SMEMWQ>>>(n1w1 + (size_t)DD*HH, w1p16, sbq1p,
                                                 DD, HH, K1*HH);                      // 4
    wquant_f16<<<dim3(HH/32, LL), 256, SMEMWQ>>>(n2w1, w316, sbq3, HH, HH, HH*HH);    // 5
    zero_kernel<<<(NUM_O + 255) / 256, 256>>>(counts, NUM_O);                         // 6
    count_kernel<<<(NUM_T + 255) / 256, 256>>>(trip, counts);                         // 7
    inv_kernel<<<(NUM_O + 255) / 256, 256>>>(counts, inv);                            // 8
    wtrans_split<<<dim3(DD/32, HH/32, LL), dim3(32,32)>>>(n2w2, w4h, w4l, HH, DD);    // 9

    for (int l = 0; l < LL; l++) {
        if (l > 0) {
            gemm_hmma<0,64,3,0,0><<<dim3(HH/BN, mO64, 2), 256, SMEM64>>>(
                ovh, ovl, nullptr, nullptr, nullptr,
                w1h + (size_t)l*HH*K1, w1l + (size_t)l*HH*K1, K1, nullptr, nullptr, nullptr,
                U, nullptr, nullptr, nullptr, nullptr, nullptr,
                2*DD, NUM_O*HH, NUM_O, HH, DD);
        }

        // pv GEMM: fp16 1-term row-scaled + dequant + gather-add epilogue
        gemm_hmma<5,128,1,1,1><<<dim3(HH/BN, mT), 256, SMEM128>>>(
            (const bf16*)pv16, nullptr, spq, sbq1p + (size_t)l*HH, trip,
            (const bf16*)(w1p16 + (size_t)l*HH*DD), nullptr, DD,
            n1b1 + (size_t)l*HH, Us, Uo,
            nullptr, hh, hl, nullptr, nullptr, nullptr,
            0, 0, NUM_T, HH, DD);

        // quantize h rows to fp16
        quant_rows_f16<HH><<<NUM_T, 128>>>(hh, hl, h16, saq);

        zero_kernel<<<(NUM_O * HH + 255) / 256, 256>>>(pooled, NUM_O * HH);

        // GEMM2: fp16 1-term row-scaled, dequant + fused scatter (pv block -> pv16 + spq)
        gemm_hmma<3,128,1,1,0><<<dim3(N2/BN, mT), 256, SMEM128>>>(
            (const bf16*)h16, nullptr, nullptr, nullptr, trip,
            (const bf16*)(w2h16 + (size_t)l*N2*HH), nullptr, HH,
            n1b2 + (size_t)l*N2,
            saq, sbq2 + (size_t)l*N2,
            nullptr, nullptr, nullptr, pooled, (bf16*)pv16, (bf16*)spq,
            0, 0, NUM_T, N2, HH);

        // quantize pooled*inv rows to fp16
        quant_pooled_f16<<<NUM_O, 128>>>(pooled, inv, p16, spl);

        // GEMM3: fp16 1-term row-scaled + dequant
        gemm_hmma<1,64,1,1,1><<<dim3(HH/BN, mO64), 256, SMEM64>>>(
            (const bf16*)p16, nullptr, spl, sbq3 + (size_t)l*HH, nullptr,
            (const bf16*)(w316 + (size_t)l*HH*HH), nullptr, HH,
            n2b1 + (size_t)l*HH, nullptr, nullptr,
            nullptr, h2h, h2l, nullptr, nullptr, nullptr,
            0, 0, NUM_O, HH, HH);

        // GEMM4: ov fp32 + bf16 pair (3-term bf16)
        gemm_hmma<2,64,3,0,0><<<dim3(DD/BN, mO64), 256, SMEM64>>>(
            h2h, h2l, nullptr, nullptr, nullptr,
            w4h + (size_t)l*DD*HH, w4l + (size_t)l*DD*HH, HH, n2b2 + (size_t)l*DD,
            nullptr, nullptr,
            ov, ovh, ovl, nullptr, nullptr, nullptr,
            0, 0, NUM_O, DD, HH);
    }

    scores_kernel<<<(NUM_O * 32 + 255) / 256, 256>>>(ov, att_w, att_b, scores);
    segment_kernel<<<GG, 128>>>(scores, img, ov, gvec);
    concat_kernel<<<NUM_O, 256>>>(ov, gvec, img, out);
}